// round 10
// baseline (speedup 1.0000x reference)
#include <cuda_runtime.h>
#include <cuda_bf16.h>
#include <math.h>
#include <stdint.h>

// ---------------------------------------------------------------------------
// Problem constants
// ---------------------------------------------------------------------------
#define TOK   5760          // 5*24*48
#define CH    256
#define DD    5
#define HH    24
#define WW    48
#define NHEAD 8
#define HDIM  32

// fp32 scratch
__device__ float g_qkv [TOK * 768];
__device__ float g_feats[512 * TOK];                 // channel-first (512, 5, 24, 48)
__device__ float g_s0  [256 * 48 * 96];
__device__ float g_s1  [128 * 96 * 192];

// bf16 hi/lo scratch
__device__ __align__(16) __nv_bfloat16 g_xah[TOK * 256],   g_xal[TOK * 256];   // x (layer act)
__device__ __align__(16) __nv_bfloat16 g_aah[TOK * 256],   g_aal[TOK * 256];   // attn out
__device__ __align__(16) __nv_bfloat16 g_wth[2048 * 512],  g_wtl[2048 * 512];  // weight scratch
__device__ __align__(16) __nv_bfloat16 g_fth[4608 * 512],  g_ftl[4608 * 512];  // featsT (press0 B)
__device__ __align__(16) __nv_bfloat16 g_b0h[36864 * 256], g_b0l[36864 * 256]; // press0 out = press1 B
__device__ __align__(16) __nv_bfloat16 g_b1h[294912 * 128], g_b1l[294912 * 128]; // press1 out = press2 B

// ---------------------------------------------------------------------------
// fp32 -> bf16 hi/lo split, contiguous
// ---------------------------------------------------------------------------
__global__ void split_rows(const float* __restrict__ in,
                           __nv_bfloat16* __restrict__ oh,
                           __nv_bfloat16* __restrict__ ol, int n)
{
    int i = blockIdx.x * blockDim.x + threadIdx.x;
    if (i < n) {
        float v = in[i];
        __nv_bfloat16 h = __float2bfloat16(v);
        oh[i] = h;
        ol[i] = __float2bfloat16(v - __bfloat162float(h));
    }
}

// fp32 [R][C] (row stride ld) -> bf16 hi/lo [C][R]   (R, C multiples of 32)
__global__ void transpose_split(const float* __restrict__ in,
                                __nv_bfloat16* __restrict__ oh,
                                __nv_bfloat16* __restrict__ ol,
                                int R, int C, int ld)
{
    __shared__ float t[32][33];
    const int r0 = blockIdx.y * 32, c0 = blockIdx.x * 32;
    const int tx = threadIdx.x, ty = threadIdx.y;
    #pragma unroll
    for (int i = ty; i < 32; i += 8)
        t[i][tx] = in[(size_t)(r0 + i) * ld + c0 + tx];
    __syncthreads();
    #pragma unroll
    for (int i = ty; i < 32; i += 8) {
        float v = t[tx][i];
        __nv_bfloat16 h = __float2bfloat16(v);
        oh[(size_t)(c0 + i) * R + r0 + tx] = h;
        ol[(size_t)(c0 + i) * R + r0 + tx] = __float2bfloat16(v - __bfloat162float(h));
    }
}

// pw2 [128][40] -> padded A hi/lo [128][128], rows 40..127 zero
__global__ void pad_split_pw2(const float* __restrict__ pw2,
                              __nv_bfloat16* __restrict__ oh,
                              __nv_bfloat16* __restrict__ ol)
{
    const int idx = blockIdx.x * 256 + threadIdx.x;   // 0..16383
    const int m = idx >> 7, k = idx & 127;
    float v = (m < 40) ? pw2[k * 40 + m] : 0.f;
    __nv_bfloat16 h = __float2bfloat16(v);
    oh[idx] = h;
    ol[idx] = __float2bfloat16(v - __bfloat162float(h));
}

// ---------------------------------------------------------------------------
// Tensor-core GEMM, bf16x3 split (hi*hi + hi*lo + lo*hi), fp32 accum.
//   C[m][n] = epilogue( sum_k A[m][k]*B[k][n] + bias )
// A given as Ah/Al [M][K] bf16, B as Bh/Bl [N][K] bf16.
// Tile 128x128x32, 256 threads = 8 warps (2 m x 4 n), warp tile 64x32,
// mma.sync.m16n8k16. N multiple of 128; K multiple of 32; A buffer padded to
// 128 rows per tile (epilogue guards m < M).
// MODE 0: fp32 C row-major [M][ldc], bias[n]
// MODE 1: fp32 C row-major [M][ldc], bias[m]
// MODE 2: up3d scatter to fp32 C, bias[m>>3], optional SiLU, m<M guarded
// MODE 4: bf16 hi/lo Oh/Ol row-major [M][ldc], bias[n]
// MODE 5: up3d scatter to bf16 hi/lo Oh/Ol laid out [spatial][ldc]+o
//         (next GEMM's B operand), bias[m>>3], optional SiLU
// ---------------------------------------------------------------------------
#define MMA_BF16(c, a0, a1, a2, a3, b0, b1)                                   \
    asm volatile("mma.sync.aligned.m16n8k16.row.col.f32.bf16.bf16.f32 "       \
                 "{%0,%1,%2,%3}, {%4,%5,%6,%7}, {%8,%9}, {%0,%1,%2,%3};"      \
                 : "+f"(c[0]), "+f"(c[1]), "+f"(c[2]), "+f"(c[3])             \
                 : "r"(a0), "r"(a1), "r"(a2), "r"(a3), "r"(b0), "r"(b1))

template<int MODE, bool SILU>
__global__ __launch_bounds__(256)
void gemm_mma(const __nv_bfloat16* __restrict__ Ah, const __nv_bfloat16* __restrict__ Al,
              const __nv_bfloat16* __restrict__ Bh, const __nv_bfloat16* __restrict__ Bl,
              const float* __restrict__ bias, float* __restrict__ C,
              __nv_bfloat16* __restrict__ Oh, __nv_bfloat16* __restrict__ Ol,
              int M, int N, int K, int ldc, int Din, int Hin, int Win)
{
    constexpr int RS = 20;                         // smem words per row (16 data + 4 pad)
    __shared__ float sAh[128 * RS], sAl[128 * RS];
    __shared__ float sBh[128 * RS], sBl[128 * RS];

    const int tid  = threadIdx.x;
    const int warp = tid >> 5, lane = tid & 31;
    const int g = lane >> 2, t = lane & 3;
    const int wm = warp & 1, wn = warp >> 1;       // warp tile origin (wm*64, wn*32)
    const int m0 = blockIdx.y * 128, n0 = blockIdx.x * 128;

    const int lrow = tid >> 1, lseg = tid & 1;     // loader: 2 threads/row, 16 bf16 each

    float acc[4][4][4];
    #pragma unroll
    for (int a = 0; a < 4; a++)
        #pragma unroll
        for (int b = 0; b < 4; b++)
            #pragma unroll
            for (int c = 0; c < 4; c++) acc[a][b][c] = 0.f;

    const uint32_t* wAh = (const uint32_t*)sAh;
    const uint32_t* wAl = (const uint32_t*)sAl;
    const uint32_t* wBh = (const uint32_t*)sBh;
    const uint32_t* wBl = (const uint32_t*)sBl;

    for (int k0 = 0; k0 < K; k0 += 32) {
        {
            const size_t ga = (size_t)(m0 + lrow) * K + k0 + lseg * 16;
            const size_t gb = (size_t)(n0 + lrow) * K + k0 + lseg * 16;
            const uint4* pah = (const uint4*)(Ah + ga);
            const uint4* pal = (const uint4*)(Al + ga);
            const uint4* pbh = (const uint4*)(Bh + gb);
            const uint4* pbl = (const uint4*)(Bl + gb);
            uint4* dah = (uint4*)&sAh[lrow * RS + lseg * 8];
            uint4* dal = (uint4*)&sAl[lrow * RS + lseg * 8];
            uint4* dbh = (uint4*)&sBh[lrow * RS + lseg * 8];
            uint4* dbl = (uint4*)&sBl[lrow * RS + lseg * 8];
            dah[0] = pah[0]; dah[1] = pah[1];
            dal[0] = pal[0]; dal[1] = pal[1];
            dbh[0] = pbh[0]; dbh[1] = pbh[1];
            dbl[0] = pbl[0]; dbl[1] = pbl[1];
        }
        __syncthreads();

        #pragma unroll
        for (int ks = 0; ks < 2; ks++) {
            uint32_t bh[4][2], bl[4][2];
            #pragma unroll
            for (int nt = 0; nt < 4; nt++) {
                const int base = (wn * 32 + nt * 8 + g) * RS + ks * 8 + t;
                bh[nt][0] = wBh[base]; bh[nt][1] = wBh[base + 4];
                bl[nt][0] = wBl[base]; bl[nt][1] = wBl[base + 4];
            }
            #pragma unroll
            for (int mt = 0; mt < 4; mt++) {
                const int base  = (wm * 64 + mt * 16 + g) * RS + ks * 8 + t;
                const int base8 = base + 8 * RS;
                const uint32_t ah0 = wAh[base],     ah1 = wAh[base8];
                const uint32_t ah2 = wAh[base + 4], ah3 = wAh[base8 + 4];
                const uint32_t al0 = wAl[base],     al1 = wAl[base8];
                const uint32_t al2 = wAl[base + 4], al3 = wAl[base8 + 4];
                #pragma unroll
                for (int nt = 0; nt < 4; nt++) {
                    MMA_BF16(acc[mt][nt], ah0, ah1, ah2, ah3, bh[nt][0], bh[nt][1]);
                    MMA_BF16(acc[mt][nt], ah0, ah1, ah2, ah3, bl[nt][0], bl[nt][1]);
                    MMA_BF16(acc[mt][nt], al0, al1, al2, al3, bh[nt][0], bh[nt][1]);
                }
            }
        }
        __syncthreads();
    }

    // element (mt, nt, reg): m = m0+wm*64+mt*16+g+(reg>=2)*8,
    //                        n = n0+wn*32+nt*8+t*2+(reg&1)
    if (MODE == 0 || MODE == 1) {
        #pragma unroll
        for (int mt = 0; mt < 4; mt++) {
            const int mb = m0 + wm * 64 + mt * 16 + g;
            const float bmA = (MODE == 1) ? bias[mb]     : 0.f;
            const float bmB = (MODE == 1) ? bias[mb + 8] : 0.f;
            #pragma unroll
            for (int nt = 0; nt < 4; nt++) {
                const int nb = n0 + wn * 32 + nt * 8 + t * 2;
                float b0 = bmA, b1 = bmA, b2 = bmB, b3 = bmB;
                if (MODE == 0) { b0 = b2 = bias[nb]; b1 = b3 = bias[nb + 1]; }
                float2 v0 = make_float2(acc[mt][nt][0] + b0, acc[mt][nt][1] + b1);
                float2 v1 = make_float2(acc[mt][nt][2] + b2, acc[mt][nt][3] + b3);
                *(float2*)&C[(size_t)mb * ldc + nb]       = v0;
                *(float2*)&C[(size_t)(mb + 8) * ldc + nb] = v1;
            }
        }
    } else if (MODE == 4) {
        #pragma unroll
        for (int mt = 0; mt < 4; mt++) {
            const int mb = m0 + wm * 64 + mt * 16 + g;
            #pragma unroll
            for (int nt = 0; nt < 4; nt++) {
                const int nb = n0 + wn * 32 + nt * 8 + t * 2;
                const float b0 = bias[nb], b1 = bias[nb + 1];
                #pragma unroll
                for (int half = 0; half < 2; half++) {
                    const int m = mb + half * 8;
                    const float va = acc[mt][nt][half * 2 + 0] + b0;
                    const float vb = acc[mt][nt][half * 2 + 1] + b1;
                    const __nv_bfloat16 ha = __float2bfloat16(va);
                    const __nv_bfloat16 hb = __float2bfloat16(vb);
                    Oh[(size_t)m * ldc + nb]     = ha;
                    Oh[(size_t)m * ldc + nb + 1] = hb;
                    Ol[(size_t)m * ldc + nb]     = __float2bfloat16(va - __bfloat162float(ha));
                    Ol[(size_t)m * ldc + nb + 1] = __float2bfloat16(vb - __bfloat162float(hb));
                }
            }
        }
    } else { // MODE 2 / MODE 5 : up3d scatter
        int nw[4][2], nh[4][2], nd[4][2];
        #pragma unroll
        for (int nt = 0; nt < 4; nt++)
            #pragma unroll
            for (int e = 0; e < 2; e++) {
                const int n = n0 + wn * 32 + nt * 8 + t * 2 + e;
                nw[nt][e] = n % Win;
                const int tt = n / Win;
                nh[nt][e] = tt % Hin;
                nd[nt][e] = tt / Hin;
            }
        const int OD = 2 * Din, OH = 2 * Hin, OW = 2 * Win;
        #pragma unroll
        for (int mt = 0; mt < 4; mt++) {
            #pragma unroll
            for (int half = 0; half < 2; half++) {
                const int m = m0 + wm * 64 + mt * 16 + g + half * 8;
                if (m < M) {
                    const int o = m >> 3, r = m & 7;
                    const int ri = (r >> 2) & 1, rj = (r >> 1) & 1, rk = r & 1;
                    const float bv = bias[o];
                    #pragma unroll
                    for (int nt = 0; nt < 4; nt++) {
                        #pragma unroll
                        for (int e = 0; e < 2; e++) {
                            float v = acc[mt][nt][half * 2 + e] + bv;
                            if (SILU) v = v / (1.f + __expf(-v));
                            const size_t sp =
                                ((size_t)(2 * nd[nt][e] + ri) * OH
                                 + 2 * nh[nt][e] + rj) * OW + 2 * nw[nt][e] + rk;
                            if (MODE == 2) {
                                C[(size_t)o * OD * OH * OW + sp] = v;
                            } else {
                                const __nv_bfloat16 h = __float2bfloat16(v);
                                Oh[sp * ldc + o] = h;
                                Ol[sp * ldc + o] =
                                    __float2bfloat16(v - __bfloat162float(h));
                            }
                        }
                    }
                }
            }
        }
    }
}

// ---------------------------------------------------------------------------
// Double-buffered fp32 SGEMM (kept for surf chain)
// ---------------------------------------------------------------------------
template<int BM, bool TA, bool TB, int MODE, bool SILU>
__global__ __launch_bounds__(BM * 2)
void gemm_db(const float* __restrict__ A, const float* __restrict__ B,
             const float* __restrict__ bias, float* __restrict__ C,
             int M, int N, int K, int lda, int ldb, int ldc,
             int Din, int Hin, int Win)
{
    constexpr int THREADS = BM * 2;
    __shared__ float As[2][8][BM];
    __shared__ float Bs[2][8][128];
    const int tid = threadIdx.x;
    const int m0 = blockIdx.y * BM;
    const int n0 = blockIdx.x * 128;
    const int tx = tid & 15, ty = tid >> 4;

    int a_k, a_m;
    if (TA) { a_k = tid / (BM / 4); a_m = (tid % (BM / 4)) * 4; }
    else    { a_m = tid >> 1;       a_k = (tid & 1) << 2; }
    const int bn_k = TB ? ((tid & 1) << 2) : (tid >> 5);
    const int bn_n = TB ? (tid >> 1)       : ((tid & 31) << 2);

    float4 ra, rb0, rb1;

    auto ldA = [&](int k0) {
        if (TA) {
            const float* p = A + (size_t)(k0 + a_k) * lda + m0 + a_m;
            float4 v;
            if (m0 + a_m + 3 < M) v = *(const float4*)p;
            else {
                v.x = (m0 + a_m     < M) ? p[0] : 0.f;
                v.y = (m0 + a_m + 1 < M) ? p[1] : 0.f;
                v.z = (m0 + a_m + 2 < M) ? p[2] : 0.f;
                v.w = (m0 + a_m + 3 < M) ? p[3] : 0.f;
            }
            ra = v;
        } else {
            float4 v = make_float4(0.f, 0.f, 0.f, 0.f);
            if (m0 + a_m < M) v = *(const float4*)(A + (size_t)(m0 + a_m) * lda + k0 + a_k);
            ra = v;
        }
    };
    auto ldB = [&](int k0) {
        if (TB) {
            rb0 = *(const float4*)(B + (size_t)(n0 + bn_n) * ldb + k0 + bn_k);
        } else {
            rb0 = *(const float4*)(B + (size_t)(k0 + bn_k) * ldb + n0 + bn_n);
            if (THREADS == 128)
                rb1 = *(const float4*)(B + (size_t)(k0 + bn_k + 4) * ldb + n0 + bn_n);
        }
    };
    auto stA = [&](int buf) {
        if (TA) {
            *(float4*)&As[buf][a_k][a_m] = ra;
        } else {
            As[buf][a_k + 0][a_m] = ra.x; As[buf][a_k + 1][a_m] = ra.y;
            As[buf][a_k + 2][a_m] = ra.z; As[buf][a_k + 3][a_m] = ra.w;
        }
    };
    auto stB = [&](int buf) {
        if (TB) {
            Bs[buf][bn_k + 0][bn_n] = rb0.x; Bs[buf][bn_k + 1][bn_n] = rb0.y;
            Bs[buf][bn_k + 2][bn_n] = rb0.z; Bs[buf][bn_k + 3][bn_n] = rb0.w;
        } else {
            *(float4*)&Bs[buf][bn_k][bn_n] = rb0;
            if (THREADS == 128) *(float4*)&Bs[buf][bn_k + 4][bn_n] = rb1;
        }
    };

    float acc[8][8] = {};

    ldA(0); ldB(0);
    stA(0); stB(0);
    __syncthreads();

    const int nslab = K >> 3;
    int buf = 0;
    for (int s = 0; s < nslab; s++) {
        if (s + 1 < nslab) { ldA((s + 1) << 3); ldB((s + 1) << 3); }
        #pragma unroll
        for (int kk = 0; kk < 8; kk++) {
            float a[8], b[8];
            *(float4*)&a[0] = *(float4*)&As[buf][kk][ty * 4];
            *(float4*)&a[4] = *(float4*)&As[buf][kk][ty * 4 + BM / 2];
            *(float4*)&b[0] = *(float4*)&Bs[buf][kk][tx * 4];
            *(float4*)&b[4] = *(float4*)&Bs[buf][kk][tx * 4 + 64];
            #pragma unroll
            for (int i = 0; i < 8; i++)
                #pragma unroll
                for (int j = 0; j < 8; j++)
                    acc[i][j] += a[i] * b[j];
        }
        if (s + 1 < nslab) {
            stA(buf ^ 1); stB(buf ^ 1);
            __syncthreads();
            buf ^= 1;
        }
    }

    if (MODE == 0 || MODE == 1) {
        float bn[8];
        if (MODE == 0) {
            *(float4*)&bn[0] = *(const float4*)(bias + n0 + tx * 4);
            *(float4*)&bn[4] = *(const float4*)(bias + n0 + tx * 4 + 64);
        }
        #pragma unroll
        for (int i = 0; i < 8; i++) {
            const int m = m0 + ty * 4 + (i & 3) + ((i >> 2) * (BM / 2));
            if (m < M) {
                const float bm = (MODE == 1) ? bias[m] : 0.f;
                float4 v0, v1;
                v0.x = acc[i][0] + (MODE == 0 ? bn[0] : bm);
                v0.y = acc[i][1] + (MODE == 0 ? bn[1] : bm);
                v0.z = acc[i][2] + (MODE == 0 ? bn[2] : bm);
                v0.w = acc[i][3] + (MODE == 0 ? bn[3] : bm);
                v1.x = acc[i][4] + (MODE == 0 ? bn[4] : bm);
                v1.y = acc[i][5] + (MODE == 0 ? bn[5] : bm);
                v1.z = acc[i][6] + (MODE == 0 ? bn[6] : bm);
                v1.w = acc[i][7] + (MODE == 0 ? bn[7] : bm);
                *(float4*)(C + (size_t)m * ldc + n0 + tx * 4)      = v0;
                *(float4*)(C + (size_t)m * ldc + n0 + tx * 4 + 64) = v1;
            }
        }
    } else if (MODE == 2) {
        int dj[8], hj[8], wj[8];
        #pragma unroll
        for (int j = 0; j < 8; j++) {
            const int n = n0 + tx * 4 + (j & 3) + ((j >> 2) * 64);
            wj[j] = n % Win;
            const int t = n / Win;
            hj[j] = t % Hin;
            dj[j] = t / Hin;
        }
        const int OD = 2 * Din, OH = 2 * Hin, OW = 2 * Win;
        #pragma unroll
        for (int i = 0; i < 8; i++) {
            const int m = m0 + ty * 4 + (i & 3) + ((i >> 2) * (BM / 2));
            if (m < M) {
                const int o = m >> 3, r = m & 7;
                const int ri = (r >> 2) & 1, rj = (r >> 1) & 1, rk = r & 1;
                const float bv = bias[o];
                #pragma unroll
                for (int j = 0; j < 8; j++) {
                    float v = acc[i][j] + bv;
                    if (SILU) v = v / (1.f + __expf(-v));
                    const size_t idx =
                        ((size_t)(o * OD + 2 * dj[j] + ri) * OH + 2 * hj[j] + rj) * OW
                        + 2 * wj[j] + rk;
                    C[idx] = v;
                }
            }
        }
    } else { // MODE 3
        int hj[8], wj[8];
        #pragma unroll
        for (int j = 0; j < 8; j++) {
            const int n = n0 + tx * 4 + (j & 3) + ((j >> 2) * 64);
            wj[j] = n % Win;
            hj[j] = n / Win;
        }
        const int OH = 2 * Hin, OW = 2 * Win;
        #pragma unroll
        for (int i = 0; i < 8; i++) {
            const int m = m0 + ty * 4 + (i & 3) + ((i >> 2) * (BM / 2));
            if (m < M) {
                const int o = m >> 2, r = m & 3;
                const int ri = (r >> 1) & 1, rj = r & 1;
                const float bv = bias[o];
                #pragma unroll
                for (int j = 0; j < 8; j++) {
                    float v = acc[i][j] + bv;
                    if (SILU) v = v / (1.f + __expf(-v));
                    const size_t idx =
                        (size_t)(o * OH + 2 * hj[j] + ri) * OW + 2 * wj[j] + rj;
                    C[idx] = v;
                }
            }
        }
    }
}

// ---------------------------------------------------------------------------
// 3D neighborhood attention v3 (quad-parallel), now writing bf16 hi/lo
// directly (output only feeds the proj mma).
// ---------------------------------------------------------------------------
__global__ void na3d_attn_v3(const float* __restrict__ qkv,
                             __nv_bfloat16* __restrict__ oh,
                             __nv_bfloat16* __restrict__ ol)
{
    __shared__ float sp[NHEAD][80];

    const int t = blockIdx.x;
    const int d = t / (HH * WW);
    const int rem = t % (HH * WW);
    const int h = rem / WW;
    const int w = rem % WW;
    const int head = threadIdx.x >> 5;
    const int lane = threadIdx.x & 31;
    const int qd  = lane >> 2;
    const int sub = lane & 3;

    const int sd = min(max(d - 1, 0), DD - 3);
    const int sh = min(max(h - 2, 0), HH - 5);
    const int sw = min(max(w - 2, 0), WW - 5);
    const int base = (sd * HH + sh) * WW + sw;

    const float* qp = qkv + (size_t)t * 768 + head * HDIM + sub * 8;
    float4 q0 = *(const float4*)qp;
    float4 q1 = *(const float4*)(qp + 4);
    const float sc0 = 0.17677669529663687f;
    q0.x *= sc0; q0.y *= sc0; q0.z *= sc0; q0.w *= sc0;
    q1.x *= sc0; q1.y *= sc0; q1.z *= sc0; q1.w *= sc0;

    float sc[10];
    #pragma unroll
    for (int r = 0; r < 10; r++) {
        const int n = r * 8 + qd;
        const int nn = (n < 75) ? n : 74;
        const int dd = nn / 25, r2 = nn % 25;
        const int hh2 = r2 / 5, ww2 = r2 % 5;
        const int nb = base + (dd * HH + hh2) * WW + ww2;
        const float* kp = qkv + (size_t)nb * 768 + 256 + head * HDIM + sub * 8;
        const float4 k0 = *(const float4*)kp;
        const float4 k1 = *(const float4*)(kp + 4);
        float s = q0.x * k0.x + q0.y * k0.y + q0.z * k0.z + q0.w * k0.w
                + q1.x * k1.x + q1.y * k1.y + q1.z * k1.z + q1.w * k1.w;
        s += __shfl_xor_sync(0xffffffffu, s, 1);
        s += __shfl_xor_sync(0xffffffffu, s, 2);
        sc[r] = (n < 75) ? s : -1e30f;
    }

    float m = sc[0];
    #pragma unroll
    for (int r = 1; r < 10; r++) m = fmaxf(m, sc[r]);
    m = fmaxf(m, __shfl_xor_sync(0xffffffffu, m, 4));
    m = fmaxf(m, __shfl_xor_sync(0xffffffffu, m, 8));
    m = fmaxf(m, __shfl_xor_sync(0xffffffffu, m, 16));
    float e[10], ssum = 0.f;
    #pragma unroll
    for (int r = 0; r < 10; r++) { e[r] = __expf(sc[r] - m); ssum += e[r]; }
    ssum += __shfl_xor_sync(0xffffffffu, ssum, 4);
    ssum += __shfl_xor_sync(0xffffffffu, ssum, 8);
    ssum += __shfl_xor_sync(0xffffffffu, ssum, 16);
    const float inv = 1.f / ssum;
    if (sub == 0) {
        #pragma unroll
        for (int r = 0; r < 10; r++) {
            const int n = r * 8 + qd;
            if (n < 75) sp[head][n] = e[r] * inv;
        }
    }
    __syncwarp();

    float acc = 0.f;
    const float* vbase = qkv + 512 + head * HDIM + lane;
    int n = 0;
    #pragma unroll
    for (int dd = 0; dd < 3; dd++) {
        #pragma unroll
        for (int hh2 = 0; hh2 < 5; hh2++) {
            const int row = base + (dd * HH + hh2) * WW;
            #pragma unroll
            for (int ww2 = 0; ww2 < 5; ww2++) {
                acc += sp[head][n] * vbase[(size_t)(row + ww2) * 768];
                n++;
            }
        }
    }
    const size_t oidx = (size_t)t * CH + head * HDIM + lane;
    const __nv_bfloat16 hv = __float2bfloat16(acc);
    oh[oidx] = hv;
    ol[oidx] = __float2bfloat16(acc - __bfloat162float(hv));
}

// ---------------------------------------------------------------------------
// Launcher
// ---------------------------------------------------------------------------
extern "C" void kernel_launch(void* const* d_in, const int* in_sizes, int n_in,
                              void* d_out, int out_size)
{
    const float* latent  = (const float*)d_in[0];
    const float* qkv_w   = (const float*)d_in[1];
    const float* qkv_b   = (const float*)d_in[2];
    const float* proj_w  = (const float*)d_in[3];
    const float* proj_b  = (const float*)d_in[4];
    const float* split_w = (const float*)d_in[5];
    const float* split_b = (const float*)d_in[6];
    const float* pw0 = (const float*)d_in[7];
    const float* pb0 = (const float*)d_in[8];
    const float* pw1 = (const float*)d_in[9];
    const float* pb1 = (const float*)d_in[10];
    const float* pw2 = (const float*)d_in[11];
    const float* pb2 = (const float*)d_in[12];
    const float* sw0 = (const float*)d_in[13];
    const float* sb0 = (const float*)d_in[14];
    const float* sw1 = (const float*)d_in[15];
    const float* sb1 = (const float*)d_in[16];
    const float* sw2 = (const float*)d_in[17];
    const float* sb2 = (const float*)d_in[18];
    float* out = (float*)d_out;

    float *qkv, *feats, *s0, *s1;
    __nv_bfloat16 *xah, *xal, *aah, *aal, *wth, *wtl, *fth, *ftl;
    __nv_bfloat16 *b0h, *b0l, *b1h, *b1l;
    cudaGetSymbolAddress((void**)&qkv,   g_qkv);
    cudaGetSymbolAddress((void**)&feats, g_feats);
    cudaGetSymbolAddress((void**)&s0,    g_s0);
    cudaGetSymbolAddress((void**)&s1,    g_s1);
    cudaGetSymbolAddress((void**)&xah,   g_xah);
    cudaGetSymbolAddress((void**)&xal,   g_xal);
    cudaGetSymbolAddress((void**)&aah,   g_aah);
    cudaGetSymbolAddress((void**)&aal,   g_aal);
    cudaGetSymbolAddress((void**)&wth,   g_wth);
    cudaGetSymbolAddress((void**)&wtl,   g_wtl);
    cudaGetSymbolAddress((void**)&fth,   g_fth);
    cudaGetSymbolAddress((void**)&ftl,   g_ftl);
    cudaGetSymbolAddress((void**)&b0h,   g_b0h);
    cudaGetSymbolAddress((void**)&b0l,   g_b0l);
    cudaGetSymbolAddress((void**)&b1h,   g_b1h);
    cudaGetSymbolAddress((void**)&b1l,   g_b1l);

    const dim3 tb(32, 8);

    // initial x = latent -> bf16 hi/lo
    split_rows<<<(TOK * 256 + 255) / 256, 256>>>(latent, xah, xal, TOK * 256);

    for (int l = 0; l < 3; l++) {
        // qkv: A = x (XA), B = qkv_w^T -> fp32 qkv
        transpose_split<<<dim3(768 / 32, 256 / 32), tb>>>(
            qkv_w + l * 256 * 768, wth, wtl, 256, 768, 768);
        gemm_mma<0, false><<<dim3(768 / 128, TOK / 128), 256>>>(
            xah, xal, wth, wtl, qkv_b + l * 768, qkv, nullptr, nullptr,
            TOK, 768, 256, 768, 0, 0, 0);

        na3d_attn_v3<<<TOK, 256>>>(qkv, aah, aal);

        // proj: A = attn (AA), B = proj_w^T -> x bf16 hi/lo (MODE 4)
        transpose_split<<<dim3(256 / 32, 256 / 32), tb>>>(
            proj_w + l * 256 * 256, wth, wtl, 256, 256, 256);
        gemm_mma<4, false><<<dim3(256 / 128, TOK / 128), 256>>>(
            aah, aal, wth, wtl, proj_b + l * 256, nullptr, xah, xal,
            TOK, 256, 256, 256, 0, 0, 0);
    }

    // split (MODE 1): A = split_w [512][256], B = x (XA) -> fp32 feats
    split_rows<<<(512 * 256 + 255) / 256, 256>>>(split_w, wth, wtl, 512 * 256);
    gemm_mma<1, false><<<dim3(TOK / 128, 512 / 128), 256>>>(
        wth, wtl, xah, xal, split_b, feats, nullptr, nullptr,
        512, TOK, 256, TOK, 0, 0, 0);

    // press0 (MODE 5): A = pw0T, B = featsT -> press1's B (bf16, [36864][256])
    transpose_split<<<dim3(2048 / 32, 512 / 32), tb>>>(pw0, wth, wtl, 512, 2048, 2048);
    transpose_split<<<dim3(4608 / 32, 512 / 32), tb>>>(feats, fth, ftl, 512, 4608, TOK);
    gemm_mma<5, true><<<dim3(4608 / 128, 2048 / 128), 256>>>(
        wth, wtl, fth, ftl, pb0, nullptr, b0h, b0l,
        2048, 4608, 512, 256, 4, 24, 48);

    // press1 (MODE 5): A = pw1T, B = b0 -> press2's B (bf16, [294912][128])
    transpose_split<<<dim3(1024 / 32, 256 / 32), tb>>>(pw1, wth, wtl, 256, 1024, 1024);
    gemm_mma<5, true><<<dim3(36864 / 128, 1024 / 128), 256>>>(
        wth, wtl, b0h, b0l, pb1, nullptr, b1h, b1l,
        1024, 36864, 256, 128, 8, 48, 96);

    // press2 (MODE 2, M=40 guarded): A = pw2 padded, B = b1 -> out press region
    pad_split_pw2<<<64, 256>>>(pw2, wth, wtl);
    gemm_mma<2, false><<<dim3(294912 / 128, 1), 256>>>(
        wth, wtl, b1h, b1l, pb2, out + 8 * 192 * 384, nullptr, nullptr,
        40, 294912, 128, 0, 16, 96, 192);

    // surf pyramid (fp32 path, unchanged)
    gemm_db<128, true, false, 3, true><<<dim3(1152 / 128, 1024 / 128), 256>>>(
        sw0, feats + 4 * HH * WW, sb0, s0,
        1024, 1152, 512, 1024, TOK, 0, 0, 24, 48);
    gemm_db<128, true, false, 3, true><<<dim3(4608 / 128, 512 / 128), 256>>>(
        sw1, s0, sb1, s1,
        512, 4608, 256, 512, 4608, 0, 0, 48, 96);
    gemm_db<64, true, false, 3, false><<<dim3(18432 / 128, 1), 128>>>(
        sw2, s1, sb2, out,
        32, 18432, 128, 32, 18432, 0, 0, 96, 192);
}

// round 11
// speedup vs baseline: 1.7006x; 1.7006x over previous
#include <cuda_runtime.h>
#include <cuda_bf16.h>
#include <math.h>
#include <stdint.h>

// ---------------------------------------------------------------------------
// Problem constants
// ---------------------------------------------------------------------------
#define TOK   5760          // 5*24*48
#define CH    256
#define DD    5
#define HH    24
#define WW    48
#define NHEAD 8
#define HDIM  32

// fp32 scratch
__device__ float g_qkv [TOK * 768];
__device__ float g_feats[512 * TOK];                 // channel-first (512, 5, 24, 48)
__device__ float g_p0f [256 * 36864];                // press0 out (256, 8, 48, 96)
__device__ float g_p1f [128 * 294912];               // press1 out (128, 16, 96, 192)
__device__ float g_s0  [256 * 48 * 96];
__device__ float g_s1  [128 * 96 * 192];

// bf16 hi/lo scratch
__device__ __align__(16) __nv_bfloat16 g_xah[TOK * 256],   g_xal[TOK * 256];   // x (layer act)
__device__ __align__(16) __nv_bfloat16 g_aah[TOK * 256],   g_aal[TOK * 256];   // attn out
__device__ __align__(16) __nv_bfloat16 g_wth[2048 * 512],  g_wtl[2048 * 512];  // weight scratch
__device__ __align__(16) __nv_bfloat16 g_fth[4608 * 512],  g_ftl[4608 * 512];  // featsT (press0 B)
__device__ __align__(16) __nv_bfloat16 g_b0h[36864 * 256], g_b0l[36864 * 256]; // p0T (press1 B)

// ---------------------------------------------------------------------------
// fp32 -> bf16 hi/lo split, contiguous
// ---------------------------------------------------------------------------
__global__ void split_rows(const float* __restrict__ in,
                           __nv_bfloat16* __restrict__ oh,
                           __nv_bfloat16* __restrict__ ol, int n)
{
    int i = blockIdx.x * blockDim.x + threadIdx.x;
    if (i < n) {
        float v = in[i];
        __nv_bfloat16 h = __float2bfloat16(v);
        oh[i] = h;
        ol[i] = __float2bfloat16(v - __bfloat162float(h));
    }
}

// fp32 [R][C] (row stride ld) -> bf16 hi/lo [C][R]   (R, C multiples of 32)
__global__ void transpose_split(const float* __restrict__ in,
                                __nv_bfloat16* __restrict__ oh,
                                __nv_bfloat16* __restrict__ ol,
                                int R, int C, int ld)
{
    __shared__ float t[32][33];
    const int r0 = blockIdx.y * 32, c0 = blockIdx.x * 32;
    const int tx = threadIdx.x, ty = threadIdx.y;
    #pragma unroll
    for (int i = ty; i < 32; i += 8)
        t[i][tx] = in[(size_t)(r0 + i) * ld + c0 + tx];
    __syncthreads();
    #pragma unroll
    for (int i = ty; i < 32; i += 8) {
        float v = t[tx][i];
        __nv_bfloat16 h = __float2bfloat16(v);
        oh[(size_t)(c0 + i) * R + r0 + tx] = h;
        ol[(size_t)(c0 + i) * R + r0 + tx] = __float2bfloat16(v - __bfloat162float(h));
    }
}

// ---------------------------------------------------------------------------
// Tensor-core GEMM, bf16x3 split (hi*hi + hi*lo + lo*hi), fp32 accum.
//   C[m][n] = epilogue( sum_k A[m][k]*B[k][n] + bias )
// A given as Ah/Al [M][K] bf16, B as Bh/Bl [N][K] bf16.
// Tile 128x128x32, 256 threads = 8 warps (2 m x 4 n), warp tile 64x32,
// mma.sync.m16n8k16. N multiple of 128; K multiple of 32.
// MODE 0: fp32 C row-major [M][ldc], bias[n]
// MODE 1: fp32 C row-major [M][ldc], bias[m]
// MODE 2: up3d scatter to fp32 C, bias[m>>3], optional SiLU, m<M guarded
// MODE 4: bf16 hi/lo Oh/Ol row-major [M][ldc], bias[n]
// ---------------------------------------------------------------------------
#define MMA_BF16(c, a0, a1, a2, a3, b0, b1)                                   \
    asm volatile("mma.sync.aligned.m16n8k16.row.col.f32.bf16.bf16.f32 "       \
                 "{%0,%1,%2,%3}, {%4,%5,%6,%7}, {%8,%9}, {%0,%1,%2,%3};"      \
                 : "+f"(c[0]), "+f"(c[1]), "+f"(c[2]), "+f"(c[3])             \
                 : "r"(a0), "r"(a1), "r"(a2), "r"(a3), "r"(b0), "r"(b1))

template<int MODE, bool SILU>
__global__ __launch_bounds__(256)
void gemm_mma(const __nv_bfloat16* __restrict__ Ah, const __nv_bfloat16* __restrict__ Al,
              const __nv_bfloat16* __restrict__ Bh, const __nv_bfloat16* __restrict__ Bl,
              const float* __restrict__ bias, float* __restrict__ C,
              __nv_bfloat16* __restrict__ Oh, __nv_bfloat16* __restrict__ Ol,
              int M, int N, int K, int ldc, int Din, int Hin, int Win)
{
    constexpr int RS = 20;                         // smem words per row (16 data + 4 pad)
    __shared__ float sAh[128 * RS], sAl[128 * RS];
    __shared__ float sBh[128 * RS], sBl[128 * RS];

    const int tid  = threadIdx.x;
    const int warp = tid >> 5, lane = tid & 31;
    const int g = lane >> 2, t = lane & 3;
    const int wm = warp & 1, wn = warp >> 1;       // warp tile origin (wm*64, wn*32)
    const int m0 = blockIdx.y * 128, n0 = blockIdx.x * 128;

    const int lrow = tid >> 1, lseg = tid & 1;     // loader: 2 threads/row, 16 bf16 each

    float acc[4][4][4];
    #pragma unroll
    for (int a = 0; a < 4; a++)
        #pragma unroll
        for (int b = 0; b < 4; b++)
            #pragma unroll
            for (int c = 0; c < 4; c++) acc[a][b][c] = 0.f;

    const uint32_t* wAh = (const uint32_t*)sAh;
    const uint32_t* wAl = (const uint32_t*)sAl;
    const uint32_t* wBh = (const uint32_t*)sBh;
    const uint32_t* wBl = (const uint32_t*)sBl;

    for (int k0 = 0; k0 < K; k0 += 32) {
        {
            const size_t ga = (size_t)(m0 + lrow) * K + k0 + lseg * 16;
            const size_t gb = (size_t)(n0 + lrow) * K + k0 + lseg * 16;
            const uint4* pah = (const uint4*)(Ah + ga);
            const uint4* pal = (const uint4*)(Al + ga);
            const uint4* pbh = (const uint4*)(Bh + gb);
            const uint4* pbl = (const uint4*)(Bl + gb);
            uint4* dah = (uint4*)&sAh[lrow * RS + lseg * 8];
            uint4* dal = (uint4*)&sAl[lrow * RS + lseg * 8];
            uint4* dbh = (uint4*)&sBh[lrow * RS + lseg * 8];
            uint4* dbl = (uint4*)&sBl[lrow * RS + lseg * 8];
            dah[0] = pah[0]; dah[1] = pah[1];
            dal[0] = pal[0]; dal[1] = pal[1];
            dbh[0] = pbh[0]; dbh[1] = pbh[1];
            dbl[0] = pbl[0]; dbl[1] = pbl[1];
        }
        __syncthreads();

        #pragma unroll
        for (int ks = 0; ks < 2; ks++) {
            uint32_t bh[4][2], bl[4][2];
            #pragma unroll
            for (int nt = 0; nt < 4; nt++) {
                const int base = (wn * 32 + nt * 8 + g) * RS + ks * 8 + t;
                bh[nt][0] = wBh[base]; bh[nt][1] = wBh[base + 4];
                bl[nt][0] = wBl[base]; bl[nt][1] = wBl[base + 4];
            }
            #pragma unroll
            for (int mt = 0; mt < 4; mt++) {
                const int base  = (wm * 64 + mt * 16 + g) * RS + ks * 8 + t;
                const int base8 = base + 8 * RS;
                const uint32_t ah0 = wAh[base],     ah1 = wAh[base8];
                const uint32_t ah2 = wAh[base + 4], ah3 = wAh[base8 + 4];
                const uint32_t al0 = wAl[base],     al1 = wAl[base8];
                const uint32_t al2 = wAl[base + 4], al3 = wAl[base8 + 4];
                #pragma unroll
                for (int nt = 0; nt < 4; nt++) {
                    MMA_BF16(acc[mt][nt], ah0, ah1, ah2, ah3, bh[nt][0], bh[nt][1]);
                    MMA_BF16(acc[mt][nt], ah0, ah1, ah2, ah3, bl[nt][0], bl[nt][1]);
                    MMA_BF16(acc[mt][nt], al0, al1, al2, al3, bh[nt][0], bh[nt][1]);
                }
            }
        }
        __syncthreads();
    }

    // element (mt, nt, reg): m = m0+wm*64+mt*16+g+(reg>=2)*8,
    //                        n = n0+wn*32+nt*8+t*2+(reg&1)
    if (MODE == 0 || MODE == 1) {
        #pragma unroll
        for (int mt = 0; mt < 4; mt++) {
            const int mb = m0 + wm * 64 + mt * 16 + g;
            const float bmA = (MODE == 1) ? bias[mb]     : 0.f;
            const float bmB = (MODE == 1) ? bias[mb + 8] : 0.f;
            #pragma unroll
            for (int nt = 0; nt < 4; nt++) {
                const int nb = n0 + wn * 32 + nt * 8 + t * 2;
                float b0 = bmA, b1 = bmA, b2 = bmB, b3 = bmB;
                if (MODE == 0) { b0 = b2 = bias[nb]; b1 = b3 = bias[nb + 1]; }
                float2 v0 = make_float2(acc[mt][nt][0] + b0, acc[mt][nt][1] + b1);
                float2 v1 = make_float2(acc[mt][nt][2] + b2, acc[mt][nt][3] + b3);
                *(float2*)&C[(size_t)mb * ldc + nb]       = v0;
                *(float2*)&C[(size_t)(mb + 8) * ldc + nb] = v1;
            }
        }
    } else if (MODE == 4) {
        #pragma unroll
        for (int mt = 0; mt < 4; mt++) {
            const int mb = m0 + wm * 64 + mt * 16 + g;
            #pragma unroll
            for (int nt = 0; nt < 4; nt++) {
                const int nb = n0 + wn * 32 + nt * 8 + t * 2;
                const float b0 = bias[nb], b1 = bias[nb + 1];
                #pragma unroll
                for (int half = 0; half < 2; half++) {
                    const int m = mb + half * 8;
                    const float va = acc[mt][nt][half * 2 + 0] + b0;
                    const float vb = acc[mt][nt][half * 2 + 1] + b1;
                    const __nv_bfloat16 ha = __float2bfloat16(va);
                    const __nv_bfloat16 hb = __float2bfloat16(vb);
                    __nv_bfloat162 hp, lp;
                    hp.x = ha; hp.y = hb;
                    lp.x = __float2bfloat16(va - __bfloat162float(ha));
                    lp.y = __float2bfloat16(vb - __bfloat162float(hb));
                    *(__nv_bfloat162*)&Oh[(size_t)m * ldc + nb] = hp;
                    *(__nv_bfloat162*)&Ol[(size_t)m * ldc + nb] = lp;
                }
            }
        }
    } else { // MODE 2 : up3d scatter to fp32 (o-major)
        int nw[4][2], nh[4][2], nd[4][2];
        #pragma unroll
        for (int nt = 0; nt < 4; nt++)
            #pragma unroll
            for (int e = 0; e < 2; e++) {
                const int n = n0 + wn * 32 + nt * 8 + t * 2 + e;
                nw[nt][e] = n % Win;
                const int tt = n / Win;
                nh[nt][e] = tt % Hin;
                nd[nt][e] = tt / Hin;
            }
        const int OD = 2 * Din, OH = 2 * Hin, OW = 2 * Win;
        #pragma unroll
        for (int mt = 0; mt < 4; mt++) {
            #pragma unroll
            for (int half = 0; half < 2; half++) {
                const int m = m0 + wm * 64 + mt * 16 + g + half * 8;
                if (m < M) {
                    const int o = m >> 3, r = m & 7;
                    const int ri = (r >> 2) & 1, rj = (r >> 1) & 1, rk = r & 1;
                    const float bv = bias[o];
                    #pragma unroll
                    for (int nt = 0; nt < 4; nt++) {
                        #pragma unroll
                        for (int e = 0; e < 2; e++) {
                            float v = acc[mt][nt][half * 2 + e] + bv;
                            if (SILU) v = v / (1.f + __expf(-v));
                            const size_t idx =
                                ((size_t)(o * OD + 2 * nd[nt][e] + ri) * OH
                                 + 2 * nh[nt][e] + rj) * OW + 2 * nw[nt][e] + rk;
                            C[idx] = v;
                        }
                    }
                }
            }
        }
    }
}

// ---------------------------------------------------------------------------
// Double-buffered fp32 SGEMM (press2 / surf chain)
// ---------------------------------------------------------------------------
template<int BM, bool TA, bool TB, int MODE, bool SILU>
__global__ __launch_bounds__(BM * 2)
void gemm_db(const float* __restrict__ A, const float* __restrict__ B,
             const float* __restrict__ bias, float* __restrict__ C,
             int M, int N, int K, int lda, int ldb, int ldc,
             int Din, int Hin, int Win)
{
    constexpr int THREADS = BM * 2;
    __shared__ float As[2][8][BM];
    __shared__ float Bs[2][8][128];
    const int tid = threadIdx.x;
    const int m0 = blockIdx.y * BM;
    const int n0 = blockIdx.x * 128;
    const int tx = tid & 15, ty = tid >> 4;

    int a_k, a_m;
    if (TA) { a_k = tid / (BM / 4); a_m = (tid % (BM / 4)) * 4; }
    else    { a_m = tid >> 1;       a_k = (tid & 1) << 2; }
    const int bn_k = TB ? ((tid & 1) << 2) : (tid >> 5);
    const int bn_n = TB ? (tid >> 1)       : ((tid & 31) << 2);

    float4 ra, rb0, rb1;

    auto ldA = [&](int k0) {
        if (TA) {
            const float* p = A + (size_t)(k0 + a_k) * lda + m0 + a_m;
            float4 v;
            if (m0 + a_m + 3 < M) v = *(const float4*)p;
            else {
                v.x = (m0 + a_m     < M) ? p[0] : 0.f;
                v.y = (m0 + a_m + 1 < M) ? p[1] : 0.f;
                v.z = (m0 + a_m + 2 < M) ? p[2] : 0.f;
                v.w = (m0 + a_m + 3 < M) ? p[3] : 0.f;
            }
            ra = v;
        } else {
            float4 v = make_float4(0.f, 0.f, 0.f, 0.f);
            if (m0 + a_m < M) v = *(const float4*)(A + (size_t)(m0 + a_m) * lda + k0 + a_k);
            ra = v;
        }
    };
    auto ldB = [&](int k0) {
        if (TB) {
            rb0 = *(const float4*)(B + (size_t)(n0 + bn_n) * ldb + k0 + bn_k);
        } else {
            rb0 = *(const float4*)(B + (size_t)(k0 + bn_k) * ldb + n0 + bn_n);
            if (THREADS == 128)
                rb1 = *(const float4*)(B + (size_t)(k0 + bn_k + 4) * ldb + n0 + bn_n);
        }
    };
    auto stA = [&](int buf) {
        if (TA) {
            *(float4*)&As[buf][a_k][a_m] = ra;
        } else {
            As[buf][a_k + 0][a_m] = ra.x; As[buf][a_k + 1][a_m] = ra.y;
            As[buf][a_k + 2][a_m] = ra.z; As[buf][a_k + 3][a_m] = ra.w;
        }
    };
    auto stB = [&](int buf) {
        if (TB) {
            Bs[buf][bn_k + 0][bn_n] = rb0.x; Bs[buf][bn_k + 1][bn_n] = rb0.y;
            Bs[buf][bn_k + 2][bn_n] = rb0.z; Bs[buf][bn_k + 3][bn_n] = rb0.w;
        } else {
            *(float4*)&Bs[buf][bn_k][bn_n] = rb0;
            if (THREADS == 128) *(float4*)&Bs[buf][bn_k + 4][bn_n] = rb1;
        }
    };

    float acc[8][8] = {};

    ldA(0); ldB(0);
    stA(0); stB(0);
    __syncthreads();

    const int nslab = K >> 3;
    int buf = 0;
    for (int s = 0; s < nslab; s++) {
        if (s + 1 < nslab) { ldA((s + 1) << 3); ldB((s + 1) << 3); }
        #pragma unroll
        for (int kk = 0; kk < 8; kk++) {
            float a[8], b[8];
            *(float4*)&a[0] = *(float4*)&As[buf][kk][ty * 4];
            *(float4*)&a[4] = *(float4*)&As[buf][kk][ty * 4 + BM / 2];
            *(float4*)&b[0] = *(float4*)&Bs[buf][kk][tx * 4];
            *(float4*)&b[4] = *(float4*)&Bs[buf][kk][tx * 4 + 64];
            #pragma unroll
            for (int i = 0; i < 8; i++)
                #pragma unroll
                for (int j = 0; j < 8; j++)
                    acc[i][j] += a[i] * b[j];
        }
        if (s + 1 < nslab) {
            stA(buf ^ 1); stB(buf ^ 1);
            __syncthreads();
            buf ^= 1;
        }
    }

    if (MODE == 0 || MODE == 1) {
        float bn[8];
        if (MODE == 0) {
            *(float4*)&bn[0] = *(const float4*)(bias + n0 + tx * 4);
            *(float4*)&bn[4] = *(const float4*)(bias + n0 + tx * 4 + 64);
        }
        #pragma unroll
        for (int i = 0; i < 8; i++) {
            const int m = m0 + ty * 4 + (i & 3) + ((i >> 2) * (BM / 2));
            if (m < M) {
                const float bm = (MODE == 1) ? bias[m] : 0.f;
                float4 v0, v1;
                v0.x = acc[i][0] + (MODE == 0 ? bn[0] : bm);
                v0.y = acc[i][1] + (MODE == 0 ? bn[1] : bm);
                v0.z = acc[i][2] + (MODE == 0 ? bn[2] : bm);
                v0.w = acc[i][3] + (MODE == 0 ? bn[3] : bm);
                v1.x = acc[i][4] + (MODE == 0 ? bn[4] : bm);
                v1.y = acc[i][5] + (MODE == 0 ? bn[5] : bm);
                v1.z = acc[i][6] + (MODE == 0 ? bn[6] : bm);
                v1.w = acc[i][7] + (MODE == 0 ? bn[7] : bm);
                *(float4*)(C + (size_t)m * ldc + n0 + tx * 4)      = v0;
                *(float4*)(C + (size_t)m * ldc + n0 + tx * 4 + 64) = v1;
            }
        }
    } else if (MODE == 2) {
        int dj[8], hj[8], wj[8];
        #pragma unroll
        for (int j = 0; j < 8; j++) {
            const int n = n0 + tx * 4 + (j & 3) + ((j >> 2) * 64);
            wj[j] = n % Win;
            const int t = n / Win;
            hj[j] = t % Hin;
            dj[j] = t / Hin;
        }
        const int OD = 2 * Din, OH = 2 * Hin, OW = 2 * Win;
        #pragma unroll
        for (int i = 0; i < 8; i++) {
            const int m = m0 + ty * 4 + (i & 3) + ((i >> 2) * (BM / 2));
            if (m < M) {
                const int o = m >> 3, r = m & 7;
                const int ri = (r >> 2) & 1, rj = (r >> 1) & 1, rk = r & 1;
                const float bv = bias[o];
                #pragma unroll
                for (int j = 0; j < 8; j++) {
                    float v = acc[i][j] + bv;
                    if (SILU) v = v / (1.f + __expf(-v));
                    const size_t idx =
                        ((size_t)(o * OD + 2 * dj[j] + ri) * OH + 2 * hj[j] + rj) * OW
                        + 2 * wj[j] + rk;
                    C[idx] = v;
                }
            }
        }
    } else { // MODE 3
        int hj[8], wj[8];
        #pragma unroll
        for (int j = 0; j < 8; j++) {
            const int n = n0 + tx * 4 + (j & 3) + ((j >> 2) * 64);
            wj[j] = n % Win;
            hj[j] = n / Win;
        }
        const int OH = 2 * Hin, OW = 2 * Win;
        #pragma unroll
        for (int i = 0; i < 8; i++) {
            const int m = m0 + ty * 4 + (i & 3) + ((i >> 2) * (BM / 2));
            if (m < M) {
                const int o = m >> 2, r = m & 3;
                const int ri = (r >> 1) & 1, rj = r & 1;
                const float bv = bias[o];
                #pragma unroll
                for (int j = 0; j < 8; j++) {
                    float v = acc[i][j] + bv;
                    if (SILU) v = v / (1.f + __expf(-v));
                    const size_t idx =
                        (size_t)(o * OH + 2 * hj[j] + ri) * OW + 2 * wj[j] + rj;
                    C[idx] = v;
                }
            }
        }
    }
}

// ---------------------------------------------------------------------------
// 3D neighborhood attention v3 (quad-parallel), writes bf16 hi/lo directly
// (contiguous per lane -> coalesced).
// ---------------------------------------------------------------------------
__global__ void na3d_attn_v3(const float* __restrict__ qkv,
                             __nv_bfloat16* __restrict__ oh,
                             __nv_bfloat16* __restrict__ ol)
{
    __shared__ float sp[NHEAD][80];

    const int t = blockIdx.x;
    const int d = t / (HH * WW);
    const int rem = t % (HH * WW);
    const int h = rem / WW;
    const int w = rem % WW;
    const int head = threadIdx.x >> 5;
    const int lane = threadIdx.x & 31;
    const int qd  = lane >> 2;
    const int sub = lane & 3;

    const int sd = min(max(d - 1, 0), DD - 3);
    const int sh = min(max(h - 2, 0), HH - 5);
    const int sw = min(max(w - 2, 0), WW - 5);
    const int base = (sd * HH + sh) * WW + sw;

    const float* qp = qkv + (size_t)t * 768 + head * HDIM + sub * 8;
    float4 q0 = *(const float4*)qp;
    float4 q1 = *(const float4*)(qp + 4);
    const float sc0 = 0.17677669529663687f;
    q0.x *= sc0; q0.y *= sc0; q0.z *= sc0; q0.w *= sc0;
    q1.x *= sc0; q1.y *= sc0; q1.z *= sc0; q1.w *= sc0;

    float sc[10];
    #pragma unroll
    for (int r = 0; r < 10; r++) {
        const int n = r * 8 + qd;
        const int nn = (n < 75) ? n : 74;
        const int dd = nn / 25, r2 = nn % 25;
        const int hh2 = r2 / 5, ww2 = r2 % 5;
        const int nb = base + (dd * HH + hh2) * WW + ww2;
        const float* kp = qkv + (size_t)nb * 768 + 256 + head * HDIM + sub * 8;
        const float4 k0 = *(const float4*)kp;
        const float4 k1 = *(const float4*)(kp + 4);
        float s = q0.x * k0.x + q0.y * k0.y + q0.z * k0.z + q0.w * k0.w
                + q1.x * k1.x + q1.y * k1.y + q1.z * k1.z + q1.w * k1.w;
        s += __shfl_xor_sync(0xffffffffu, s, 1);
        s += __shfl_xor_sync(0xffffffffu, s, 2);
        sc[r] = (n < 75) ? s : -1e30f;
    }

    float m = sc[0];
    #pragma unroll
    for (int r = 1; r < 10; r++) m = fmaxf(m, sc[r]);
    m = fmaxf(m, __shfl_xor_sync(0xffffffffu, m, 4));
    m = fmaxf(m, __shfl_xor_sync(0xffffffffu, m, 8));
    m = fmaxf(m, __shfl_xor_sync(0xffffffffu, m, 16));
    float e[10], ssum = 0.f;
    #pragma unroll
    for (int r = 0; r < 10; r++) { e[r] = __expf(sc[r] - m); ssum += e[r]; }
    ssum += __shfl_xor_sync(0xffffffffu, ssum, 4);
    ssum += __shfl_xor_sync(0xffffffffu, ssum, 8);
    ssum += __shfl_xor_sync(0xffffffffu, ssum, 16);
    const float inv = 1.f / ssum;
    if (sub == 0) {
        #pragma unroll
        for (int r = 0; r < 10; r++) {
            const int n = r * 8 + qd;
            if (n < 75) sp[head][n] = e[r] * inv;
        }
    }
    __syncwarp();

    float acc = 0.f;
    const float* vbase = qkv + 512 + head * HDIM + lane;
    int n = 0;
    #pragma unroll
    for (int dd = 0; dd < 3; dd++) {
        #pragma unroll
        for (int hh2 = 0; hh2 < 5; hh2++) {
            const int row = base + (dd * HH + hh2) * WW;
            #pragma unroll
            for (int ww2 = 0; ww2 < 5; ww2++) {
                acc += sp[head][n] * vbase[(size_t)(row + ww2) * 768];
                n++;
            }
        }
    }
    const size_t oidx = (size_t)t * CH + head * HDIM + lane;
    const __nv_bfloat16 hv = __float2bfloat16(acc);
    oh[oidx] = hv;
    ol[oidx] = __float2bfloat16(acc - __bfloat162float(hv));
}

// ---------------------------------------------------------------------------
// Launcher
// ---------------------------------------------------------------------------
extern "C" void kernel_launch(void* const* d_in, const int* in_sizes, int n_in,
                              void* d_out, int out_size)
{
    const float* latent  = (const float*)d_in[0];
    const float* qkv_w   = (const float*)d_in[1];
    const float* qkv_b   = (const float*)d_in[2];
    const float* proj_w  = (const float*)d_in[3];
    const float* proj_b  = (const float*)d_in[4];
    const float* split_w = (const float*)d_in[5];
    const float* split_b = (const float*)d_in[6];
    const float* pw0 = (const float*)d_in[7];
    const float* pb0 = (const float*)d_in[8];
    const float* pw1 = (const float*)d_in[9];
    const float* pb1 = (const float*)d_in[10];
    const float* pw2 = (const float*)d_in[11];
    const float* pb2 = (const float*)d_in[12];
    const float* sw0 = (const float*)d_in[13];
    const float* sb0 = (const float*)d_in[14];
    const float* sw1 = (const float*)d_in[15];
    const float* sb1 = (const float*)d_in[16];
    const float* sw2 = (const float*)d_in[17];
    const float* sb2 = (const float*)d_in[18];
    float* out = (float*)d_out;

    float *qkv, *feats, *p0f, *p1f, *s0, *s1;
    __nv_bfloat16 *xah, *xal, *aah, *aal, *wth, *wtl, *fth, *ftl, *b0h, *b0l;
    cudaGetSymbolAddress((void**)&qkv,   g_qkv);
    cudaGetSymbolAddress((void**)&feats, g_feats);
    cudaGetSymbolAddress((void**)&p0f,   g_p0f);
    cudaGetSymbolAddress((void**)&p1f,   g_p1f);
    cudaGetSymbolAddress((void**)&s0,    g_s0);
    cudaGetSymbolAddress((void**)&s1,    g_s1);
    cudaGetSymbolAddress((void**)&xah,   g_xah);
    cudaGetSymbolAddress((void**)&xal,   g_xal);
    cudaGetSymbolAddress((void**)&aah,   g_aah);
    cudaGetSymbolAddress((void**)&aal,   g_aal);
    cudaGetSymbolAddress((void**)&wth,   g_wth);
    cudaGetSymbolAddress((void**)&wtl,   g_wtl);
    cudaGetSymbolAddress((void**)&fth,   g_fth);
    cudaGetSymbolAddress((void**)&ftl,   g_ftl);
    cudaGetSymbolAddress((void**)&b0h,   g_b0h);
    cudaGetSymbolAddress((void**)&b0l,   g_b0l);

    const dim3 tb(32, 8);

    // initial x = latent -> bf16 hi/lo
    split_rows<<<(TOK * 256 + 255) / 256, 256>>>(latent, xah, xal, TOK * 256);

    for (int l = 0; l < 3; l++) {
        // qkv: A = x, B = qkv_w^T -> fp32 qkv
        transpose_split<<<dim3(768 / 32, 256 / 32), tb>>>(
            qkv_w + l * 256 * 768, wth, wtl, 256, 768, 768);
        gemm_mma<0, false><<<dim3(768 / 128, TOK / 128), 256>>>(
            xah, xal, wth, wtl, qkv_b + l * 768, qkv, nullptr, nullptr,
            TOK, 768, 256, 768, 0, 0, 0);

        na3d_attn_v3<<<TOK, 256>>>(qkv, aah, aal);

        // proj: A = attn, B = proj_w^T -> x bf16 hi/lo (MODE 4)
        transpose_split<<<dim3(256 / 32, 256 / 32), tb>>>(
            proj_w + l * 256 * 256, wth, wtl, 256, 256, 256);
        gemm_mma<4, false><<<dim3(256 / 128, TOK / 128), 256>>>(
            aah, aal, wth, wtl, proj_b + l * 256, nullptr, xah, xal,
            TOK, 256, 256, 256, 0, 0, 0);
    }

    // split (MODE 1): A = split_w [512][256], B = x -> fp32 feats (channel-first)
    split_rows<<<(512 * 256 + 255) / 256, 256>>>(split_w, wth, wtl, 512 * 256);
    gemm_mma<1, false><<<dim3(TOK / 128, 512 / 128), 256>>>(
        wth, wtl, xah, xal, split_b, feats, nullptr, nullptr,
        512, TOK, 256, TOK, 0, 0, 0);

    // press0 (MODE 2): A = pw0T [2048][512], B = featsT [4608][512] -> fp32 p0
    transpose_split<<<dim3(2048 / 32, 512 / 32), tb>>>(pw0, wth, wtl, 512, 2048, 2048);
    transpose_split<<<dim3(4608 / 32, 512 / 32), tb>>>(feats, fth, ftl, 512, 4608, TOK);
    gemm_mma<2, true><<<dim3(4608 / 128, 2048 / 128), 256>>>(
        wth, wtl, fth, ftl, pb0, p0f, nullptr, nullptr,
        2048, 4608, 512, 0, 4, 24, 48);

    // press1 (MODE 2): A = pw1T [1024][256], B = p0T [36864][256] -> fp32 p1
    transpose_split<<<dim3(1024 / 32, 256 / 32), tb>>>(pw1, wth, wtl, 256, 1024, 1024);
    transpose_split<<<dim3(36864 / 32, 256 / 32), tb>>>(p0f, b0h, b0l, 256, 36864, 36864);
    gemm_mma<2, true><<<dim3(36864 / 128, 1024 / 128), 256>>>(
        wth, wtl, b0h, b0l, pb1, p1f, nullptr, nullptr,
        1024, 36864, 256, 0, 8, 48, 96);

    // press2 (fp32, M=40 -> BM=64)
    gemm_db<64, true, false, 2, false><<<dim3(294912 / 128, 1), 128>>>(
        pw2, p1f, pb2, out + 8 * 192 * 384,
        40, 294912, 128, 40, 294912, 0, 16, 96, 192);

    // surf pyramid (fp32 path)
    gemm_db<128, true, false, 3, true><<<dim3(1152 / 128, 1024 / 128), 256>>>(
        sw0, feats + 4 * HH * WW, sb0, s0,
        1024, 1152, 512, 1024, TOK, 0, 0, 24, 48);
    gemm_db<128, true, false, 3, true><<<dim3(4608 / 128, 512 / 128), 256>>>(
        sw1, s0, sb1, s1,
        512, 4608, 256, 512, 4608, 0, 0, 48, 96);
    gemm_db<64, true, false, 3, false><<<dim3(18432 / 128, 1), 128>>>(
        sw2, s1, sb2, out,
        32, 18432, 128, 32, 18432, 0, 0, 96, 192);
}

// round 12
// speedup vs baseline: 1.7342x; 1.0197x over previous
#include <cuda_runtime.h>
#include <cuda_bf16.h>
#include <math.h>
#include <stdint.h>

// ---------------------------------------------------------------------------
// Problem constants
// ---------------------------------------------------------------------------
#define TOK   5760          // 5*24*48
#define CH    256
#define DD    5
#define HH    24
#define WW    48
#define NHEAD 8
#define HDIM  32

// fp32 scratch
__device__ float g_qkv [TOK * 768];
__device__ float g_feats[512 * TOK];                 // channel-first (512, 5, 24, 48)
__device__ float g_p0f [256 * 36864];                // press0 out (256, 8, 48, 96)
__device__ float g_p1f [128 * 294912];               // press1 out (128, 16, 96, 192)
__device__ float g_s0  [256 * 48 * 96];
__device__ float g_s1  [128 * 96 * 192];

// bf16 hi/lo scratch
__device__ __align__(16) __nv_bfloat16 g_xah[TOK * 256],   g_xal[TOK * 256];   // x (layer act)
__device__ __align__(16) __nv_bfloat16 g_aah[TOK * 256],   g_aal[TOK * 256];   // attn out
__device__ __align__(16) __nv_bfloat16 g_wth[2048 * 512],  g_wtl[2048 * 512];  // weight scratch
__device__ __align__(16) __nv_bfloat16 g_fth[4608 * 512],  g_ftl[4608 * 512];  // featsT (press0 B)
__device__ __align__(16) __nv_bfloat16 g_b0h[36864 * 256], g_b0l[36864 * 256]; // p0T (press1 B)

// ---------------------------------------------------------------------------
// fp32 -> bf16 hi/lo split, contiguous
// ---------------------------------------------------------------------------
__global__ void split_rows(const float* __restrict__ in,
                           __nv_bfloat16* __restrict__ oh,
                           __nv_bfloat16* __restrict__ ol, int n)
{
    int i = blockIdx.x * blockDim.x + threadIdx.x;
    if (i < n) {
        float v = in[i];
        __nv_bfloat16 h = __float2bfloat16(v);
        oh[i] = h;
        ol[i] = __float2bfloat16(v - __bfloat162float(h));
    }
}

// fp32 [R][C] (row stride ld) -> bf16 hi/lo [C][R]   (R, C multiples of 32)
__global__ void transpose_split(const float* __restrict__ in,
                                __nv_bfloat16* __restrict__ oh,
                                __nv_bfloat16* __restrict__ ol,
                                int R, int C, int ld)
{
    __shared__ float t[32][33];
    const int r0 = blockIdx.y * 32, c0 = blockIdx.x * 32;
    const int tx = threadIdx.x, ty = threadIdx.y;
    #pragma unroll
    for (int i = ty; i < 32; i += 8)
        t[i][tx] = in[(size_t)(r0 + i) * ld + c0 + tx];
    __syncthreads();
    #pragma unroll
    for (int i = ty; i < 32; i += 8) {
        float v = t[tx][i];
        __nv_bfloat16 h = __float2bfloat16(v);
        oh[(size_t)(c0 + i) * R + r0 + tx] = h;
        ol[(size_t)(c0 + i) * R + r0 + tx] = __float2bfloat16(v - __bfloat162float(h));
    }
}

// ---------------------------------------------------------------------------
// Tensor-core GEMM, bf16x3 split (hi*hi + hi*lo + lo*hi), fp32 accum.
//   C[m][n] = epilogue( sum_k A[m][k]*B[k][n] + bias )
// A given as Ah/Al [M][K] bf16, B as Bh/Bl [N][K] bf16.
// Tile 128x128x32, 256 threads = 8 warps (2 m x 4 n), warp tile 64x32,
// mma.sync.m16n8k16. N multiple of 128; K multiple of 32.
// MODE 0: fp32 C row-major [M][ldc], bias[n]
// MODE 1: fp32 C row-major [M][ldc], bias[m]
// MODE 2: up3d scatter to fp32 C, bias[m>>3], optional SiLU, m<M guarded
// MODE 4: bf16 hi/lo Oh/Ol row-major [M][ldc], bias[n]
// ---------------------------------------------------------------------------
#define MMA_BF16(c, a0, a1, a2, a3, b0, b1)                                   \
    asm volatile("mma.sync.aligned.m16n8k16.row.col.f32.bf16.bf16.f32 "       \
                 "{%0,%1,%2,%3}, {%4,%5,%6,%7}, {%8,%9}, {%0,%1,%2,%3};"      \
                 : "+f"(c[0]), "+f"(c[1]), "+f"(c[2]), "+f"(c[3])             \
                 : "r"(a0), "r"(a1), "r"(a2), "r"(a3), "r"(b0), "r"(b1))

template<int MODE, bool SILU>
__global__ __launch_bounds__(256)
void gemm_mma(const __nv_bfloat16* __restrict__ Ah, const __nv_bfloat16* __restrict__ Al,
              const __nv_bfloat16* __restrict__ Bh, const __nv_bfloat16* __restrict__ Bl,
              const float* __restrict__ bias, float* __restrict__ C,
              __nv_bfloat16* __restrict__ Oh, __nv_bfloat16* __restrict__ Ol,
              int M, int N, int K, int ldc, int Din, int Hin, int Win)
{
    constexpr int RS = 20;                         // smem words per row (16 data + 4 pad)
    __shared__ float sAh[128 * RS], sAl[128 * RS];
    __shared__ float sBh[128 * RS], sBl[128 * RS];

    const int tid  = threadIdx.x;
    const int warp = tid >> 5, lane = tid & 31;
    const int g = lane >> 2, t = lane & 3;
    const int wm = warp & 1, wn = warp >> 1;       // warp tile origin (wm*64, wn*32)
    const int m0 = blockIdx.y * 128, n0 = blockIdx.x * 128;

    const int lrow = tid >> 1, lseg = tid & 1;     // loader: 2 threads/row, 16 bf16 each

    float acc[4][4][4];
    #pragma unroll
    for (int a = 0; a < 4; a++)
        #pragma unroll
        for (int b = 0; b < 4; b++)
            #pragma unroll
            for (int c = 0; c < 4; c++) acc[a][b][c] = 0.f;

    const uint32_t* wAh = (const uint32_t*)sAh;
    const uint32_t* wAl = (const uint32_t*)sAl;
    const uint32_t* wBh = (const uint32_t*)sBh;
    const uint32_t* wBl = (const uint32_t*)sBl;

    for (int k0 = 0; k0 < K; k0 += 32) {
        {
            const size_t ga = (size_t)(m0 + lrow) * K + k0 + lseg * 16;
            const size_t gb = (size_t)(n0 + lrow) * K + k0 + lseg * 16;
            const uint4* pah = (const uint4*)(Ah + ga);
            const uint4* pal = (const uint4*)(Al + ga);
            const uint4* pbh = (const uint4*)(Bh + gb);
            const uint4* pbl = (const uint4*)(Bl + gb);
            uint4* dah = (uint4*)&sAh[lrow * RS + lseg * 8];
            uint4* dal = (uint4*)&sAl[lrow * RS + lseg * 8];
            uint4* dbh = (uint4*)&sBh[lrow * RS + lseg * 8];
            uint4* dbl = (uint4*)&sBl[lrow * RS + lseg * 8];
            dah[0] = pah[0]; dah[1] = pah[1];
            dal[0] = pal[0]; dal[1] = pal[1];
            dbh[0] = pbh[0]; dbh[1] = pbh[1];
            dbl[0] = pbl[0]; dbl[1] = pbl[1];
        }
        __syncthreads();

        #pragma unroll
        for (int ks = 0; ks < 2; ks++) {
            uint32_t bh[4][2], bl[4][2];
            #pragma unroll
            for (int nt = 0; nt < 4; nt++) {
                const int base = (wn * 32 + nt * 8 + g) * RS + ks * 8 + t;
                bh[nt][0] = wBh[base]; bh[nt][1] = wBh[base + 4];
                bl[nt][0] = wBl[base]; bl[nt][1] = wBl[base + 4];
            }
            #pragma unroll
            for (int mt = 0; mt < 4; mt++) {
                const int base  = (wm * 64 + mt * 16 + g) * RS + ks * 8 + t;
                const int base8 = base + 8 * RS;
                const uint32_t ah0 = wAh[base],     ah1 = wAh[base8];
                const uint32_t ah2 = wAh[base + 4], ah3 = wAh[base8 + 4];
                const uint32_t al0 = wAl[base],     al1 = wAl[base8];
                const uint32_t al2 = wAl[base + 4], al3 = wAl[base8 + 4];
                #pragma unroll
                for (int nt = 0; nt < 4; nt++) {
                    MMA_BF16(acc[mt][nt], ah0, ah1, ah2, ah3, bh[nt][0], bh[nt][1]);
                    MMA_BF16(acc[mt][nt], ah0, ah1, ah2, ah3, bl[nt][0], bl[nt][1]);
                    MMA_BF16(acc[mt][nt], al0, al1, al2, al3, bh[nt][0], bh[nt][1]);
                }
            }
        }
        __syncthreads();
    }

    // element (mt, nt, reg): m = m0+wm*64+mt*16+g+(reg>=2)*8,
    //                        n = n0+wn*32+nt*8+t*2+(reg&1)
    if (MODE == 0 || MODE == 1) {
        #pragma unroll
        for (int mt = 0; mt < 4; mt++) {
            const int mb = m0 + wm * 64 + mt * 16 + g;
            const float bmA = (MODE == 1) ? bias[mb]     : 0.f;
            const float bmB = (MODE == 1) ? bias[mb + 8] : 0.f;
            #pragma unroll
            for (int nt = 0; nt < 4; nt++) {
                const int nb = n0 + wn * 32 + nt * 8 + t * 2;
                float b0 = bmA, b1 = bmA, b2 = bmB, b3 = bmB;
                if (MODE == 0) { b0 = b2 = bias[nb]; b1 = b3 = bias[nb + 1]; }
                float2 v0 = make_float2(acc[mt][nt][0] + b0, acc[mt][nt][1] + b1);
                float2 v1 = make_float2(acc[mt][nt][2] + b2, acc[mt][nt][3] + b3);
                *(float2*)&C[(size_t)mb * ldc + nb]       = v0;
                *(float2*)&C[(size_t)(mb + 8) * ldc + nb] = v1;
            }
        }
    } else if (MODE == 4) {
        #pragma unroll
        for (int mt = 0; mt < 4; mt++) {
            const int mb = m0 + wm * 64 + mt * 16 + g;
            #pragma unroll
            for (int nt = 0; nt < 4; nt++) {
                const int nb = n0 + wn * 32 + nt * 8 + t * 2;
                const float b0 = bias[nb], b1 = bias[nb + 1];
                #pragma unroll
                for (int half = 0; half < 2; half++) {
                    const int m = mb + half * 8;
                    const float va = acc[mt][nt][half * 2 + 0] + b0;
                    const float vb = acc[mt][nt][half * 2 + 1] + b1;
                    const __nv_bfloat16 ha = __float2bfloat16(va);
                    const __nv_bfloat16 hb = __float2bfloat16(vb);
                    __nv_bfloat162 hp, lp;
                    hp.x = ha; hp.y = hb;
                    lp.x = __float2bfloat16(va - __bfloat162float(ha));
                    lp.y = __float2bfloat16(vb - __bfloat162float(hb));
                    *(__nv_bfloat162*)&Oh[(size_t)m * ldc + nb] = hp;
                    *(__nv_bfloat162*)&Ol[(size_t)m * ldc + nb] = lp;
                }
            }
        }
    } else { // MODE 2 : up3d scatter to fp32 (o-major)
        int nw[4][2], nh[4][2], nd[4][2];
        #pragma unroll
        for (int nt = 0; nt < 4; nt++)
            #pragma unroll
            for (int e = 0; e < 2; e++) {
                const int n = n0 + wn * 32 + nt * 8 + t * 2 + e;
                nw[nt][e] = n % Win;
                const int tt = n / Win;
                nh[nt][e] = tt % Hin;
                nd[nt][e] = tt / Hin;
            }
        const int OD = 2 * Din, OH = 2 * Hin, OW = 2 * Win;
        #pragma unroll
        for (int mt = 0; mt < 4; mt++) {
            #pragma unroll
            for (int half = 0; half < 2; half++) {
                const int m = m0 + wm * 64 + mt * 16 + g + half * 8;
                if (m < M) {
                    const int o = m >> 3, r = m & 7;
                    const int ri = (r >> 2) & 1, rj = (r >> 1) & 1, rk = r & 1;
                    const float bv = bias[o];
                    #pragma unroll
                    for (int nt = 0; nt < 4; nt++) {
                        #pragma unroll
                        for (int e = 0; e < 2; e++) {
                            float v = acc[mt][nt][half * 2 + e] + bv;
                            if (SILU) v = v / (1.f + __expf(-v));
                            const size_t idx =
                                ((size_t)(o * OD + 2 * nd[nt][e] + ri) * OH
                                 + 2 * nh[nt][e] + rj) * OW + 2 * nw[nt][e] + rk;
                            C[idx] = v;
                        }
                    }
                }
            }
        }
    }
}

// ---------------------------------------------------------------------------
// Double-buffered fp32 SGEMM (press2 / surf chain)
// ---------------------------------------------------------------------------
template<int BM, bool TA, bool TB, int MODE, bool SILU>
__global__ __launch_bounds__(BM * 2)
void gemm_db(const float* __restrict__ A, const float* __restrict__ B,
             const float* __restrict__ bias, float* __restrict__ C,
             int M, int N, int K, int lda, int ldb, int ldc,
             int Din, int Hin, int Win)
{
    constexpr int THREADS = BM * 2;
    __shared__ float As[2][8][BM];
    __shared__ float Bs[2][8][128];
    const int tid = threadIdx.x;
    const int m0 = blockIdx.y * BM;
    const int n0 = blockIdx.x * 128;
    const int tx = tid & 15, ty = tid >> 4;

    int a_k, a_m;
    if (TA) { a_k = tid / (BM / 4); a_m = (tid % (BM / 4)) * 4; }
    else    { a_m = tid >> 1;       a_k = (tid & 1) << 2; }
    const int bn_k = TB ? ((tid & 1) << 2) : (tid >> 5);
    const int bn_n = TB ? (tid >> 1)       : ((tid & 31) << 2);

    float4 ra, rb0, rb1;

    auto ldA = [&](int k0) {
        if (TA) {
            const float* p = A + (size_t)(k0 + a_k) * lda + m0 + a_m;
            float4 v;
            if (m0 + a_m + 3 < M) v = *(const float4*)p;
            else {
                v.x = (m0 + a_m     < M) ? p[0] : 0.f;
                v.y = (m0 + a_m + 1 < M) ? p[1] : 0.f;
                v.z = (m0 + a_m + 2 < M) ? p[2] : 0.f;
                v.w = (m0 + a_m + 3 < M) ? p[3] : 0.f;
            }
            ra = v;
        } else {
            float4 v = make_float4(0.f, 0.f, 0.f, 0.f);
            if (m0 + a_m < M) v = *(const float4*)(A + (size_t)(m0 + a_m) * lda + k0 + a_k);
            ra = v;
        }
    };
    auto ldB = [&](int k0) {
        if (TB) {
            rb0 = *(const float4*)(B + (size_t)(n0 + bn_n) * ldb + k0 + bn_k);
        } else {
            rb0 = *(const float4*)(B + (size_t)(k0 + bn_k) * ldb + n0 + bn_n);
            if (THREADS == 128)
                rb1 = *(const float4*)(B + (size_t)(k0 + bn_k + 4) * ldb + n0 + bn_n);
        }
    };
    auto stA = [&](int buf) {
        if (TA) {
            *(float4*)&As[buf][a_k][a_m] = ra;
        } else {
            As[buf][a_k + 0][a_m] = ra.x; As[buf][a_k + 1][a_m] = ra.y;
            As[buf][a_k + 2][a_m] = ra.z; As[buf][a_k + 3][a_m] = ra.w;
        }
    };
    auto stB = [&](int buf) {
        if (TB) {
            Bs[buf][bn_k + 0][bn_n] = rb0.x; Bs[buf][bn_k + 1][bn_n] = rb0.y;
            Bs[buf][bn_k + 2][bn_n] = rb0.z; Bs[buf][bn_k + 3][bn_n] = rb0.w;
        } else {
            *(float4*)&Bs[buf][bn_k][bn_n] = rb0;
            if (THREADS == 128) *(float4*)&Bs[buf][bn_k + 4][bn_n] = rb1;
        }
    };

    float acc[8][8] = {};

    ldA(0); ldB(0);
    stA(0); stB(0);
    __syncthreads();

    const int nslab = K >> 3;
    int buf = 0;
    for (int s = 0; s < nslab; s++) {
        if (s + 1 < nslab) { ldA((s + 1) << 3); ldB((s + 1) << 3); }
        #pragma unroll
        for (int kk = 0; kk < 8; kk++) {
            float a[8], b[8];
            *(float4*)&a[0] = *(float4*)&As[buf][kk][ty * 4];
            *(float4*)&a[4] = *(float4*)&As[buf][kk][ty * 4 + BM / 2];
            *(float4*)&b[0] = *(float4*)&Bs[buf][kk][tx * 4];
            *(float4*)&b[4] = *(float4*)&Bs[buf][kk][tx * 4 + 64];
            #pragma unroll
            for (int i = 0; i < 8; i++)
                #pragma unroll
                for (int j = 0; j < 8; j++)
                    acc[i][j] += a[i] * b[j];
        }
        if (s + 1 < nslab) {
            stA(buf ^ 1); stB(buf ^ 1);
            __syncthreads();
            buf ^= 1;
        }
    }

    if (MODE == 0 || MODE == 1) {
        float bn[8];
        if (MODE == 0) {
            *(float4*)&bn[0] = *(const float4*)(bias + n0 + tx * 4);
            *(float4*)&bn[4] = *(const float4*)(bias + n0 + tx * 4 + 64);
        }
        #pragma unroll
        for (int i = 0; i < 8; i++) {
            const int m = m0 + ty * 4 + (i & 3) + ((i >> 2) * (BM / 2));
            if (m < M) {
                const float bm = (MODE == 1) ? bias[m] : 0.f;
                float4 v0, v1;
                v0.x = acc[i][0] + (MODE == 0 ? bn[0] : bm);
                v0.y = acc[i][1] + (MODE == 0 ? bn[1] : bm);
                v0.z = acc[i][2] + (MODE == 0 ? bn[2] : bm);
                v0.w = acc[i][3] + (MODE == 0 ? bn[3] : bm);
                v1.x = acc[i][4] + (MODE == 0 ? bn[4] : bm);
                v1.y = acc[i][5] + (MODE == 0 ? bn[5] : bm);
                v1.z = acc[i][6] + (MODE == 0 ? bn[6] : bm);
                v1.w = acc[i][7] + (MODE == 0 ? bn[7] : bm);
                *(float4*)(C + (size_t)m * ldc + n0 + tx * 4)      = v0;
                *(float4*)(C + (size_t)m * ldc + n0 + tx * 4 + 64) = v1;
            }
        }
    } else if (MODE == 2) {
        int dj[8], hj[8], wj[8];
        #pragma unroll
        for (int j = 0; j < 8; j++) {
            const int n = n0 + tx * 4 + (j & 3) + ((j >> 2) * 64);
            wj[j] = n % Win;
            const int t = n / Win;
            hj[j] = t % Hin;
            dj[j] = t / Hin;
        }
        const int OD = 2 * Din, OH = 2 * Hin, OW = 2 * Win;
        #pragma unroll
        for (int i = 0; i < 8; i++) {
            const int m = m0 + ty * 4 + (i & 3) + ((i >> 2) * (BM / 2));
            if (m < M) {
                const int o = m >> 3, r = m & 7;
                const int ri = (r >> 2) & 1, rj = (r >> 1) & 1, rk = r & 1;
                const float bv = bias[o];
                #pragma unroll
                for (int j = 0; j < 8; j++) {
                    float v = acc[i][j] + bv;
                    if (SILU) v = v / (1.f + __expf(-v));
                    const size_t idx =
                        ((size_t)(o * OD + 2 * dj[j] + ri) * OH + 2 * hj[j] + rj) * OW
                        + 2 * wj[j] + rk;
                    C[idx] = v;
                }
            }
        }
    } else { // MODE 3
        int hj[8], wj[8];
        #pragma unroll
        for (int j = 0; j < 8; j++) {
            const int n = n0 + tx * 4 + (j & 3) + ((j >> 2) * 64);
            wj[j] = n % Win;
            hj[j] = n / Win;
        }
        const int OH = 2 * Hin, OW = 2 * Win;
        #pragma unroll
        for (int i = 0; i < 8; i++) {
            const int m = m0 + ty * 4 + (i & 3) + ((i >> 2) * (BM / 2));
            if (m < M) {
                const int o = m >> 2, r = m & 3;
                const int ri = (r >> 1) & 1, rj = r & 1;
                const float bv = bias[o];
                #pragma unroll
                for (int j = 0; j < 8; j++) {
                    float v = acc[i][j] + bv;
                    if (SILU) v = v / (1.f + __expf(-v));
                    const size_t idx =
                        (size_t)(o * OH + 2 * hj[j] + ri) * OW + 2 * wj[j] + rj;
                    C[idx] = v;
                }
            }
        }
    }
}

// ---------------------------------------------------------------------------
// 3D neighborhood attention v5: 4 tokens per block share a window union.
// Block = 4 consecutive-w tokens x 8 heads (256 thr). Warp = head.
// Union = 3 x 5 x 8 = 120 rows (vs 4x75=300) -> 2.5x less K/V traffic.
//  P1: quad qd scores union pos n=r*8+qd vs all 4 tokens' q (dot always
//      computed, invalid (pos,token) -> -1e30). Leader packs float4 -> smem.
//  P2: per-token softmax from smem (invalid entries exp to 0).
//  P3: lane = dim; 120 coalesced V loads; one LDS.128 broadcast gives all
//      4 tokens' probs; 4 FMAs per load.
// ---------------------------------------------------------------------------
__global__ void na3d_attn_v5(const float* __restrict__ qkv,
                             __nv_bfloat16* __restrict__ oh,
                             __nv_bfloat16* __restrict__ ol)
{
    __shared__ __align__(16) float sp[NHEAD][120][4];

    const int t4 = blockIdx.x * 4;
    const int d = t4 / (HH * WW);
    const int rem = t4 % (HH * WW);
    const int h = rem / WW;
    const int w0 = rem % WW;              // multiple of 4, row-aligned
    const int head = threadIdx.x >> 5;
    const int lane = threadIdx.x & 31;
    const int qd  = lane >> 2;            // union w-offset (0..7)
    const int sub = lane & 3;             // dim chunk within quad

    const int sd = min(max(d - 1, 0), DD - 3);
    const int sh = min(max(h - 2, 0), HH - 5);
    const int swu = min(max(w0 - 2, 0), WW - 8);
    int off[4];
    #pragma unroll
    for (int t = 0; t < 4; t++)
        off[t] = min(max(w0 + t - 2, 0), WW - 5) - swu;   // 0..3

    // q fragments for 4 tokens (dims sub*8..sub*8+8), scaled
    const float sc0 = 0.17677669529663687f;
    float4 q0[4], q1[4];
    #pragma unroll
    for (int t = 0; t < 4; t++) {
        const float* qp = qkv + (size_t)(t4 + t) * 768 + head * HDIM + sub * 8;
        q0[t] = *(const float4*)qp;
        q1[t] = *(const float4*)(qp + 4);
        q0[t].x *= sc0; q0[t].y *= sc0; q0[t].z *= sc0; q0[t].w *= sc0;
        q1[t].x *= sc0; q1[t].y *= sc0; q1[t].z *= sc0; q1[t].w *= sc0;
    }

    // P1: 15 rounds x 8 quads = 120 union positions
    for (int r = 0; r < 15; r++) {
        const int dd = r / 5, hh2 = r % 5;
        const int nb = ((sd + dd) * HH + (sh + hh2)) * WW + swu + qd;
        const float* kp = qkv + (size_t)nb * 768 + 256 + head * HDIM + sub * 8;
        const float4 k0 = *(const float4*)kp;
        const float4 k1 = *(const float4*)(kp + 4);
        float4 sv;
        float sr[4];
        #pragma unroll
        for (int t = 0; t < 4; t++) {
            float s = q0[t].x * k0.x + q0[t].y * k0.y + q0[t].z * k0.z + q0[t].w * k0.w
                    + q1[t].x * k1.x + q1[t].y * k1.y + q1[t].z * k1.z + q1[t].w * k1.w;
            s += __shfl_xor_sync(0xffffffffu, s, 1);
            s += __shfl_xor_sync(0xffffffffu, s, 2);
            const bool valid = (qd >= off[t]) && (qd < off[t] + 5);
            sr[t] = valid ? s : -1e30f;
        }
        sv.x = sr[0]; sv.y = sr[1]; sv.z = sr[2]; sv.w = sr[3];
        if (sub == 0) *(float4*)&sp[head][r * 8 + qd][0] = sv;
    }
    __syncwarp();

    // P2: per-token softmax (lane covers n, n+32, n+64, n+96)
    #pragma unroll
    for (int t = 0; t < 4; t++) {
        const float v0 = sp[head][lane][t];
        const float v1 = sp[head][lane + 32][t];
        const float v2 = sp[head][lane + 64][t];
        const float v3 = (lane < 24) ? sp[head][lane + 96][t] : -1e30f;
        float m = fmaxf(fmaxf(v0, v1), fmaxf(v2, v3));
        #pragma unroll
        for (int o = 16; o; o >>= 1) m = fmaxf(m, __shfl_xor_sync(0xffffffffu, m, o));
        const float e0 = __expf(v0 - m);
        const float e1 = __expf(v1 - m);
        const float e2 = __expf(v2 - m);
        const float e3 = (lane < 24) ? __expf(v3 - m) : 0.f;
        float ssum = e0 + e1 + e2 + e3;
        #pragma unroll
        for (int o = 16; o; o >>= 1) ssum += __shfl_xor_sync(0xffffffffu, ssum, o);
        const float inv = 1.f / ssum;
        sp[head][lane][t]      = e0 * inv;
        sp[head][lane + 32][t] = e1 * inv;
        sp[head][lane + 64][t] = e2 * inv;
        if (lane < 24) sp[head][lane + 96][t] = e3 * inv;
    }
    __syncwarp();

    // P3: lane = dim; 120 V loads, 4 FMAs each
    float acc[4] = {0.f, 0.f, 0.f, 0.f};
    const float* vbase = qkv + 512 + head * HDIM + lane;
    int p = 0;
    #pragma unroll
    for (int dd = 0; dd < 3; dd++) {
        #pragma unroll
        for (int hh2 = 0; hh2 < 5; hh2++) {
            const int rowb = ((sd + dd) * HH + (sh + hh2)) * WW + swu;
            #pragma unroll
            for (int wwu = 0; wwu < 8; wwu++) {
                const float v = vbase[(size_t)(rowb + wwu) * 768];
                const float4 pr = *(const float4*)&sp[head][p][0];
                acc[0] += pr.x * v;
                acc[1] += pr.y * v;
                acc[2] += pr.z * v;
                acc[3] += pr.w * v;
                p++;
            }
        }
    }
    #pragma unroll
    for (int t = 0; t < 4; t++) {
        const size_t oidx = (size_t)(t4 + t) * CH + head * HDIM + lane;
        const __nv_bfloat16 hv = __float2bfloat16(acc[t]);
        oh[oidx] = hv;
        ol[oidx] = __float2bfloat16(acc[t] - __bfloat162float(hv));
    }
}

// ---------------------------------------------------------------------------
// Launcher
// ---------------------------------------------------------------------------
extern "C" void kernel_launch(void* const* d_in, const int* in_sizes, int n_in,
                              void* d_out, int out_size)
{
    const float* latent  = (const float*)d_in[0];
    const float* qkv_w   = (const float*)d_in[1];
    const float* qkv_b   = (const float*)d_in[2];
    const float* proj_w  = (const float*)d_in[3];
    const float* proj_b  = (const float*)d_in[4];
    const float* split_w = (const float*)d_in[5];
    const float* split_b = (const float*)d_in[6];
    const float* pw0 = (const float*)d_in[7];
    const float* pb0 = (const float*)d_in[8];
    const float* pw1 = (const float*)d_in[9];
    const float* pb1 = (const float*)d_in[10];
    const float* pw2 = (const float*)d_in[11];
    const float* pb2 = (const float*)d_in[12];
    const float* sw0 = (const float*)d_in[13];
    const float* sb0 = (const float*)d_in[14];
    const float* sw1 = (const float*)d_in[15];
    const float* sb1 = (const float*)d_in[16];
    const float* sw2 = (const float*)d_in[17];
    const float* sb2 = (const float*)d_in[18];
    float* out = (float*)d_out;

    float *qkv, *feats, *p0f, *p1f, *s0, *s1;
    __nv_bfloat16 *xah, *xal, *aah, *aal, *wth, *wtl, *fth, *ftl, *b0h, *b0l;
    cudaGetSymbolAddress((void**)&qkv,   g_qkv);
    cudaGetSymbolAddress((void**)&feats, g_feats);
    cudaGetSymbolAddress((void**)&p0f,   g_p0f);
    cudaGetSymbolAddress((void**)&p1f,   g_p1f);
    cudaGetSymbolAddress((void**)&s0,    g_s0);
    cudaGetSymbolAddress((void**)&s1,    g_s1);
    cudaGetSymbolAddress((void**)&xah,   g_xah);
    cudaGetSymbolAddress((void**)&xal,   g_xal);
    cudaGetSymbolAddress((void**)&aah,   g_aah);
    cudaGetSymbolAddress((void**)&aal,   g_aal);
    cudaGetSymbolAddress((void**)&wth,   g_wth);
    cudaGetSymbolAddress((void**)&wtl,   g_wtl);
    cudaGetSymbolAddress((void**)&fth,   g_fth);
    cudaGetSymbolAddress((void**)&ftl,   g_ftl);
    cudaGetSymbolAddress((void**)&b0h,   g_b0h);
    cudaGetSymbolAddress((void**)&b0l,   g_b0l);

    const dim3 tb(32, 8);

    // initial x = latent -> bf16 hi/lo
    split_rows<<<(TOK * 256 + 255) / 256, 256>>>(latent, xah, xal, TOK * 256);

    for (int l = 0; l < 3; l++) {
        // qkv: A = x, B = qkv_w^T -> fp32 qkv
        transpose_split<<<dim3(768 / 32, 256 / 32), tb>>>(
            qkv_w + l * 256 * 768, wth, wtl, 256, 768, 768);
        gemm_mma<0, false><<<dim3(768 / 128, TOK / 128), 256>>>(
            xah, xal, wth, wtl, qkv_b + l * 768, qkv, nullptr, nullptr,
            TOK, 768, 256, 768, 0, 0, 0);

        na3d_attn_v5<<<TOK / 4, 256>>>(qkv, aah, aal);

        // proj: A = attn, B = proj_w^T -> x bf16 hi/lo (MODE 4)
        transpose_split<<<dim3(256 / 32, 256 / 32), tb>>>(
            proj_w + l * 256 * 256, wth, wtl, 256, 256, 256);
        gemm_mma<4, false><<<dim3(256 / 128, TOK / 128), 256>>>(
            aah, aal, wth, wtl, proj_b + l * 256, nullptr, xah, xal,
            TOK, 256, 256, 256, 0, 0, 0);
    }

    // split (MODE 1): A = split_w [512][256], B = x -> fp32 feats (channel-first)
    split_rows<<<(512 * 256 + 255) / 256, 256>>>(split_w, wth, wtl, 512 * 256);
    gemm_mma<1, false><<<dim3(TOK / 128, 512 / 128), 256>>>(
        wth, wtl, xah, xal, split_b, feats, nullptr, nullptr,
        512, TOK, 256, TOK, 0, 0, 0);

    // press0 (MODE 2): A = pw0T [2048][512], B = featsT [4608][512] -> fp32 p0
    transpose_split<<<dim3(2048 / 32, 512 / 32), tb>>>(pw0, wth, wtl, 512, 2048, 2048);
    transpose_split<<<dim3(4608 / 32, 512 / 32), tb>>>(feats, fth, ftl, 512, 4608, TOK);
    gemm_mma<2, true><<<dim3(4608 / 128, 2048 / 128), 256>>>(
        wth, wtl, fth, ftl, pb0, p0f, nullptr, nullptr,
        2048, 4608, 512, 0, 4, 24, 48);

    // press1 (MODE 2): A = pw1T [1024][256], B = p0T [36864][256] -> fp32 p1
    transpose_split<<<dim3(1024 / 32, 256 / 32), tb>>>(pw1, wth, wtl, 256, 1024, 1024);
    transpose_split<<<dim3(36864 / 32, 256 / 32), tb>>>(p0f, b0h, b0l, 256, 36864, 36864);
    gemm_mma<2, true><<<dim3(36864 / 128, 1024 / 128), 256>>>(
        wth, wtl, b0h, b0l, pb1, p1f, nullptr, nullptr,
        1024, 36864, 256, 0, 8, 48, 96);

    // press2 (fp32, M=40 -> BM=64)
    gemm_db<64, true, false, 2, false><<<dim3(294912 / 128, 1), 128>>>(
        pw2, p1f, pb2, out + 8 * 192 * 384,
        40, 294912, 128, 40, 294912, 0, 16, 96, 192);

    // surf pyramid (fp32 path)
    gemm_db<128, true, false, 3, true><<<dim3(1152 / 128, 1024 / 128), 256>>>(
        sw0, feats + 4 * HH * WW, sb0, s0,
        1024, 1152, 512, 1024, TOK, 0, 0, 24, 48);
    gemm_db<128, true, false, 3, true><<<dim3(4608 / 128, 512 / 128), 256>>>(
        sw1, s0, sb1, s1,
        512, 4608, 256, 512, 4608, 0, 0, 48, 96);
    gemm_db<64, true, false, 3, false><<<dim3(18432 / 128, 1), 128>>>(
        sw2, s1, sb2, out,
        32, 18432, 128, 32, 18432, 0, 0, 96, 192);
}

// round 13
// speedup vs baseline: 1.8411x; 1.0617x over previous
#include <cuda_runtime.h>
#include <cuda_bf16.h>
#include <math.h>
#include <stdint.h>

// ---------------------------------------------------------------------------
// Problem constants
// ---------------------------------------------------------------------------
#define TOK   5760          // 5*24*48
#define CH    256
#define DD    5
#define HH    24
#define WW    48
#define NHEAD 8
#define HDIM  32

// fp32 scratch
__device__ float g_qkv [TOK * 768];
__device__ float g_feats[512 * TOK];                 // channel-first (512, 5, 24, 48)
__device__ float g_p0f [256 * 36864];                // press0 out (256, 8, 48, 96)
__device__ float g_p1f [128 * 294912];               // press1 out (128, 16, 96, 192)
__device__ float g_s0  [256 * 48 * 96];
__device__ float g_s1  [128 * 96 * 192];

// bf16 hi/lo scratch
__device__ __align__(16) __nv_bfloat16 g_xah[TOK * 256],   g_xal[TOK * 256];   // x (layer act)
__device__ __align__(16) __nv_bfloat16 g_aah[TOK * 256],   g_aal[TOK * 256];   // attn out
__device__ __align__(16) __nv_bfloat16 g_wth[2048 * 512],  g_wtl[2048 * 512];  // weight scratch
__device__ __align__(16) __nv_bfloat16 g_fth[4608 * 512],  g_ftl[4608 * 512];  // featsT (press0 B)
__device__ __align__(16) __nv_bfloat16 g_b0h[36864 * 256], g_b0l[36864 * 256]; // p0T (press1 B)

// ---------------------------------------------------------------------------
// fp32 -> bf16 hi/lo split, contiguous
// ---------------------------------------------------------------------------
__global__ void split_rows(const float* __restrict__ in,
                           __nv_bfloat16* __restrict__ oh,
                           __nv_bfloat16* __restrict__ ol, int n)
{
    int i = blockIdx.x * blockDim.x + threadIdx.x;
    if (i < n) {
        float v = in[i];
        __nv_bfloat16 h = __float2bfloat16(v);
        oh[i] = h;
        ol[i] = __float2bfloat16(v - __bfloat162float(h));
    }
}

// fp32 [R][C] (row stride ld) -> bf16 hi/lo [C][R]   (R, C multiples of 32)
__global__ void transpose_split(const float* __restrict__ in,
                                __nv_bfloat16* __restrict__ oh,
                                __nv_bfloat16* __restrict__ ol,
                                int R, int C, int ld)
{
    __shared__ float t[32][33];
    const int r0 = blockIdx.y * 32, c0 = blockIdx.x * 32;
    const int tx = threadIdx.x, ty = threadIdx.y;
    #pragma unroll
    for (int i = ty; i < 32; i += 8)
        t[i][tx] = in[(size_t)(r0 + i) * ld + c0 + tx];
    __syncthreads();
    #pragma unroll
    for (int i = ty; i < 32; i += 8) {
        float v = t[tx][i];
        __nv_bfloat16 h = __float2bfloat16(v);
        oh[(size_t)(c0 + i) * R + r0 + tx] = h;
        ol[(size_t)(c0 + i) * R + r0 + tx] = __float2bfloat16(v - __bfloat162float(h));
    }
}

// ---------------------------------------------------------------------------
// Tensor-core GEMM, bf16x3 split (hi*hi + hi*lo + lo*hi), fp32 accum.
// cp.async double-buffered: loads for slab s+1 overlap MMA of slab s.
//   C[m][n] = epilogue( sum_k A[m][k]*B[k][n] + bias )
// A given as Ah/Al [M][K] bf16, B as Bh/Bl [N][K] bf16.
// Tile 128x128x32, 256 threads = 8 warps (2 m x 4 n), warp tile 64x32,
// mma.sync.m16n8k16. N multiple of 128; K multiple of 32.
// Dynamic smem: 2 buffers x 4 arrays x 128 rows x 20 words = 81920 bytes.
// MODE 0: fp32 C row-major [M][ldc], bias[n]
// MODE 1: fp32 C row-major [M][ldc], bias[m]
// MODE 2: up3d scatter to fp32 C, bias[m>>3], optional SiLU, m<M guarded
// MODE 4: bf16 hi/lo Oh/Ol row-major [M][ldc], bias[n]
// ---------------------------------------------------------------------------
#define MMA_BF16(c, a0, a1, a2, a3, b0, b1)                                   \
    asm volatile("mma.sync.aligned.m16n8k16.row.col.f32.bf16.bf16.f32 "       \
                 "{%0,%1,%2,%3}, {%4,%5,%6,%7}, {%8,%9}, {%0,%1,%2,%3};"      \
                 : "+f"(c[0]), "+f"(c[1]), "+f"(c[2]), "+f"(c[3])             \
                 : "r"(a0), "r"(a1), "r"(a2), "r"(a3), "r"(b0), "r"(b1))

__device__ __forceinline__ void cp16(uint32_t dst, const void* src) {
    asm volatile("cp.async.ca.shared.global [%0], [%1], 16;" :: "r"(dst), "l"(src));
}

#define GEMM_MMA_SMEM 81920

template<int MODE, bool SILU>
__global__ __launch_bounds__(256)
void gemm_mma(const __nv_bfloat16* __restrict__ Ah, const __nv_bfloat16* __restrict__ Al,
              const __nv_bfloat16* __restrict__ Bh, const __nv_bfloat16* __restrict__ Bl,
              const float* __restrict__ bias, float* __restrict__ C,
              __nv_bfloat16* __restrict__ Oh, __nv_bfloat16* __restrict__ Ol,
              int M, int N, int K, int ldc, int Din, int Hin, int Win)
{
    constexpr int RS = 20;                  // smem words per row (16 data + 4 pad)
    constexpr int BUFW = 128 * RS;          // words per array
    extern __shared__ __align__(16) float smem_dyn[];
    const uint32_t sbase = (uint32_t)__cvta_generic_to_shared(smem_dyn);
    const uint32_t* W = (const uint32_t*)smem_dyn;

    const int tid  = threadIdx.x;
    const int warp = tid >> 5, lane = tid & 31;
    const int g = lane >> 2, t = lane & 3;
    const int wm = warp & 1, wn = warp >> 1;       // warp tile origin (wm*64, wn*32)
    const int m0 = blockIdx.y * 128, n0 = blockIdx.x * 128;

    const int lrow = tid >> 1, lseg = tid & 1;     // loader: 2 threads/row, 16 bf16 each

    float acc[4][4][4];
    #pragma unroll
    for (int a = 0; a < 4; a++)
        #pragma unroll
        for (int b = 0; b < 4; b++)
            #pragma unroll
            for (int c = 0; c < 4; c++) acc[a][b][c] = 0.f;

    auto issue = [&](int k0, int buf) {
        const size_t ga = (size_t)(m0 + lrow) * K + k0 + lseg * 16;
        const size_t gb = (size_t)(n0 + lrow) * K + k0 + lseg * 16;
        const uint32_t doff = (uint32_t)(lrow * RS + lseg * 8) * 4;
        const uint32_t p0 = sbase + (uint32_t)(buf * 4 + 0) * BUFW * 4 + doff;
        const uint32_t p1 = sbase + (uint32_t)(buf * 4 + 1) * BUFW * 4 + doff;
        const uint32_t p2 = sbase + (uint32_t)(buf * 4 + 2) * BUFW * 4 + doff;
        const uint32_t p3 = sbase + (uint32_t)(buf * 4 + 3) * BUFW * 4 + doff;
        cp16(p0, Ah + ga); cp16(p0 + 16, Ah + ga + 8);
        cp16(p1, Al + ga); cp16(p1 + 16, Al + ga + 8);
        cp16(p2, Bh + gb); cp16(p2 + 16, Bh + gb + 8);
        cp16(p3, Bl + gb); cp16(p3 + 16, Bl + gb + 8);
    };

    issue(0, 0);
    asm volatile("cp.async.commit_group;" ::: "memory");

    const int nslab = K >> 5;
    int buf = 0;
    for (int s = 0; s < nslab; s++) {
        asm volatile("cp.async.wait_group 0;" ::: "memory");
        __syncthreads();                     // slab s resident; prior compute done
        if (s + 1 < nslab) {
            issue((s + 1) << 5, buf ^ 1);
            asm volatile("cp.async.commit_group;" ::: "memory");
        }

        const int oAh = (buf * 4 + 0) * BUFW;
        const int oAl = (buf * 4 + 1) * BUFW;
        const int oBh = (buf * 4 + 2) * BUFW;
        const int oBl = (buf * 4 + 3) * BUFW;

        #pragma unroll
        for (int ks = 0; ks < 2; ks++) {
            uint32_t bh[4][2], bl[4][2];
            #pragma unroll
            for (int nt = 0; nt < 4; nt++) {
                const int base = (wn * 32 + nt * 8 + g) * RS + ks * 8 + t;
                bh[nt][0] = W[oBh + base]; bh[nt][1] = W[oBh + base + 4];
                bl[nt][0] = W[oBl + base]; bl[nt][1] = W[oBl + base + 4];
            }
            #pragma unroll
            for (int mt = 0; mt < 4; mt++) {
                const int base  = (wm * 64 + mt * 16 + g) * RS + ks * 8 + t;
                const int base8 = base + 8 * RS;
                const uint32_t ah0 = W[oAh + base],     ah1 = W[oAh + base8];
                const uint32_t ah2 = W[oAh + base + 4], ah3 = W[oAh + base8 + 4];
                const uint32_t al0 = W[oAl + base],     al1 = W[oAl + base8];
                const uint32_t al2 = W[oAl + base + 4], al3 = W[oAl + base8 + 4];
                #pragma unroll
                for (int nt = 0; nt < 4; nt++) {
                    MMA_BF16(acc[mt][nt], ah0, ah1, ah2, ah3, bh[nt][0], bh[nt][1]);
                    MMA_BF16(acc[mt][nt], ah0, ah1, ah2, ah3, bl[nt][0], bl[nt][1]);
                    MMA_BF16(acc[mt][nt], al0, al1, al2, al3, bh[nt][0], bh[nt][1]);
                }
            }
        }
        buf ^= 1;
    }

    // element (mt, nt, reg): m = m0+wm*64+mt*16+g+(reg>=2)*8,
    //                        n = n0+wn*32+nt*8+t*2+(reg&1)
    if (MODE == 0 || MODE == 1) {
        #pragma unroll
        for (int mt = 0; mt < 4; mt++) {
            const int mb = m0 + wm * 64 + mt * 16 + g;
            const float bmA = (MODE == 1) ? bias[mb]     : 0.f;
            const float bmB = (MODE == 1) ? bias[mb + 8] : 0.f;
            #pragma unroll
            for (int nt = 0; nt < 4; nt++) {
                const int nb = n0 + wn * 32 + nt * 8 + t * 2;
                float b0 = bmA, b1 = bmA, b2 = bmB, b3 = bmB;
                if (MODE == 0) { b0 = b2 = bias[nb]; b1 = b3 = bias[nb + 1]; }
                float2 v0 = make_float2(acc[mt][nt][0] + b0, acc[mt][nt][1] + b1);
                float2 v1 = make_float2(acc[mt][nt][2] + b2, acc[mt][nt][3] + b3);
                *(float2*)&C[(size_t)mb * ldc + nb]       = v0;
                *(float2*)&C[(size_t)(mb + 8) * ldc + nb] = v1;
            }
        }
    } else if (MODE == 4) {
        #pragma unroll
        for (int mt = 0; mt < 4; mt++) {
            const int mb = m0 + wm * 64 + mt * 16 + g;
            #pragma unroll
            for (int nt = 0; nt < 4; nt++) {
                const int nb = n0 + wn * 32 + nt * 8 + t * 2;
                const float b0 = bias[nb], b1 = bias[nb + 1];
                #pragma unroll
                for (int half = 0; half < 2; half++) {
                    const int m = mb + half * 8;
                    const float va = acc[mt][nt][half * 2 + 0] + b0;
                    const float vb = acc[mt][nt][half * 2 + 1] + b1;
                    const __nv_bfloat16 ha = __float2bfloat16(va);
                    const __nv_bfloat16 hb = __float2bfloat16(vb);
                    __nv_bfloat162 hp, lp;
                    hp.x = ha; hp.y = hb;
                    lp.x = __float2bfloat16(va - __bfloat162float(ha));
                    lp.y = __float2bfloat16(vb - __bfloat162float(hb));
                    *(__nv_bfloat162*)&Oh[(size_t)m * ldc + nb] = hp;
                    *(__nv_bfloat162*)&Ol[(size_t)m * ldc + nb] = lp;
                }
            }
        }
    } else { // MODE 2 : up3d scatter to fp32 (o-major)
        int nw[4][2], nh[4][2], nd[4][2];
        #pragma unroll
        for (int nt = 0; nt < 4; nt++)
            #pragma unroll
            for (int e = 0; e < 2; e++) {
                const int n = n0 + wn * 32 + nt * 8 + t * 2 + e;
                nw[nt][e] = n % Win;
                const int tt = n / Win;
                nh[nt][e] = tt % Hin;
                nd[nt][e] = tt / Hin;
            }
        const int OD = 2 * Din, OH = 2 * Hin, OW = 2 * Win;
        #pragma unroll
        for (int mt = 0; mt < 4; mt++) {
            #pragma unroll
            for (int half = 0; half < 2; half++) {
                const int m = m0 + wm * 64 + mt * 16 + g + half * 8;
                if (m < M) {
                    const int o = m >> 3, r = m & 7;
                    const int ri = (r >> 2) & 1, rj = (r >> 1) & 1, rk = r & 1;
                    const float bv = bias[o];
                    #pragma unroll
                    for (int nt = 0; nt < 4; nt++) {
                        #pragma unroll
                        for (int e = 0; e < 2; e++) {
                            float v = acc[mt][nt][half * 2 + e] + bv;
                            if (SILU) v = v / (1.f + __expf(-v));
                            const size_t idx =
                                ((size_t)(o * OD + 2 * nd[nt][e] + ri) * OH
                                 + 2 * nh[nt][e] + rj) * OW + 2 * nw[nt][e] + rk;
                            C[idx] = v;
                        }
                    }
                }
            }
        }
    }
}

// ---------------------------------------------------------------------------
// Double-buffered fp32 SGEMM (press2 / surf chain)
// ---------------------------------------------------------------------------
template<int BM, bool TA, bool TB, int MODE, bool SILU>
__global__ __launch_bounds__(BM * 2)
void gemm_db(const float* __restrict__ A, const float* __restrict__ B,
             const float* __restrict__ bias, float* __restrict__ C,
             int M, int N, int K, int lda, int ldb, int ldc,
             int Din, int Hin, int Win)
{
    constexpr int THREADS = BM * 2;
    __shared__ float As[2][8][BM];
    __shared__ float Bs[2][8][128];
    const int tid = threadIdx.x;
    const int m0 = blockIdx.y * BM;
    const int n0 = blockIdx.x * 128;
    const int tx = tid & 15, ty = tid >> 4;

    int a_k, a_m;
    if (TA) { a_k = tid / (BM / 4); a_m = (tid % (BM / 4)) * 4; }
    else    { a_m = tid >> 1;       a_k = (tid & 1) << 2; }
    const int bn_k = TB ? ((tid & 1) << 2) : (tid >> 5);
    const int bn_n = TB ? (tid >> 1)       : ((tid & 31) << 2);

    float4 ra, rb0, rb1;

    auto ldA = [&](int k0) {
        if (TA) {
            const float* p = A + (size_t)(k0 + a_k) * lda + m0 + a_m;
            float4 v;
            if (m0 + a_m + 3 < M) v = *(const float4*)p;
            else {
                v.x = (m0 + a_m     < M) ? p[0] : 0.f;
                v.y = (m0 + a_m + 1 < M) ? p[1] : 0.f;
                v.z = (m0 + a_m + 2 < M) ? p[2] : 0.f;
                v.w = (m0 + a_m + 3 < M) ? p[3] : 0.f;
            }
            ra = v;
        } else {
            float4 v = make_float4(0.f, 0.f, 0.f, 0.f);
            if (m0 + a_m < M) v = *(const float4*)(A + (size_t)(m0 + a_m) * lda + k0 + a_k);
            ra = v;
        }
    };
    auto ldB = [&](int k0) {
        if (TB) {
            rb0 = *(const float4*)(B + (size_t)(n0 + bn_n) * ldb + k0 + bn_k);
        } else {
            rb0 = *(const float4*)(B + (size_t)(k0 + bn_k) * ldb + n0 + bn_n);
            if (THREADS == 128)
                rb1 = *(const float4*)(B + (size_t)(k0 + bn_k + 4) * ldb + n0 + bn_n);
        }
    };
    auto stA = [&](int buf) {
        if (TA) {
            *(float4*)&As[buf][a_k][a_m] = ra;
        } else {
            As[buf][a_k + 0][a_m] = ra.x; As[buf][a_k + 1][a_m] = ra.y;
            As[buf][a_k + 2][a_m] = ra.z; As[buf][a_k + 3][a_m] = ra.w;
        }
    };
    auto stB = [&](int buf) {
        if (TB) {
            Bs[buf][bn_k + 0][bn_n] = rb0.x; Bs[buf][bn_k + 1][bn_n] = rb0.y;
            Bs[buf][bn_k + 2][bn_n] = rb0.z; Bs[buf][bn_k + 3][bn_n] = rb0.w;
        } else {
            *(float4*)&Bs[buf][bn_k][bn_n] = rb0;
            if (THREADS == 128) *(float4*)&Bs[buf][bn_k + 4][bn_n] = rb1;
        }
    };

    float acc[8][8] = {};

    ldA(0); ldB(0);
    stA(0); stB(0);
    __syncthreads();

    const int nslab = K >> 3;
    int buf = 0;
    for (int s = 0; s < nslab; s++) {
        if (s + 1 < nslab) { ldA((s + 1) << 3); ldB((s + 1) << 3); }
        #pragma unroll
        for (int kk = 0; kk < 8; kk++) {
            float a[8], b[8];
            *(float4*)&a[0] = *(float4*)&As[buf][kk][ty * 4];
            *(float4*)&a[4] = *(float4*)&As[buf][kk][ty * 4 + BM / 2];
            *(float4*)&b[0] = *(float4*)&Bs[buf][kk][tx * 4];
            *(float4*)&b[4] = *(float4*)&Bs[buf][kk][tx * 4 + 64];
            #pragma unroll
            for (int i = 0; i < 8; i++)
                #pragma unroll
                for (int j = 0; j < 8; j++)
                    acc[i][j] += a[i] * b[j];
        }
        if (s + 1 < nslab) {
            stA(buf ^ 1); stB(buf ^ 1);
            __syncthreads();
            buf ^= 1;
        }
    }

    if (MODE == 0 || MODE == 1) {
        float bn[8];
        if (MODE == 0) {
            *(float4*)&bn[0] = *(const float4*)(bias + n0 + tx * 4);
            *(float4*)&bn[4] = *(const float4*)(bias + n0 + tx * 4 + 64);
        }
        #pragma unroll
        for (int i = 0; i < 8; i++) {
            const int m = m0 + ty * 4 + (i & 3) + ((i >> 2) * (BM / 2));
            if (m < M) {
                const float bm = (MODE == 1) ? bias[m] : 0.f;
                float4 v0, v1;
                v0.x = acc[i][0] + (MODE == 0 ? bn[0] : bm);
                v0.y = acc[i][1] + (MODE == 0 ? bn[1] : bm);
                v0.z = acc[i][2] + (MODE == 0 ? bn[2] : bm);
                v0.w = acc[i][3] + (MODE == 0 ? bn[3] : bm);
                v1.x = acc[i][4] + (MODE == 0 ? bn[4] : bm);
                v1.y = acc[i][5] + (MODE == 0 ? bn[5] : bm);
                v1.z = acc[i][6] + (MODE == 0 ? bn[6] : bm);
                v1.w = acc[i][7] + (MODE == 0 ? bn[7] : bm);
                *(float4*)(C + (size_t)m * ldc + n0 + tx * 4)      = v0;
                *(float4*)(C + (size_t)m * ldc + n0 + tx * 4 + 64) = v1;
            }
        }
    } else if (MODE == 2) {
        int dj[8], hj[8], wj[8];
        #pragma unroll
        for (int j = 0; j < 8; j++) {
            const int n = n0 + tx * 4 + (j & 3) + ((j >> 2) * 64);
            wj[j] = n % Win;
            const int t = n / Win;
            hj[j] = t % Hin;
            dj[j] = t / Hin;
        }
        const int OD = 2 * Din, OH = 2 * Hin, OW = 2 * Win;
        #pragma unroll
        for (int i = 0; i < 8; i++) {
            const int m = m0 + ty * 4 + (i & 3) + ((i >> 2) * (BM / 2));
            if (m < M) {
                const int o = m >> 3, r = m & 7;
                const int ri = (r >> 2) & 1, rj = (r >> 1) & 1, rk = r & 1;
                const float bv = bias[o];
                #pragma unroll
                for (int j = 0; j < 8; j++) {
                    float v = acc[i][j] + bv;
                    if (SILU) v = v / (1.f + __expf(-v));
                    const size_t idx =
                        ((size_t)(o * OD + 2 * dj[j] + ri) * OH + 2 * hj[j] + rj) * OW
                        + 2 * wj[j] + rk;
                    C[idx] = v;
                }
            }
        }
    } else { // MODE 3
        int hj[8], wj[8];
        #pragma unroll
        for (int j = 0; j < 8; j++) {
            const int n = n0 + tx * 4 + (j & 3) + ((j >> 2) * 64);
            wj[j] = n % Win;
            hj[j] = n / Win;
        }
        const int OH = 2 * Hin, OW = 2 * Win;
        #pragma unroll
        for (int i = 0; i < 8; i++) {
            const int m = m0 + ty * 4 + (i & 3) + ((i >> 2) * (BM / 2));
            if (m < M) {
                const int o = m >> 2, r = m & 3;
                const int ri = (r >> 1) & 1, rj = r & 1;
                const float bv = bias[o];
                #pragma unroll
                for (int j = 0; j < 8; j++) {
                    float v = acc[i][j] + bv;
                    if (SILU) v = v / (1.f + __expf(-v));
                    const size_t idx =
                        (size_t)(o * OH + 2 * hj[j] + ri) * OW + 2 * wj[j] + rj;
                    C[idx] = v;
                }
            }
        }
    }
}

// ---------------------------------------------------------------------------
// 3D neighborhood attention v5: 4 tokens per block share a window union.
// ---------------------------------------------------------------------------
__global__ void na3d_attn_v5(const float* __restrict__ qkv,
                             __nv_bfloat16* __restrict__ oh,
                             __nv_bfloat16* __restrict__ ol)
{
    __shared__ __align__(16) float sp[NHEAD][120][4];

    const int t4 = blockIdx.x * 4;
    const int d = t4 / (HH * WW);
    const int rem = t4 % (HH * WW);
    const int h = rem / WW;
    const int w0 = rem % WW;              // multiple of 4, row-aligned
    const int head = threadIdx.x >> 5;
    const int lane = threadIdx.x & 31;
    const int qd  = lane >> 2;            // union w-offset (0..7)
    const int sub = lane & 3;             // dim chunk within quad

    const int sd = min(max(d - 1, 0), DD - 3);
    const int sh = min(max(h - 2, 0), HH - 5);
    const int swu = min(max(w0 - 2, 0), WW - 8);
    int off[4];
    #pragma unroll
    for (int t = 0; t < 4; t++)
        off[t] = min(max(w0 + t - 2, 0), WW - 5) - swu;   // 0..3

    const float sc0 = 0.17677669529663687f;
    float4 q0[4], q1[4];
    #pragma unroll
    for (int t = 0; t < 4; t++) {
        const float* qp = qkv + (size_t)(t4 + t) * 768 + head * HDIM + sub * 8;
        q0[t] = *(const float4*)qp;
        q1[t] = *(const float4*)(qp + 4);
        q0[t].x *= sc0; q0[t].y *= sc0; q0[t].z *= sc0; q0[t].w *= sc0;
        q1[t].x *= sc0; q1[t].y *= sc0; q1[t].z *= sc0; q1[t].w *= sc0;
    }

    for (int r = 0; r < 15; r++) {
        const int dd = r / 5, hh2 = r % 5;
        const int nb = ((sd + dd) * HH + (sh + hh2)) * WW + swu + qd;
        const float* kp = qkv + (size_t)nb * 768 + 256 + head * HDIM + sub * 8;
        const float4 k0 = *(const float4*)kp;
        const float4 k1 = *(const float4*)(kp + 4);
        float4 sv;
        float sr[4];
        #pragma unroll
        for (int t = 0; t < 4; t++) {
            float s = q0[t].x * k0.x + q0[t].y * k0.y + q0[t].z * k0.z + q0[t].w * k0.w
                    + q1[t].x * k1.x + q1[t].y * k1.y + q1[t].z * k1.z + q1[t].w * k1.w;
            s += __shfl_xor_sync(0xffffffffu, s, 1);
            s += __shfl_xor_sync(0xffffffffu, s, 2);
            const bool valid = (qd >= off[t]) && (qd < off[t] + 5);
            sr[t] = valid ? s : -1e30f;
        }
        sv.x = sr[0]; sv.y = sr[1]; sv.z = sr[2]; sv.w = sr[3];
        if (sub == 0) *(float4*)&sp[head][r * 8 + qd][0] = sv;
    }
    __syncwarp();

    #pragma unroll
    for (int t = 0; t < 4; t++) {
        const float v0 = sp[head][lane][t];
        const float v1 = sp[head][lane + 32][t];
        const float v2 = sp[head][lane + 64][t];
        const float v3 = (lane < 24) ? sp[head][lane + 96][t] : -1e30f;
        float m = fmaxf(fmaxf(v0, v1), fmaxf(v2, v3));
        #pragma unroll
        for (int o = 16; o; o >>= 1) m = fmaxf(m, __shfl_xor_sync(0xffffffffu, m, o));
        const float e0 = __expf(v0 - m);
        const float e1 = __expf(v1 - m);
        const float e2 = __expf(v2 - m);
        const float e3 = (lane < 24) ? __expf(v3 - m) : 0.f;
        float ssum = e0 + e1 + e2 + e3;
        #pragma unroll
        for (int o = 16; o; o >>= 1) ssum += __shfl_xor_sync(0xffffffffu, ssum, o);
        const float inv = 1.f / ssum;
        sp[head][lane][t]      = e0 * inv;
        sp[head][lane + 32][t] = e1 * inv;
        sp[head][lane + 64][t] = e2 * inv;
        if (lane < 24) sp[head][lane + 96][t] = e3 * inv;
    }
    __syncwarp();

    float acc[4] = {0.f, 0.f, 0.f, 0.f};
    const float* vbase = qkv + 512 + head * HDIM + lane;
    int p = 0;
    #pragma unroll
    for (int dd = 0; dd < 3; dd++) {
        #pragma unroll
        for (int hh2 = 0; hh2 < 5; hh2++) {
            const int rowb = ((sd + dd) * HH + (sh + hh2)) * WW + swu;
            #pragma unroll
            for (int wwu = 0; wwu < 8; wwu++) {
                const float v = vbase[(size_t)(rowb + wwu) * 768];
                const float4 pr = *(const float4*)&sp[head][p][0];
                acc[0] += pr.x * v;
                acc[1] += pr.y * v;
                acc[2] += pr.z * v;
                acc[3] += pr.w * v;
                p++;
            }
        }
    }
    #pragma unroll
    for (int t = 0; t < 4; t++) {
        const size_t oidx = (size_t)(t4 + t) * CH + head * HDIM + lane;
        const __nv_bfloat16 hv = __float2bfloat16(acc[t]);
        oh[oidx] = hv;
        ol[oidx] = __float2bfloat16(acc[t] - __bfloat162float(hv));
    }
}

// ---------------------------------------------------------------------------
// Launcher
// ---------------------------------------------------------------------------
extern "C" void kernel_launch(void* const* d_in, const int* in_sizes, int n_in,
                              void* d_out, int out_size)
{
    const float* latent  = (const float*)d_in[0];
    const float* qkv_w   = (const float*)d_in[1];
    const float* qkv_b   = (const float*)d_in[2];
    const float* proj_w  = (const float*)d_in[3];
    const float* proj_b  = (const float*)d_in[4];
    const float* split_w = (const float*)d_in[5];
    const float* split_b = (const float*)d_in[6];
    const float* pw0 = (const float*)d_in[7];
    const float* pb0 = (const float*)d_in[8];
    const float* pw1 = (const float*)d_in[9];
    const float* pb1 = (const float*)d_in[10];
    const float* pw2 = (const float*)d_in[11];
    const float* pb2 = (const float*)d_in[12];
    const float* sw0 = (const float*)d_in[13];
    const float* sb0 = (const float*)d_in[14];
    const float* sw1 = (const float*)d_in[15];
    const float* sb1 = (const float*)d_in[16];
    const float* sw2 = (const float*)d_in[17];
    const float* sb2 = (const float*)d_in[18];
    float* out = (float*)d_out;

    float *qkv, *feats, *p0f, *p1f, *s0, *s1;
    __nv_bfloat16 *xah, *xal, *aah, *aal, *wth, *wtl, *fth, *ftl, *b0h, *b0l;
    cudaGetSymbolAddress((void**)&qkv,   g_qkv);
    cudaGetSymbolAddress((void**)&feats, g_feats);
    cudaGetSymbolAddress((void**)&p0f,   g_p0f);
    cudaGetSymbolAddress((void**)&p1f,   g_p1f);
    cudaGetSymbolAddress((void**)&s0,    g_s0);
    cudaGetSymbolAddress((void**)&s1,    g_s1);
    cudaGetSymbolAddress((void**)&xah,   g_xah);
    cudaGetSymbolAddress((void**)&xal,   g_xal);
    cudaGetSymbolAddress((void**)&aah,   g_aah);
    cudaGetSymbolAddress((void**)&aal,   g_aal);
    cudaGetSymbolAddress((void**)&wth,   g_wth);
    cudaGetSymbolAddress((void**)&wtl,   g_wtl);
    cudaGetSymbolAddress((void**)&fth,   g_fth);
    cudaGetSymbolAddress((void**)&ftl,   g_ftl);
    cudaGetSymbolAddress((void**)&b0h,   g_b0h);
    cudaGetSymbolAddress((void**)&b0l,   g_b0l);

    // allow 80KB dynamic smem for the mma kernel (idempotent, capture-safe)
    cudaFuncSetAttribute(gemm_mma<0, false>,
                         cudaFuncAttributeMaxDynamicSharedMemorySize, GEMM_MMA_SMEM);
    cudaFuncSetAttribute(gemm_mma<1, false>,
                         cudaFuncAttributeMaxDynamicSharedMemorySize, GEMM_MMA_SMEM);
    cudaFuncSetAttribute(gemm_mma<2, true>,
                         cudaFuncAttributeMaxDynamicSharedMemorySize, GEMM_MMA_SMEM);
    cudaFuncSetAttribute(gemm_mma<4, false>,
                         cudaFuncAttributeMaxDynamicSharedMemorySize, GEMM_MMA_SMEM);

    const dim3 tb(32, 8);

    // initial x = latent -> bf16 hi/lo
    split_rows<<<(TOK * 256 + 255) / 256, 256>>>(latent, xah, xal, TOK * 256);

    for (int l = 0; l < 3; l++) {
        // qkv: A = x, B = qkv_w^T -> fp32 qkv
        transpose_split<<<dim3(768 / 32, 256 / 32), tb>>>(
            qkv_w + l * 256 * 768, wth, wtl, 256, 768, 768);
        gemm_mma<0, false><<<dim3(768 / 128, TOK / 128), 256, GEMM_MMA_SMEM>>>(
            xah, xal, wth, wtl, qkv_b + l * 768, qkv, nullptr, nullptr,
            TOK, 768, 256, 768, 0, 0, 0);

        na3d_attn_v5<<<TOK / 4, 256>>>(qkv, aah, aal);

        // proj: A = attn, B = proj_w^T -> x bf16 hi/lo (MODE 4)
        transpose_split<<<dim3(256 / 32, 256 / 32), tb>>>(
            proj_w + l * 256 * 256, wth, wtl, 256, 256, 256);
        gemm_mma<4, false><<<dim3(256 / 128, TOK / 128), 256, GEMM_MMA_SMEM>>>(
            aah, aal, wth, wtl, proj_b + l * 256, nullptr, xah, xal,
            TOK, 256, 256, 256, 0, 0, 0);
    }

    // split (MODE 1): A = split_w [512][256], B = x -> fp32 feats (channel-first)
    split_rows<<<(512 * 256 + 255) / 256, 256>>>(split_w, wth, wtl, 512 * 256);
    gemm_mma<1, false><<<dim3(TOK / 128, 512 / 128), 256, GEMM_MMA_SMEM>>>(
        wth, wtl, xah, xal, split_b, feats, nullptr, nullptr,
        512, TOK, 256, TOK, 0, 0, 0);

    // press0 (MODE 2): A = pw0T [2048][512], B = featsT [4608][512] -> fp32 p0
    transpose_split<<<dim3(2048 / 32, 512 / 32), tb>>>(pw0, wth, wtl, 512, 2048, 2048);
    transpose_split<<<dim3(4608 / 32, 512 / 32), tb>>>(feats, fth, ftl, 512, 4608, TOK);
    gemm_mma<2, true><<<dim3(4608 / 128, 2048 / 128), 256, GEMM_MMA_SMEM>>>(
        wth, wtl, fth, ftl, pb0, p0f, nullptr, nullptr,
        2048, 4608, 512, 0, 4, 24, 48);

    // press1 (MODE 2): A = pw1T [1024][256], B = p0T [36864][256] -> fp32 p1
    transpose_split<<<dim3(1024 / 32, 256 / 32), tb>>>(pw1, wth, wtl, 256, 1024, 1024);
    transpose_split<<<dim3(36864 / 32, 256 / 32), tb>>>(p0f, b0h, b0l, 256, 36864, 36864);
    gemm_mma<2, true><<<dim3(36864 / 128, 1024 / 128), 256, GEMM_MMA_SMEM>>>(
        wth, wtl, b0h, b0l, pb1, p1f, nullptr, nullptr,
        1024, 36864, 256, 0, 8, 48, 96);

    // press2 (fp32, M=40 -> BM=64)
    gemm_db<64, true, false, 2, false><<<dim3(294912 / 128, 1), 128>>>(
        pw2, p1f, pb2, out + 8 * 192 * 384,
        40, 294912, 128, 40, 294912, 0, 16, 96, 192);

    // surf pyramid (fp32 path)
    gemm_db<128, true, false, 3, true><<<dim3(1152 / 128, 1024 / 128), 256>>>(
        sw0, feats + 4 * HH * WW, sb0, s0,
        1024, 1152, 512, 1024, TOK, 0, 0, 24, 48);
    gemm_db<128, true, false, 3, true><<<dim3(4608 / 128, 512 / 128), 256>>>(
        sw1, s0, sb1, s1,
        512, 4608, 256, 512, 4608, 0, 0, 48, 96);
    gemm_db<64, true, false, 3, false><<<dim3(18432 / 128, 1), 128>>>(
        sw2, s1, sb2, out,
        32, 18432, 128, 32, 18432, 0, 0, 96, 192);
}

// round 14
// speedup vs baseline: 2.0107x; 1.0921x over previous
#include <cuda_runtime.h>
#include <cuda_bf16.h>
#include <math.h>
#include <stdint.h>

// ---------------------------------------------------------------------------
// Problem constants
// ---------------------------------------------------------------------------
#define TOK   5760          // 5*24*48
#define CH    256
#define DD    5
#define HH    24
#define WW    48
#define NHEAD 8
#define HDIM  32

// fp32 scratch
__device__ float g_qkv [TOK * 768];
__device__ float g_feats[512 * TOK];                 // channel-first (512, 5, 24, 48)
__device__ float g_p0f [256 * 36864];                // press0 out (256, 8, 48, 96)
__device__ float g_p1f [128 * 294912];               // press1 out (128, 16, 96, 192)
__device__ float g_s0  [256 * 48 * 96];
__device__ float g_s1  [128 * 96 * 192];

// bf16 hi/lo scratch
__device__ __align__(16) __nv_bfloat16 g_xah[TOK * 256],   g_xal[TOK * 256];   // x (layer act)
__device__ __align__(16) __nv_bfloat16 g_aah[TOK * 256],   g_aal[TOK * 256];   // attn out
__device__ __align__(16) __nv_bfloat16 g_wth[2048 * 512],  g_wtl[2048 * 512];  // weight scratch
__device__ __align__(16) __nv_bfloat16 g_fth[4608 * 512],  g_ftl[4608 * 512];  // featsT (press0 B)
__device__ __align__(16) __nv_bfloat16 g_b0h[36864 * 256], g_b0l[36864 * 256]; // p0T (press1 B)

// ---------------------------------------------------------------------------
// fp32 -> bf16 hi/lo split, contiguous
// ---------------------------------------------------------------------------
__global__ void split_rows(const float* __restrict__ in,
                           __nv_bfloat16* __restrict__ oh,
                           __nv_bfloat16* __restrict__ ol, int n)
{
    int i = blockIdx.x * blockDim.x + threadIdx.x;
    if (i < n) {
        float v = in[i];
        __nv_bfloat16 h = __float2bfloat16(v);
        oh[i] = h;
        ol[i] = __float2bfloat16(v - __bfloat162float(h));
    }
}

// fp32 [R][C] (row stride ld) -> bf16 hi/lo [C][R]   (R, C multiples of 32)
__global__ void transpose_split(const float* __restrict__ in,
                                __nv_bfloat16* __restrict__ oh,
                                __nv_bfloat16* __restrict__ ol,
                                int R, int C, int ld)
{
    __shared__ float t[32][33];
    const int r0 = blockIdx.y * 32, c0 = blockIdx.x * 32;
    const int tx = threadIdx.x, ty = threadIdx.y;
    #pragma unroll
    for (int i = ty; i < 32; i += 8)
        t[i][tx] = in[(size_t)(r0 + i) * ld + c0 + tx];
    __syncthreads();
    #pragma unroll
    for (int i = ty; i < 32; i += 8) {
        float v = t[tx][i];
        __nv_bfloat16 h = __float2bfloat16(v);
        oh[(size_t)(c0 + i) * R + r0 + tx] = h;
        ol[(size_t)(c0 + i) * R + r0 + tx] = __float2bfloat16(v - __bfloat162float(h));
    }
}

// ---------------------------------------------------------------------------
// Tensor-core GEMM, bf16x3 split (hi*hi + hi*lo + lo*hi), fp32 accum.
// cp.async double-buffered; ldmatrix.x4 fragment loads.
//   C[m][n] = epilogue( sum_k A[m][k]*B[k][n] + bias )
// A given as Ah/Al [M][K] bf16, B as Bh/Bl [N][K] bf16.
// Tile 128x128x32, 256 threads = 8 warps (2 m x 4 n), warp tile 64x32,
// mma.sync.m16n8k16. N multiple of 128; K multiple of 32.
// Dynamic smem: 2 buffers x 4 arrays x 128 rows x 20 words = 81920 bytes.
// MODE 0: fp32 C row-major [M][ldc], bias[n]
// MODE 1: fp32 C row-major [M][ldc], bias[m]
// MODE 2: up3d scatter to fp32 C, bias[m>>3], optional SiLU, m<M guarded
// MODE 4: bf16 hi/lo Oh/Ol row-major [M][ldc], bias[n]
// ---------------------------------------------------------------------------
#define MMA_BF16(c, a0, a1, a2, a3, b0, b1)                                   \
    asm volatile("mma.sync.aligned.m16n8k16.row.col.f32.bf16.bf16.f32 "       \
                 "{%0,%1,%2,%3}, {%4,%5,%6,%7}, {%8,%9}, {%0,%1,%2,%3};"      \
                 : "+f"(c[0]), "+f"(c[1]), "+f"(c[2]), "+f"(c[3])             \
                 : "r"(a0), "r"(a1), "r"(a2), "r"(a3), "r"(b0), "r"(b1))

__device__ __forceinline__ void cp16(uint32_t dst, const void* src) {
    asm volatile("cp.async.ca.shared.global [%0], [%1], 16;" :: "r"(dst), "l"(src));
}

__device__ __forceinline__ void ldsm4(uint32_t& r0, uint32_t& r1,
                                      uint32_t& r2, uint32_t& r3, uint32_t addr) {
    asm volatile("ldmatrix.sync.aligned.m8n8.x4.shared.b16 {%0,%1,%2,%3}, [%4];"
                 : "=r"(r0), "=r"(r1), "=r"(r2), "=r"(r3) : "r"(addr));
}

#define GEMM_MMA_SMEM 81920

template<int MODE, bool SILU>
__global__ __launch_bounds__(256)
void gemm_mma(const __nv_bfloat16* __restrict__ Ah, const __nv_bfloat16* __restrict__ Al,
              const __nv_bfloat16* __restrict__ Bh, const __nv_bfloat16* __restrict__ Bl,
              const float* __restrict__ bias, float* __restrict__ C,
              __nv_bfloat16* __restrict__ Oh, __nv_bfloat16* __restrict__ Ol,
              int M, int N, int K, int ldc, int Din, int Hin, int Win)
{
    constexpr int RS = 20;                  // smem words per row (16 data + 4 pad)
    constexpr int BUFW = 128 * RS;          // words per array
    extern __shared__ __align__(16) float smem_dyn[];
    const uint32_t sbase = (uint32_t)__cvta_generic_to_shared(smem_dyn);

    const int tid  = threadIdx.x;
    const int warp = tid >> 5, lane = tid & 31;
    const int g = lane >> 2, t = lane & 3;
    const int wm = warp & 1, wn = warp >> 1;       // warp tile origin (wm*64, wn*32)
    const int m0 = blockIdx.y * 128, n0 = blockIdx.x * 128;

    const int lrow = tid >> 1, lseg = tid & 1;     // loader: 2 threads/row, 16 bf16 each

    // ldmatrix per-lane row/chunk decomposition
    const int rA = (lane & 7) + ((lane >> 3) & 1) * 8;   // A row within 16
    const int cA = (lane >> 4) & 1;                       // A k-chunk (0/1)
    const int rB = (lane & 7) + ((lane >> 4) & 1) * 8;   // B row within 16
    const int cB = (lane >> 3) & 1;                       // B k-chunk (0/1)

    float acc[4][4][4];
    #pragma unroll
    for (int a = 0; a < 4; a++)
        #pragma unroll
        for (int b = 0; b < 4; b++)
            #pragma unroll
            for (int c = 0; c < 4; c++) acc[a][b][c] = 0.f;

    auto issue = [&](int k0, int buf) {
        const size_t ga = (size_t)(m0 + lrow) * K + k0 + lseg * 16;
        const size_t gb = (size_t)(n0 + lrow) * K + k0 + lseg * 16;
        const uint32_t doff = (uint32_t)(lrow * RS + lseg * 8) * 4;
        const uint32_t p0 = sbase + (uint32_t)(buf * 4 + 0) * BUFW * 4 + doff;
        const uint32_t p1 = sbase + (uint32_t)(buf * 4 + 1) * BUFW * 4 + doff;
        const uint32_t p2 = sbase + (uint32_t)(buf * 4 + 2) * BUFW * 4 + doff;
        const uint32_t p3 = sbase + (uint32_t)(buf * 4 + 3) * BUFW * 4 + doff;
        cp16(p0, Ah + ga); cp16(p0 + 16, Ah + ga + 8);
        cp16(p1, Al + ga); cp16(p1 + 16, Al + ga + 8);
        cp16(p2, Bh + gb); cp16(p2 + 16, Bh + gb + 8);
        cp16(p3, Bl + gb); cp16(p3 + 16, Bl + gb + 8);
    };

    issue(0, 0);
    asm volatile("cp.async.commit_group;" ::: "memory");

    const int nslab = K >> 5;
    int buf = 0;
    for (int s = 0; s < nslab; s++) {
        asm volatile("cp.async.wait_group 0;" ::: "memory");
        __syncthreads();                     // slab s resident; prior compute done
        if (s + 1 < nslab) {
            issue((s + 1) << 5, buf ^ 1);
            asm volatile("cp.async.commit_group;" ::: "memory");
        }

        const uint32_t bAh = sbase + (uint32_t)(buf * 4 + 0) * BUFW * 4;
        const uint32_t bAl = sbase + (uint32_t)(buf * 4 + 1) * BUFW * 4;
        const uint32_t bBh = sbase + (uint32_t)(buf * 4 + 2) * BUFW * 4;
        const uint32_t bBl = sbase + (uint32_t)(buf * 4 + 3) * BUFW * 4;

        #pragma unroll
        for (int ks = 0; ks < 2; ks++) {
            // B fragments: 2x ldmatrix.x4 per array cover nt = 0..3
            uint32_t bh[4][2], bl[4][2];
            #pragma unroll
            for (int p = 0; p < 2; p++) {
                const uint32_t boff =
                    (uint32_t)((wn * 32 + p * 16 + rB) * RS + ks * 8 + cB * 4) * 4;
                ldsm4(bh[2 * p][0], bh[2 * p][1], bh[2 * p + 1][0], bh[2 * p + 1][1],
                      bBh + boff);
                ldsm4(bl[2 * p][0], bl[2 * p][1], bl[2 * p + 1][0], bl[2 * p + 1][1],
                      bBl + boff);
            }
            #pragma unroll
            for (int mt = 0; mt < 4; mt++) {
                const uint32_t aoff =
                    (uint32_t)((wm * 64 + mt * 16 + rA) * RS + ks * 8 + cA * 4) * 4;
                uint32_t ah0, ah1, ah2, ah3, al0, al1, al2, al3;
                ldsm4(ah0, ah1, ah2, ah3, bAh + aoff);
                ldsm4(al0, al1, al2, al3, bAl + aoff);
                #pragma unroll
                for (int nt = 0; nt < 4; nt++) {
                    MMA_BF16(acc[mt][nt], ah0, ah1, ah2, ah3, bh[nt][0], bh[nt][1]);
                    MMA_BF16(acc[mt][nt], ah0, ah1, ah2, ah3, bl[nt][0], bl[nt][1]);
                    MMA_BF16(acc[mt][nt], al0, al1, al2, al3, bh[nt][0], bh[nt][1]);
                }
            }
        }
        buf ^= 1;
    }

    // element (mt, nt, reg): m = m0+wm*64+mt*16+g+(reg>=2)*8,
    //                        n = n0+wn*32+nt*8+t*2+(reg&1)
    if (MODE == 0 || MODE == 1) {
        #pragma unroll
        for (int mt = 0; mt < 4; mt++) {
            const int mb = m0 + wm * 64 + mt * 16 + g;
            const float bmA = (MODE == 1) ? bias[mb]     : 0.f;
            const float bmB = (MODE == 1) ? bias[mb + 8] : 0.f;
            #pragma unroll
            for (int nt = 0; nt < 4; nt++) {
                const int nb = n0 + wn * 32 + nt * 8 + t * 2;
                float b0 = bmA, b1 = bmA, b2 = bmB, b3 = bmB;
                if (MODE == 0) { b0 = b2 = bias[nb]; b1 = b3 = bias[nb + 1]; }
                float2 v0 = make_float2(acc[mt][nt][0] + b0, acc[mt][nt][1] + b1);
                float2 v1 = make_float2(acc[mt][nt][2] + b2, acc[mt][nt][3] + b3);
                *(float2*)&C[(size_t)mb * ldc + nb]       = v0;
                *(float2*)&C[(size_t)(mb + 8) * ldc + nb] = v1;
            }
        }
    } else if (MODE == 4) {
        #pragma unroll
        for (int mt = 0; mt < 4; mt++) {
            const int mb = m0 + wm * 64 + mt * 16 + g;
            #pragma unroll
            for (int nt = 0; nt < 4; nt++) {
                const int nb = n0 + wn * 32 + nt * 8 + t * 2;
                const float b0 = bias[nb], b1 = bias[nb + 1];
                #pragma unroll
                for (int half = 0; half < 2; half++) {
                    const int m = mb + half * 8;
                    const float va = acc[mt][nt][half * 2 + 0] + b0;
                    const float vb = acc[mt][nt][half * 2 + 1] + b1;
                    const __nv_bfloat16 ha = __float2bfloat16(va);
                    const __nv_bfloat16 hb = __float2bfloat16(vb);
                    __nv_bfloat162 hp, lp;
                    hp.x = ha; hp.y = hb;
                    lp.x = __float2bfloat16(va - __bfloat162float(ha));
                    lp.y = __float2bfloat16(vb - __bfloat162float(hb));
                    *(__nv_bfloat162*)&Oh[(size_t)m * ldc + nb] = hp;
                    *(__nv_bfloat162*)&Ol[(size_t)m * ldc + nb] = lp;
                }
            }
        }
    } else { // MODE 2 : up3d scatter to fp32 (o-major)
        int nw[4][2], nh[4][2], nd[4][2];
        #pragma unroll
        for (int nt = 0; nt < 4; nt++)
            #pragma unroll
            for (int e = 0; e < 2; e++) {
                const int n = n0 + wn * 32 + nt * 8 + t * 2 + e;
                nw[nt][e] = n % Win;
                const int tt = n / Win;
                nh[nt][e] = tt % Hin;
                nd[nt][e] = tt / Hin;
            }
        const int OD = 2 * Din, OH = 2 * Hin, OW = 2 * Win;
        #pragma unroll
        for (int mt = 0; mt < 4; mt++) {
            #pragma unroll
            for (int half = 0; half < 2; half++) {
                const int m = m0 + wm * 64 + mt * 16 + g + half * 8;
                if (m < M) {
                    const int o = m >> 3, r = m & 7;
                    const int ri = (r >> 2) & 1, rj = (r >> 1) & 1, rk = r & 1;
                    const float bv = bias[o];
                    #pragma unroll
                    for (int nt = 0; nt < 4; nt++) {
                        #pragma unroll
                        for (int e = 0; e < 2; e++) {
                            float v = acc[mt][nt][half * 2 + e] + bv;
                            if (SILU) v = v / (1.f + __expf(-v));
                            const size_t idx =
                                ((size_t)(o * OD + 2 * nd[nt][e] + ri) * OH
                                 + 2 * nh[nt][e] + rj) * OW + 2 * nw[nt][e] + rk;
                            C[idx] = v;
                        }
                    }
                }
            }
        }
    }
}

// ---------------------------------------------------------------------------
// Double-buffered fp32 SGEMM (press2 / surf chain)
// ---------------------------------------------------------------------------
template<int BM, bool TA, bool TB, int MODE, bool SILU>
__global__ __launch_bounds__(BM * 2)
void gemm_db(const float* __restrict__ A, const float* __restrict__ B,
             const float* __restrict__ bias, float* __restrict__ C,
             int M, int N, int K, int lda, int ldb, int ldc,
             int Din, int Hin, int Win)
{
    constexpr int THREADS = BM * 2;
    __shared__ float As[2][8][BM];
    __shared__ float Bs[2][8][128];
    const int tid = threadIdx.x;
    const int m0 = blockIdx.y * BM;
    const int n0 = blockIdx.x * 128;
    const int tx = tid & 15, ty = tid >> 4;

    int a_k, a_m;
    if (TA) { a_k = tid / (BM / 4); a_m = (tid % (BM / 4)) * 4; }
    else    { a_m = tid >> 1;       a_k = (tid & 1) << 2; }
    const int bn_k = TB ? ((tid & 1) << 2) : (tid >> 5);
    const int bn_n = TB ? (tid >> 1)       : ((tid & 31) << 2);

    float4 ra, rb0, rb1;

    auto ldA = [&](int k0) {
        if (TA) {
            const float* p = A + (size_t)(k0 + a_k) * lda + m0 + a_m;
            float4 v;
            if (m0 + a_m + 3 < M) v = *(const float4*)p;
            else {
                v.x = (m0 + a_m     < M) ? p[0] : 0.f;
                v.y = (m0 + a_m + 1 < M) ? p[1] : 0.f;
                v.z = (m0 + a_m + 2 < M) ? p[2] : 0.f;
                v.w = (m0 + a_m + 3 < M) ? p[3] : 0.f;
            }
            ra = v;
        } else {
            float4 v = make_float4(0.f, 0.f, 0.f, 0.f);
            if (m0 + a_m < M) v = *(const float4*)(A + (size_t)(m0 + a_m) * lda + k0 + a_k);
            ra = v;
        }
    };
    auto ldB = [&](int k0) {
        if (TB) {
            rb0 = *(const float4*)(B + (size_t)(n0 + bn_n) * ldb + k0 + bn_k);
        } else {
            rb0 = *(const float4*)(B + (size_t)(k0 + bn_k) * ldb + n0 + bn_n);
            if (THREADS == 128)
                rb1 = *(const float4*)(B + (size_t)(k0 + bn_k + 4) * ldb + n0 + bn_n);
        }
    };
    auto stA = [&](int buf) {
        if (TA) {
            *(float4*)&As[buf][a_k][a_m] = ra;
        } else {
            As[buf][a_k + 0][a_m] = ra.x; As[buf][a_k + 1][a_m] = ra.y;
            As[buf][a_k + 2][a_m] = ra.z; As[buf][a_k + 3][a_m] = ra.w;
        }
    };
    auto stB = [&](int buf) {
        if (TB) {
            Bs[buf][bn_k + 0][bn_n] = rb0.x; Bs[buf][bn_k + 1][bn_n] = rb0.y;
            Bs[buf][bn_k + 2][bn_n] = rb0.z; Bs[buf][bn_k + 3][bn_n] = rb0.w;
        } else {
            *(float4*)&Bs[buf][bn_k][bn_n] = rb0;
            if (THREADS == 128) *(float4*)&Bs[buf][bn_k + 4][bn_n] = rb1;
        }
    };

    float acc[8][8] = {};

    ldA(0); ldB(0);
    stA(0); stB(0);
    __syncthreads();

    const int nslab = K >> 3;
    int buf = 0;
    for (int s = 0; s < nslab; s++) {
        if (s + 1 < nslab) { ldA((s + 1) << 3); ldB((s + 1) << 3); }
        #pragma unroll
        for (int kk = 0; kk < 8; kk++) {
            float a[8], b[8];
            *(float4*)&a[0] = *(float4*)&As[buf][kk][ty * 4];
            *(float4*)&a[4] = *(float4*)&As[buf][kk][ty * 4 + BM / 2];
            *(float4*)&b[0] = *(float4*)&Bs[buf][kk][tx * 4];
            *(float4*)&b[4] = *(float4*)&Bs[buf][kk][tx * 4 + 64];
            #pragma unroll
            for (int i = 0; i < 8; i++)
                #pragma unroll
                for (int j = 0; j < 8; j++)
                    acc[i][j] += a[i] * b[j];
        }
        if (s + 1 < nslab) {
            stA(buf ^ 1); stB(buf ^ 1);
            __syncthreads();
            buf ^= 1;
        }
    }

    if (MODE == 0 || MODE == 1) {
        float bn[8];
        if (MODE == 0) {
            *(float4*)&bn[0] = *(const float4*)(bias + n0 + tx * 4);
            *(float4*)&bn[4] = *(const float4*)(bias + n0 + tx * 4 + 64);
        }
        #pragma unroll
        for (int i = 0; i < 8; i++) {
            const int m = m0 + ty * 4 + (i & 3) + ((i >> 2) * (BM / 2));
            if (m < M) {
                const float bm = (MODE == 1) ? bias[m] : 0.f;
                float4 v0, v1;
                v0.x = acc[i][0] + (MODE == 0 ? bn[0] : bm);
                v0.y = acc[i][1] + (MODE == 0 ? bn[1] : bm);
                v0.z = acc[i][2] + (MODE == 0 ? bn[2] : bm);
                v0.w = acc[i][3] + (MODE == 0 ? bn[3] : bm);
                v1.x = acc[i][4] + (MODE == 0 ? bn[4] : bm);
                v1.y = acc[i][5] + (MODE == 0 ? bn[5] : bm);
                v1.z = acc[i][6] + (MODE == 0 ? bn[6] : bm);
                v1.w = acc[i][7] + (MODE == 0 ? bn[7] : bm);
                *(float4*)(C + (size_t)m * ldc + n0 + tx * 4)      = v0;
                *(float4*)(C + (size_t)m * ldc + n0 + tx * 4 + 64) = v1;
            }
        }
    } else if (MODE == 2) {
        int dj[8], hj[8], wj[8];
        #pragma unroll
        for (int j = 0; j < 8; j++) {
            const int n = n0 + tx * 4 + (j & 3) + ((j >> 2) * 64);
            wj[j] = n % Win;
            const int t = n / Win;
            hj[j] = t % Hin;
            dj[j] = t / Hin;
        }
        const int OD = 2 * Din, OH = 2 * Hin, OW = 2 * Win;
        #pragma unroll
        for (int i = 0; i < 8; i++) {
            const int m = m0 + ty * 4 + (i & 3) + ((i >> 2) * (BM / 2));
            if (m < M) {
                const int o = m >> 3, r = m & 7;
                const int ri = (r >> 2) & 1, rj = (r >> 1) & 1, rk = r & 1;
                const float bv = bias[o];
                #pragma unroll
                for (int j = 0; j < 8; j++) {
                    float v = acc[i][j] + bv;
                    if (SILU) v = v / (1.f + __expf(-v));
                    const size_t idx =
                        ((size_t)(o * OD + 2 * dj[j] + ri) * OH + 2 * hj[j] + rj) * OW
                        + 2 * wj[j] + rk;
                    C[idx] = v;
                }
            }
        }
    } else { // MODE 3
        int hj[8], wj[8];
        #pragma unroll
        for (int j = 0; j < 8; j++) {
            const int n = n0 + tx * 4 + (j & 3) + ((j >> 2) * 64);
            wj[j] = n % Win;
            hj[j] = n / Win;
        }
        const int OH = 2 * Hin, OW = 2 * Win;
        #pragma unroll
        for (int i = 0; i < 8; i++) {
            const int m = m0 + ty * 4 + (i & 3) + ((i >> 2) * (BM / 2));
            if (m < M) {
                const int o = m >> 2, r = m & 3;
                const int ri = (r >> 1) & 1, rj = r & 1;
                const float bv = bias[o];
                #pragma unroll
                for (int j = 0; j < 8; j++) {
                    float v = acc[i][j] + bv;
                    if (SILU) v = v / (1.f + __expf(-v));
                    const size_t idx =
                        (size_t)(o * OH + 2 * hj[j] + ri) * OW + 2 * wj[j] + rj;
                    C[idx] = v;
                }
            }
        }
    }
}

// ---------------------------------------------------------------------------
// 3D neighborhood attention v5: 4 tokens per block share a window union.
// ---------------------------------------------------------------------------
__global__ void na3d_attn_v5(const float* __restrict__ qkv,
                             __nv_bfloat16* __restrict__ oh,
                             __nv_bfloat16* __restrict__ ol)
{
    __shared__ __align__(16) float sp[NHEAD][120][4];

    const int t4 = blockIdx.x * 4;
    const int d = t4 / (HH * WW);
    const int rem = t4 % (HH * WW);
    const int h = rem / WW;
    const int w0 = rem % WW;              // multiple of 4, row-aligned
    const int head = threadIdx.x >> 5;
    const int lane = threadIdx.x & 31;
    const int qd  = lane >> 2;            // union w-offset (0..7)
    const int sub = lane & 3;             // dim chunk within quad

    const int sd = min(max(d - 1, 0), DD - 3);
    const int sh = min(max(h - 2, 0), HH - 5);
    const int swu = min(max(w0 - 2, 0), WW - 8);
    int off[4];
    #pragma unroll
    for (int t = 0; t < 4; t++)
        off[t] = min(max(w0 + t - 2, 0), WW - 5) - swu;   // 0..3

    const float sc0 = 0.17677669529663687f;
    float4 q0[4], q1[4];
    #pragma unroll
    for (int t = 0; t < 4; t++) {
        const float* qp = qkv + (size_t)(t4 + t) * 768 + head * HDIM + sub * 8;
        q0[t] = *(const float4*)qp;
        q1[t] = *(const float4*)(qp + 4);
        q0[t].x *= sc0; q0[t].y *= sc0; q0[t].z *= sc0; q0[t].w *= sc0;
        q1[t].x *= sc0; q1[t].y *= sc0; q1[t].z *= sc0; q1[t].w *= sc0;
    }

    for (int r = 0; r < 15; r++) {
        const int dd = r / 5, hh2 = r % 5;
        const int nb = ((sd + dd) * HH + (sh + hh2)) * WW + swu + qd;
        const float* kp = qkv + (size_t)nb * 768 + 256 + head * HDIM + sub * 8;
        const float4 k0 = *(const float4*)kp;
        const float4 k1 = *(const float4*)(kp + 4);
        float4 sv;
        float sr[4];
        #pragma unroll
        for (int t = 0; t < 4; t++) {
            float s = q0[t].x * k0.x + q0[t].y * k0.y + q0[t].z * k0.z + q0[t].w * k0.w
                    + q1[t].x * k1.x + q1[t].y * k1.y + q1[t].z * k1.z + q1[t].w * k1.w;
            s += __shfl_xor_sync(0xffffffffu, s, 1);
            s += __shfl_xor_sync(0xffffffffu, s, 2);
            const bool valid = (qd >= off[t]) && (qd < off[t] + 5);
            sr[t] = valid ? s : -1e30f;
        }
        sv.x = sr[0]; sv.y = sr[1]; sv.z = sr[2]; sv.w = sr[3];
        if (sub == 0) *(float4*)&sp[head][r * 8 + qd][0] = sv;
    }
    __syncwarp();

    #pragma unroll
    for (int t = 0; t < 4; t++) {
        const float v0 = sp[head][lane][t];
        const float v1 = sp[head][lane + 32][t];
        const float v2 = sp[head][lane + 64][t];
        const float v3 = (lane < 24) ? sp[head][lane + 96][t] : -1e30f;
        float m = fmaxf(fmaxf(v0, v1), fmaxf(v2, v3));
        #pragma unroll
        for (int o = 16; o; o >>= 1) m = fmaxf(m, __shfl_xor_sync(0xffffffffu, m, o));
        const float e0 = __expf(v0 - m);
        const float e1 = __expf(v1 - m);
        const float e2 = __expf(v2 - m);
        const float e3 = (lane < 24) ? __expf(v3 - m) : 0.f;
        float ssum = e0 + e1 + e2 + e3;
        #pragma unroll
        for (int o = 16; o; o >>= 1) ssum += __shfl_xor_sync(0xffffffffu, ssum, o);
        const float inv = 1.f / ssum;
        sp[head][lane][t]      = e0 * inv;
        sp[head][lane + 32][t] = e1 * inv;
        sp[head][lane + 64][t] = e2 * inv;
        if (lane < 24) sp[head][lane + 96][t] = e3 * inv;
    }
    __syncwarp();

    float acc[4] = {0.f, 0.f, 0.f, 0.f};
    const float* vbase = qkv + 512 + head * HDIM + lane;
    int p = 0;
    #pragma unroll
    for (int dd = 0; dd < 3; dd++) {
        #pragma unroll
        for (int hh2 = 0; hh2 < 5; hh2++) {
            const int rowb = ((sd + dd) * HH + (sh + hh2)) * WW + swu;
            #pragma unroll
            for (int wwu = 0; wwu < 8; wwu++) {
                const float v = vbase[(size_t)(rowb + wwu) * 768];
                const float4 pr = *(const float4*)&sp[head][p][0];
                acc[0] += pr.x * v;
                acc[1] += pr.y * v;
                acc[2] += pr.z * v;
                acc[3] += pr.w * v;
                p++;
            }
        }
    }
    #pragma unroll
    for (int t = 0; t < 4; t++) {
        const size_t oidx = (size_t)(t4 + t) * CH + head * HDIM + lane;
        const __nv_bfloat16 hv = __float2bfloat16(acc[t]);
        oh[oidx] = hv;
        ol[oidx] = __float2bfloat16(acc[t] - __bfloat162float(hv));
    }
}

// ---------------------------------------------------------------------------
// Launcher
// ---------------------------------------------------------------------------
extern "C" void kernel_launch(void* const* d_in, const int* in_sizes, int n_in,
                              void* d_out, int out_size)
{
    const float* latent  = (const float*)d_in[0];
    const float* qkv_w   = (const float*)d_in[1];
    const float* qkv_b   = (const float*)d_in[2];
    const float* proj_w  = (const float*)d_in[3];
    const float* proj_b  = (const float*)d_in[4];
    const float* split_w = (const float*)d_in[5];
    const float* split_b = (const float*)d_in[6];
    const float* pw0 = (const float*)d_in[7];
    const float* pb0 = (const float*)d_in[8];
    const float* pw1 = (const float*)d_in[9];
    const float* pb1 = (const float*)d_in[10];
    const float* pw2 = (const float*)d_in[11];
    const float* pb2 = (const float*)d_in[12];
    const float* sw0 = (const float*)d_in[13];
    const float* sb0 = (const float*)d_in[14];
    const float* sw1 = (const float*)d_in[15];
    const float* sb1 = (const float*)d_in[16];
    const float* sw2 = (const float*)d_in[17];
    const float* sb2 = (const float*)d_in[18];
    float* out = (float*)d_out;

    float *qkv, *feats, *p0f, *p1f, *s0, *s1;
    __nv_bfloat16 *xah, *xal, *aah, *aal, *wth, *wtl, *fth, *ftl, *b0h, *b0l;
    cudaGetSymbolAddress((void**)&qkv,   g_qkv);
    cudaGetSymbolAddress((void**)&feats, g_feats);
    cudaGetSymbolAddress((void**)&p0f,   g_p0f);
    cudaGetSymbolAddress((void**)&p1f,   g_p1f);
    cudaGetSymbolAddress((void**)&s0,    g_s0);
    cudaGetSymbolAddress((void**)&s1,    g_s1);
    cudaGetSymbolAddress((void**)&xah,   g_xah);
    cudaGetSymbolAddress((void**)&xal,   g_xal);
    cudaGetSymbolAddress((void**)&aah,   g_aah);
    cudaGetSymbolAddress((void**)&aal,   g_aal);
    cudaGetSymbolAddress((void**)&wth,   g_wth);
    cudaGetSymbolAddress((void**)&wtl,   g_wtl);
    cudaGetSymbolAddress((void**)&fth,   g_fth);
    cudaGetSymbolAddress((void**)&ftl,   g_ftl);
    cudaGetSymbolAddress((void**)&b0h,   g_b0h);
    cudaGetSymbolAddress((void**)&b0l,   g_b0l);

    // allow 80KB dynamic smem for the mma kernel (idempotent, capture-safe)
    cudaFuncSetAttribute(gemm_mma<0, false>,
                         cudaFuncAttributeMaxDynamicSharedMemorySize, GEMM_MMA_SMEM);
    cudaFuncSetAttribute(gemm_mma<1, false>,
                         cudaFuncAttributeMaxDynamicSharedMemorySize, GEMM_MMA_SMEM);
    cudaFuncSetAttribute(gemm_mma<2, true>,
                         cudaFuncAttributeMaxDynamicSharedMemorySize, GEMM_MMA_SMEM);
    cudaFuncSetAttribute(gemm_mma<4, false>,
                         cudaFuncAttributeMaxDynamicSharedMemorySize, GEMM_MMA_SMEM);

    const dim3 tb(32, 8);

    // initial x = latent -> bf16 hi/lo
    split_rows<<<(TOK * 256 + 255) / 256, 256>>>(latent, xah, xal, TOK * 256);

    for (int l = 0; l < 3; l++) {
        // qkv: A = x, B = qkv_w^T -> fp32 qkv
        transpose_split<<<dim3(768 / 32, 256 / 32), tb>>>(
            qkv_w + l * 256 * 768, wth, wtl, 256, 768, 768);
        gemm_mma<0, false><<<dim3(768 / 128, TOK / 128), 256, GEMM_MMA_SMEM>>>(
            xah, xal, wth, wtl, qkv_b + l * 768, qkv, nullptr, nullptr,
            TOK, 768, 256, 768, 0, 0, 0);

        na3d_attn_v5<<<TOK / 4, 256>>>(qkv, aah, aal);

        // proj: A = attn, B = proj_w^T -> x bf16 hi/lo (MODE 4)
        transpose_split<<<dim3(256 / 32, 256 / 32), tb>>>(
            proj_w + l * 256 * 256, wth, wtl, 256, 256, 256);
        gemm_mma<4, false><<<dim3(256 / 128, TOK / 128), 256, GEMM_MMA_SMEM>>>(
            aah, aal, wth, wtl, proj_b + l * 256, nullptr, xah, xal,
            TOK, 256, 256, 256, 0, 0, 0);
    }

    // split (MODE 1): A = split_w [512][256], B = x -> fp32 feats (channel-first)
    split_rows<<<(512 * 256 + 255) / 256, 256>>>(split_w, wth, wtl, 512 * 256);
    gemm_mma<1, false><<<dim3(TOK / 128, 512 / 128), 256, GEMM_MMA_SMEM>>>(
        wth, wtl, xah, xal, split_b, feats, nullptr, nullptr,
        512, TOK, 256, TOK, 0, 0, 0);

    // press0 (MODE 2): A = pw0T [2048][512], B = featsT [4608][512] -> fp32 p0
    transpose_split<<<dim3(2048 / 32, 512 / 32), tb>>>(pw0, wth, wtl, 512, 2048, 2048);
    transpose_split<<<dim3(4608 / 32, 512 / 32), tb>>>(feats, fth, ftl, 512, 4608, TOK);
    gemm_mma<2, true><<<dim3(4608 / 128, 2048 / 128), 256, GEMM_MMA_SMEM>>>(
        wth, wtl, fth, ftl, pb0, p0f, nullptr, nullptr,
        2048, 4608, 512, 0, 4, 24, 48);

    // press1 (MODE 2): A = pw1T [1024][256], B = p0T [36864][256] -> fp32 p1
    transpose_split<<<dim3(1024 / 32, 256 / 32), tb>>>(pw1, wth, wtl, 256, 1024, 1024);
    transpose_split<<<dim3(36864 / 32, 256 / 32), tb>>>(p0f, b0h, b0l, 256, 36864, 36864);
    gemm_mma<2, true><<<dim3(36864 / 128, 1024 / 128), 256, GEMM_MMA_SMEM>>>(
        wth, wtl, b0h, b0l, pb1, p1f, nullptr, nullptr,
        1024, 36864, 256, 0, 8, 48, 96);

    // press2 (fp32, M=40 -> BM=64)
    gemm_db<64, true, false, 2, false><<<dim3(294912 / 128, 1), 128>>>(
        pw2, p1f, pb2, out + 8 * 192 * 384,
        40, 294912, 128, 40, 294912, 0, 16, 96, 192);

    // surf pyramid (fp32 path)
    gemm_db<128, true, false, 3, true><<<dim3(1152 / 128, 1024 / 128), 256>>>(
        sw0, feats + 4 * HH * WW, sb0, s0,
        1024, 1152, 512, 1024, TOK, 0, 0, 24, 48);
    gemm_db<128, true, false, 3, true><<<dim3(4608 / 128, 512 / 128), 256>>>(
        sw1, s0, sb1, s1,
        512, 4608, 256, 512, 4608, 0, 0, 48, 96);
    gemm_db<64, true, false, 3, false><<<dim3(18432 / 128, 1), 128>>>(
        sw2, s1, sb2, out,
        32, 18432, 128, 32, 18432, 0, 0, 96, 192);
}

// round 15
// speedup vs baseline: 2.1113x; 1.0500x over previous
#include <cuda_runtime.h>
#include <cuda_bf16.h>
#include <math.h>
#include <stdint.h>

// ---------------------------------------------------------------------------
// Problem constants
// ---------------------------------------------------------------------------
#define TOK   5760          // 5*24*48
#define CH    256
#define DD    5
#define HH    24
#define WW    48
#define NHEAD 8
#define HDIM  32

// fp32 scratch
__device__ float g_qkv [TOK * 768];
__device__ float g_feats[512 * TOK];                 // channel-first (512, 5, 24, 48)
__device__ float g_p0f [256 * 36864];                // press0 out (256, 8, 48, 96)
__device__ float g_p1f [128 * 294912];               // press1 out (128, 16, 96, 192)
__device__ float g_s0  [256 * 48 * 96];
__device__ float g_s1  [128 * 96 * 192];

// bf16 hi/lo scratch
__device__ __align__(16) __nv_bfloat16 g_xah[TOK * 256],   g_xal[TOK * 256];   // x (layer act)
__device__ __align__(16) __nv_bfloat16 g_aah[TOK * 256],   g_aal[TOK * 256];   // attn out
__device__ __align__(16) __nv_bfloat16 g_qwh[3 * 768 * 256], g_qwl[3 * 768 * 256]; // qkv_w^T
__device__ __align__(16) __nv_bfloat16 g_pwh[3 * 256 * 256], g_pwl[3 * 256 * 256]; // proj_w^T
__device__ __align__(16) __nv_bfloat16 g_swh[512 * 256],   g_swl[512 * 256];   // split_w
__device__ __align__(16) __nv_bfloat16 g_w0h[2048 * 512],  g_w0l[2048 * 512];  // pw0^T
__device__ __align__(16) __nv_bfloat16 g_w1h[1024 * 256],  g_w1l[1024 * 256];  // pw1^T
__device__ __align__(16) __nv_bfloat16 g_u0h[1024 * 512],  g_u0l[1024 * 512];  // sw0^T
__device__ __align__(16) __nv_bfloat16 g_u1h[512 * 256],   g_u1l[512 * 256];   // sw1^T
__device__ __align__(16) __nv_bfloat16 g_u2h[128 * 128],   g_u2l[128 * 128];   // sw2 padded
__device__ __align__(16) __nv_bfloat16 g_fth[5760 * 512],  g_ftl[5760 * 512];  // featsT (all d)
__device__ __align__(16) __nv_bfloat16 g_b0h[36864 * 256], g_b0l[36864 * 256]; // p0T; later s0T/s1T

// ---------------------------------------------------------------------------
// fp32 -> bf16 hi/lo split, contiguous
// ---------------------------------------------------------------------------
__global__ void split_rows(const float* __restrict__ in,
                           __nv_bfloat16* __restrict__ oh,
                           __nv_bfloat16* __restrict__ ol, int n)
{
    int i = blockIdx.x * blockDim.x + threadIdx.x;
    if (i < n) {
        float v = in[i];
        __nv_bfloat16 h = __float2bfloat16(v);
        oh[i] = h;
        ol[i] = __float2bfloat16(v - __bfloat162float(h));
    }
}

// fp32 [R][C] (row stride ld) -> bf16 hi/lo [C][R]   (R, C multiples of 32)
__global__ void transpose_split(const float* __restrict__ in,
                                __nv_bfloat16* __restrict__ oh,
                                __nv_bfloat16* __restrict__ ol,
                                int R, int C, int ld)
{
    __shared__ float t[32][33];
    const int r0 = blockIdx.y * 32, c0 = blockIdx.x * 32;
    const int tx = threadIdx.x, ty = threadIdx.y;
    #pragma unroll
    for (int i = ty; i < 32; i += 8)
        t[i][tx] = in[(size_t)(r0 + i) * ld + c0 + tx];
    __syncthreads();
    #pragma unroll
    for (int i = ty; i < 32; i += 8) {
        float v = t[tx][i];
        __nv_bfloat16 h = __float2bfloat16(v);
        oh[(size_t)(c0 + i) * R + r0 + tx] = h;
        ol[(size_t)(c0 + i) * R + r0 + tx] = __float2bfloat16(v - __bfloat162float(h));
    }
}

// src fp32 [K][Mreal] -> padded A hi/lo [128][K], rows >= Mreal zero. K*128 elems.
__global__ void pad_split(const float* __restrict__ src,
                          __nv_bfloat16* __restrict__ oh,
                          __nv_bfloat16* __restrict__ ol, int Mreal, int K)
{
    const int idx = blockIdx.x * 256 + threadIdx.x;
    if (idx < 128 * K) {
        const int m = idx / K, k = idx % K;
        float v = (m < Mreal) ? src[k * Mreal + m] : 0.f;
        __nv_bfloat16 h = __float2bfloat16(v);
        oh[idx] = h;
        ol[idx] = __float2bfloat16(v - __bfloat162float(h));
    }
}

// ---------------------------------------------------------------------------
// Tensor-core GEMM, bf16x3 split (hi*hi + hi*lo + lo*hi), fp32 accum.
// cp.async double-buffered; ldmatrix.x4 fragment loads.
//   C[m][n] = epilogue( sum_k A[m][k]*B[k][n] + bias )
// Tile 128x128x32, 256 threads = 8 warps (2 m x 4 n), warp tile 64x32,
// mma.sync.m16n8k16. N multiple of 128; K multiple of 32.
// MODE 0: fp32 C row-major [M][ldc], bias[n]
// MODE 1: fp32 C row-major [M][ldc], bias[m]
// MODE 2: up3d scatter to fp32 C, bias[m>>3], optional SiLU, m<M guarded
// MODE 3: up2d scatter to fp32 C, bias[m>>2], optional SiLU, m<M guarded
// MODE 4: bf16 hi/lo Oh/Ol row-major [M][ldc], bias[n]
// ---------------------------------------------------------------------------
#define MMA_BF16(c, a0, a1, a2, a3, b0, b1)                                   \
    asm volatile("mma.sync.aligned.m16n8k16.row.col.f32.bf16.bf16.f32 "       \
                 "{%0,%1,%2,%3}, {%4,%5,%6,%7}, {%8,%9}, {%0,%1,%2,%3};"      \
                 : "+f"(c[0]), "+f"(c[1]), "+f"(c[2]), "+f"(c[3])             \
                 : "r"(a0), "r"(a1), "r"(a2), "r"(a3), "r"(b0), "r"(b1))

__device__ __forceinline__ void cp16(uint32_t dst, const void* src) {
    asm volatile("cp.async.ca.shared.global [%0], [%1], 16;" :: "r"(dst), "l"(src));
}

__device__ __forceinline__ void ldsm4(uint32_t& r0, uint32_t& r1,
                                      uint32_t& r2, uint32_t& r3, uint32_t addr) {
    asm volatile("ldmatrix.sync.aligned.m8n8.x4.shared.b16 {%0,%1,%2,%3}, [%4];"
                 : "=r"(r0), "=r"(r1), "=r"(r2), "=r"(r3) : "r"(addr));
}

#define GEMM_MMA_SMEM 81920

template<int MODE, bool SILU>
__global__ __launch_bounds__(256)
void gemm_mma(const __nv_bfloat16* __restrict__ Ah, const __nv_bfloat16* __restrict__ Al,
              const __nv_bfloat16* __restrict__ Bh, const __nv_bfloat16* __restrict__ Bl,
              const float* __restrict__ bias, float* __restrict__ C,
              __nv_bfloat16* __restrict__ Oh, __nv_bfloat16* __restrict__ Ol,
              int M, int N, int K, int ldc, int Din, int Hin, int Win)
{
    constexpr int RS = 20;                  // smem words per row (16 data + 4 pad)
    constexpr int BUFW = 128 * RS;          // words per array
    extern __shared__ __align__(16) float smem_dyn[];
    const uint32_t sbase = (uint32_t)__cvta_generic_to_shared(smem_dyn);

    const int tid  = threadIdx.x;
    const int warp = tid >> 5, lane = tid & 31;
    const int g = lane >> 2, t = lane & 3;
    const int wm = warp & 1, wn = warp >> 1;       // warp tile origin (wm*64, wn*32)
    const int m0 = blockIdx.y * 128, n0 = blockIdx.x * 128;

    const int lrow = tid >> 1, lseg = tid & 1;     // loader: 2 threads/row, 16 bf16 each

    // ldmatrix per-lane row/chunk decomposition
    const int rA = (lane & 7) + ((lane >> 3) & 1) * 8;
    const int cA = (lane >> 4) & 1;
    const int rB = (lane & 7) + ((lane >> 4) & 1) * 8;
    const int cB = (lane >> 3) & 1;

    float acc[4][4][4];
    #pragma unroll
    for (int a = 0; a < 4; a++)
        #pragma unroll
        for (int b = 0; b < 4; b++)
            #pragma unroll
            for (int c = 0; c < 4; c++) acc[a][b][c] = 0.f;

    auto issue = [&](int k0, int buf) {
        const size_t ga = (size_t)(m0 + lrow) * K + k0 + lseg * 16;
        const size_t gb = (size_t)(n0 + lrow) * K + k0 + lseg * 16;
        const uint32_t doff = (uint32_t)(lrow * RS + lseg * 8) * 4;
        const uint32_t p0 = sbase + (uint32_t)(buf * 4 + 0) * BUFW * 4 + doff;
        const uint32_t p1 = sbase + (uint32_t)(buf * 4 + 1) * BUFW * 4 + doff;
        const uint32_t p2 = sbase + (uint32_t)(buf * 4 + 2) * BUFW * 4 + doff;
        const uint32_t p3 = sbase + (uint32_t)(buf * 4 + 3) * BUFW * 4 + doff;
        cp16(p0, Ah + ga); cp16(p0 + 16, Ah + ga + 8);
        cp16(p1, Al + ga); cp16(p1 + 16, Al + ga + 8);
        cp16(p2, Bh + gb); cp16(p2 + 16, Bh + gb + 8);
        cp16(p3, Bl + gb); cp16(p3 + 16, Bl + gb + 8);
    };

    issue(0, 0);
    asm volatile("cp.async.commit_group;" ::: "memory");

    const int nslab = K >> 5;
    int buf = 0;
    for (int s = 0; s < nslab; s++) {
        asm volatile("cp.async.wait_group 0;" ::: "memory");
        __syncthreads();
        if (s + 1 < nslab) {
            issue((s + 1) << 5, buf ^ 1);
            asm volatile("cp.async.commit_group;" ::: "memory");
        }

        const uint32_t bAh = sbase + (uint32_t)(buf * 4 + 0) * BUFW * 4;
        const uint32_t bAl = sbase + (uint32_t)(buf * 4 + 1) * BUFW * 4;
        const uint32_t bBh = sbase + (uint32_t)(buf * 4 + 2) * BUFW * 4;
        const uint32_t bBl = sbase + (uint32_t)(buf * 4 + 3) * BUFW * 4;

        #pragma unroll
        for (int ks = 0; ks < 2; ks++) {
            uint32_t bh[4][2], bl[4][2];
            #pragma unroll
            for (int p = 0; p < 2; p++) {
                const uint32_t boff =
                    (uint32_t)((wn * 32 + p * 16 + rB) * RS + ks * 8 + cB * 4) * 4;
                ldsm4(bh[2 * p][0], bh[2 * p][1], bh[2 * p + 1][0], bh[2 * p + 1][1],
                      bBh + boff);
                ldsm4(bl[2 * p][0], bl[2 * p][1], bl[2 * p + 1][0], bl[2 * p + 1][1],
                      bBl + boff);
            }
            #pragma unroll
            for (int mt = 0; mt < 4; mt++) {
                const uint32_t aoff =
                    (uint32_t)((wm * 64 + mt * 16 + rA) * RS + ks * 8 + cA * 4) * 4;
                uint32_t ah0, ah1, ah2, ah3, al0, al1, al2, al3;
                ldsm4(ah0, ah1, ah2, ah3, bAh + aoff);
                ldsm4(al0, al1, al2, al3, bAl + aoff);
                #pragma unroll
                for (int nt = 0; nt < 4; nt++) {
                    MMA_BF16(acc[mt][nt], ah0, ah1, ah2, ah3, bh[nt][0], bh[nt][1]);
                    MMA_BF16(acc[mt][nt], ah0, ah1, ah2, ah3, bl[nt][0], bl[nt][1]);
                    MMA_BF16(acc[mt][nt], al0, al1, al2, al3, bh[nt][0], bh[nt][1]);
                }
            }
        }
        buf ^= 1;
    }

    // element (mt, nt, reg): m = m0+wm*64+mt*16+g+(reg>=2)*8,
    //                        n = n0+wn*32+nt*8+t*2+(reg&1)
    if (MODE == 0 || MODE == 1) {
        #pragma unroll
        for (int mt = 0; mt < 4; mt++) {
            const int mb = m0 + wm * 64 + mt * 16 + g;
            const float bmA = (MODE == 1) ? bias[mb]     : 0.f;
            const float bmB = (MODE == 1) ? bias[mb + 8] : 0.f;
            #pragma unroll
            for (int nt = 0; nt < 4; nt++) {
                const int nb = n0 + wn * 32 + nt * 8 + t * 2;
                float b0 = bmA, b1 = bmA, b2 = bmB, b3 = bmB;
                if (MODE == 0) { b0 = b2 = bias[nb]; b1 = b3 = bias[nb + 1]; }
                float2 v0 = make_float2(acc[mt][nt][0] + b0, acc[mt][nt][1] + b1);
                float2 v1 = make_float2(acc[mt][nt][2] + b2, acc[mt][nt][3] + b3);
                *(float2*)&C[(size_t)mb * ldc + nb]       = v0;
                *(float2*)&C[(size_t)(mb + 8) * ldc + nb] = v1;
            }
        }
    } else if (MODE == 4) {
        #pragma unroll
        for (int mt = 0; mt < 4; mt++) {
            const int mb = m0 + wm * 64 + mt * 16 + g;
            #pragma unroll
            for (int nt = 0; nt < 4; nt++) {
                const int nb = n0 + wn * 32 + nt * 8 + t * 2;
                const float b0 = bias[nb], b1 = bias[nb + 1];
                #pragma unroll
                for (int half = 0; half < 2; half++) {
                    const int m = mb + half * 8;
                    const float va = acc[mt][nt][half * 2 + 0] + b0;
                    const float vb = acc[mt][nt][half * 2 + 1] + b1;
                    const __nv_bfloat16 ha = __float2bfloat16(va);
                    const __nv_bfloat16 hb = __float2bfloat16(vb);
                    __nv_bfloat162 hp, lp;
                    hp.x = ha; hp.y = hb;
                    lp.x = __float2bfloat16(va - __bfloat162float(ha));
                    lp.y = __float2bfloat16(vb - __bfloat162float(hb));
                    *(__nv_bfloat162*)&Oh[(size_t)m * ldc + nb] = hp;
                    *(__nv_bfloat162*)&Ol[(size_t)m * ldc + nb] = lp;
                }
            }
        }
    } else if (MODE == 2) { // up3d scatter to fp32 (o-major)
        int nw[4][2], nh[4][2], nd[4][2];
        #pragma unroll
        for (int nt = 0; nt < 4; nt++)
            #pragma unroll
            for (int e = 0; e < 2; e++) {
                const int n = n0 + wn * 32 + nt * 8 + t * 2 + e;
                nw[nt][e] = n % Win;
                const int tt = n / Win;
                nh[nt][e] = tt % Hin;
                nd[nt][e] = tt / Hin;
            }
        const int OD = 2 * Din, OH = 2 * Hin, OW = 2 * Win;
        #pragma unroll
        for (int mt = 0; mt < 4; mt++) {
            #pragma unroll
            for (int half = 0; half < 2; half++) {
                const int m = m0 + wm * 64 + mt * 16 + g + half * 8;
                if (m < M) {
                    const int o = m >> 3, r = m & 7;
                    const int ri = (r >> 2) & 1, rj = (r >> 1) & 1, rk = r & 1;
                    const float bv = bias[o];
                    #pragma unroll
                    for (int nt = 0; nt < 4; nt++) {
                        #pragma unroll
                        for (int e = 0; e < 2; e++) {
                            float v = acc[mt][nt][half * 2 + e] + bv;
                            if (SILU) v = v / (1.f + __expf(-v));
                            const size_t idx =
                                ((size_t)(o * OD + 2 * nd[nt][e] + ri) * OH
                                 + 2 * nh[nt][e] + rj) * OW + 2 * nw[nt][e] + rk;
                            C[idx] = v;
                        }
                    }
                }
            }
        }
    } else { // MODE 3 : up2d scatter to fp32 (o-major)
        int nw[4][2], nh[4][2];
        #pragma unroll
        for (int nt = 0; nt < 4; nt++)
            #pragma unroll
            for (int e = 0; e < 2; e++) {
                const int n = n0 + wn * 32 + nt * 8 + t * 2 + e;
                nw[nt][e] = n % Win;
                nh[nt][e] = n / Win;
            }
        const int OH = 2 * Hin, OW = 2 * Win;
        #pragma unroll
        for (int mt = 0; mt < 4; mt++) {
            #pragma unroll
            for (int half = 0; half < 2; half++) {
                const int m = m0 + wm * 64 + mt * 16 + g + half * 8;
                if (m < M) {
                    const int o = m >> 2, r = m & 3;
                    const int ri = (r >> 1) & 1, rj = r & 1;
                    const float bv = bias[o];
                    #pragma unroll
                    for (int nt = 0; nt < 4; nt++) {
                        #pragma unroll
                        for (int e = 0; e < 2; e++) {
                            float v = acc[mt][nt][half * 2 + e] + bv;
                            if (SILU) v = v / (1.f + __expf(-v));
                            const size_t idx =
                                (size_t)(o * OH + 2 * nh[nt][e] + ri) * OW
                                + 2 * nw[nt][e] + rj;
                            C[idx] = v;
                        }
                    }
                }
            }
        }
    }
}

// ---------------------------------------------------------------------------
// Double-buffered fp32 SGEMM (press2 only; B layout [K][N] is ideal here)
// ---------------------------------------------------------------------------
template<int BM, bool TA, bool TB, int MODE, bool SILU>
__global__ __launch_bounds__(BM * 2)
void gemm_db(const float* __restrict__ A, const float* __restrict__ B,
             const float* __restrict__ bias, float* __restrict__ C,
             int M, int N, int K, int lda, int ldb, int ldc,
             int Din, int Hin, int Win)
{
    constexpr int THREADS = BM * 2;
    __shared__ float As[2][8][BM];
    __shared__ float Bs[2][8][128];
    const int tid = threadIdx.x;
    const int m0 = blockIdx.y * BM;
    const int n0 = blockIdx.x * 128;
    const int tx = tid & 15, ty = tid >> 4;

    int a_k, a_m;
    if (TA) { a_k = tid / (BM / 4); a_m = (tid % (BM / 4)) * 4; }
    else    { a_m = tid >> 1;       a_k = (tid & 1) << 2; }
    const int bn_k = TB ? ((tid & 1) << 2) : (tid >> 5);
    const int bn_n = TB ? (tid >> 1)       : ((tid & 31) << 2);

    float4 ra, rb0, rb1;

    auto ldA = [&](int k0) {
        if (TA) {
            const float* p = A + (size_t)(k0 + a_k) * lda + m0 + a_m;
            float4 v;
            if (m0 + a_m + 3 < M) v = *(const float4*)p;
            else {
                v.x = (m0 + a_m     < M) ? p[0] : 0.f;
                v.y = (m0 + a_m + 1 < M) ? p[1] : 0.f;
                v.z = (m0 + a_m + 2 < M) ? p[2] : 0.f;
                v.w = (m0 + a_m + 3 < M) ? p[3] : 0.f;
            }
            ra = v;
        } else {
            float4 v = make_float4(0.f, 0.f, 0.f, 0.f);
            if (m0 + a_m < M) v = *(const float4*)(A + (size_t)(m0 + a_m) * lda + k0 + a_k);
            ra = v;
        }
    };
    auto ldB = [&](int k0) {
        if (TB) {
            rb0 = *(const float4*)(B + (size_t)(n0 + bn_n) * ldb + k0 + bn_k);
        } else {
            rb0 = *(const float4*)(B + (size_t)(k0 + bn_k) * ldb + n0 + bn_n);
            if (THREADS == 128)
                rb1 = *(const float4*)(B + (size_t)(k0 + bn_k + 4) * ldb + n0 + bn_n);
        }
    };
    auto stA = [&](int buf) {
        if (TA) {
            *(float4*)&As[buf][a_k][a_m] = ra;
        } else {
            As[buf][a_k + 0][a_m] = ra.x; As[buf][a_k + 1][a_m] = ra.y;
            As[buf][a_k + 2][a_m] = ra.z; As[buf][a_k + 3][a_m] = ra.w;
        }
    };
    auto stB = [&](int buf) {
        if (TB) {
            Bs[buf][bn_k + 0][bn_n] = rb0.x; Bs[buf][bn_k + 1][bn_n] = rb0.y;
            Bs[buf][bn_k + 2][bn_n] = rb0.z; Bs[buf][bn_k + 3][bn_n] = rb0.w;
        } else {
            *(float4*)&Bs[buf][bn_k][bn_n] = rb0;
            if (THREADS == 128) *(float4*)&Bs[buf][bn_k + 4][bn_n] = rb1;
        }
    };

    float acc[8][8] = {};

    ldA(0); ldB(0);
    stA(0); stB(0);
    __syncthreads();

    const int nslab = K >> 3;
    int buf = 0;
    for (int s = 0; s < nslab; s++) {
        if (s + 1 < nslab) { ldA((s + 1) << 3); ldB((s + 1) << 3); }
        #pragma unroll
        for (int kk = 0; kk < 8; kk++) {
            float a[8], b[8];
            *(float4*)&a[0] = *(float4*)&As[buf][kk][ty * 4];
            *(float4*)&a[4] = *(float4*)&As[buf][kk][ty * 4 + BM / 2];
            *(float4*)&b[0] = *(float4*)&Bs[buf][kk][tx * 4];
            *(float4*)&b[4] = *(float4*)&Bs[buf][kk][tx * 4 + 64];
            #pragma unroll
            for (int i = 0; i < 8; i++)
                #pragma unroll
                for (int j = 0; j < 8; j++)
                    acc[i][j] += a[i] * b[j];
        }
        if (s + 1 < nslab) {
            stA(buf ^ 1); stB(buf ^ 1);
            __syncthreads();
            buf ^= 1;
        }
    }

    if (MODE == 2) {
        int dj[8], hj[8], wj[8];
        #pragma unroll
        for (int j = 0; j < 8; j++) {
            const int n = n0 + tx * 4 + (j & 3) + ((j >> 2) * 64);
            wj[j] = n % Win;
            const int t = n / Win;
            hj[j] = t % Hin;
            dj[j] = t / Hin;
        }
        const int OD = 2 * Din, OH = 2 * Hin, OW = 2 * Win;
        #pragma unroll
        for (int i = 0; i < 8; i++) {
            const int m = m0 + ty * 4 + (i & 3) + ((i >> 2) * (BM / 2));
            if (m < M) {
                const int o = m >> 3, r = m & 7;
                const int ri = (r >> 2) & 1, rj = (r >> 1) & 1, rk = r & 1;
                const float bv = bias[o];
                #pragma unroll
                for (int j = 0; j < 8; j++) {
                    float v = acc[i][j] + bv;
                    if (SILU) v = v / (1.f + __expf(-v));
                    const size_t idx =
                        ((size_t)(o * OD + 2 * dj[j] + ri) * OH + 2 * hj[j] + rj) * OW
                        + 2 * wj[j] + rk;
                    C[idx] = v;
                }
            }
        }
    }
}

// ---------------------------------------------------------------------------
// 3D neighborhood attention v5: 4 tokens per block share a window union.
// ---------------------------------------------------------------------------
__global__ void na3d_attn_v5(const float* __restrict__ qkv,
                             __nv_bfloat16* __restrict__ oh,
                             __nv_bfloat16* __restrict__ ol)
{
    __shared__ __align__(16) float sp[NHEAD][120][4];

    const int t4 = blockIdx.x * 4;
    const int d = t4 / (HH * WW);
    const int rem = t4 % (HH * WW);
    const int h = rem / WW;
    const int w0 = rem % WW;
    const int head = threadIdx.x >> 5;
    const int lane = threadIdx.x & 31;
    const int qd  = lane >> 2;
    const int sub = lane & 3;

    const int sd = min(max(d - 1, 0), DD - 3);
    const int sh = min(max(h - 2, 0), HH - 5);
    const int swu = min(max(w0 - 2, 0), WW - 8);
    int off[4];
    #pragma unroll
    for (int t = 0; t < 4; t++)
        off[t] = min(max(w0 + t - 2, 0), WW - 5) - swu;

    const float sc0 = 0.17677669529663687f;
    float4 q0[4], q1[4];
    #pragma unroll
    for (int t = 0; t < 4; t++) {
        const float* qp = qkv + (size_t)(t4 + t) * 768 + head * HDIM + sub * 8;
        q0[t] = *(const float4*)qp;
        q1[t] = *(const float4*)(qp + 4);
        q0[t].x *= sc0; q0[t].y *= sc0; q0[t].z *= sc0; q0[t].w *= sc0;
        q1[t].x *= sc0; q1[t].y *= sc0; q1[t].z *= sc0; q1[t].w *= sc0;
    }

    for (int r = 0; r < 15; r++) {
        const int dd = r / 5, hh2 = r % 5;
        const int nb = ((sd + dd) * HH + (sh + hh2)) * WW + swu + qd;
        const float* kp = qkv + (size_t)nb * 768 + 256 + head * HDIM + sub * 8;
        const float4 k0 = *(const float4*)kp;
        const float4 k1 = *(const float4*)(kp + 4);
        float4 sv;
        float sr[4];
        #pragma unroll
        for (int t = 0; t < 4; t++) {
            float s = q0[t].x * k0.x + q0[t].y * k0.y + q0[t].z * k0.z + q0[t].w * k0.w
                    + q1[t].x * k1.x + q1[t].y * k1.y + q1[t].z * k1.z + q1[t].w * k1.w;
            s += __shfl_xor_sync(0xffffffffu, s, 1);
            s += __shfl_xor_sync(0xffffffffu, s, 2);
            const bool valid = (qd >= off[t]) && (qd < off[t] + 5);
            sr[t] = valid ? s : -1e30f;
        }
        sv.x = sr[0]; sv.y = sr[1]; sv.z = sr[2]; sv.w = sr[3];
        if (sub == 0) *(float4*)&sp[head][r * 8 + qd][0] = sv;
    }
    __syncwarp();

    #pragma unroll
    for (int t = 0; t < 4; t++) {
        const float v0 = sp[head][lane][t];
        const float v1 = sp[head][lane + 32][t];
        const float v2 = sp[head][lane + 64][t];
        const float v3 = (lane < 24) ? sp[head][lane + 96][t] : -1e30f;
        float m = fmaxf(fmaxf(v0, v1), fmaxf(v2, v3));
        #pragma unroll
        for (int o = 16; o; o >>= 1) m = fmaxf(m, __shfl_xor_sync(0xffffffffu, m, o));
        const float e0 = __expf(v0 - m);
        const float e1 = __expf(v1 - m);
        const float e2 = __expf(v2 - m);
        const float e3 = (lane < 24) ? __expf(v3 - m) : 0.f;
        float ssum = e0 + e1 + e2 + e3;
        #pragma unroll
        for (int o = 16; o; o >>= 1) ssum += __shfl_xor_sync(0xffffffffu, ssum, o);
        const float inv = 1.f / ssum;
        sp[head][lane][t]      = e0 * inv;
        sp[head][lane + 32][t] = e1 * inv;
        sp[head][lane + 64][t] = e2 * inv;
        if (lane < 24) sp[head][lane + 96][t] = e3 * inv;
    }
    __syncwarp();

    float acc[4] = {0.f, 0.f, 0.f, 0.f};
    const float* vbase = qkv + 512 + head * HDIM + lane;
    int p = 0;
    #pragma unroll
    for (int dd = 0; dd < 3; dd++) {
        #pragma unroll
        for (int hh2 = 0; hh2 < 5; hh2++) {
            const int rowb = ((sd + dd) * HH + (sh + hh2)) * WW + swu;
            #pragma unroll
            for (int wwu = 0; wwu < 8; wwu++) {
                const float v = vbase[(size_t)(rowb + wwu) * 768];
                const float4 pr = *(const float4*)&sp[head][p][0];
                acc[0] += pr.x * v;
                acc[1] += pr.y * v;
                acc[2] += pr.z * v;
                acc[3] += pr.w * v;
                p++;
            }
        }
    }
    #pragma unroll
    for (int t = 0; t < 4; t++) {
        const size_t oidx = (size_t)(t4 + t) * CH + head * HDIM + lane;
        const __nv_bfloat16 hv = __float2bfloat16(acc[t]);
        oh[oidx] = hv;
        ol[oidx] = __float2bfloat16(acc[t] - __bfloat162float(hv));
    }
}

// ---------------------------------------------------------------------------
// Launcher
// ---------------------------------------------------------------------------
extern "C" void kernel_launch(void* const* d_in, const int* in_sizes, int n_in,
                              void* d_out, int out_size)
{
    const float* latent  = (const float*)d_in[0];
    const float* qkv_w   = (const float*)d_in[1];
    const float* qkv_b   = (const float*)d_in[2];
    const float* proj_w  = (const float*)d_in[3];
    const float* proj_b  = (const float*)d_in[4];
    const float* split_w = (const float*)d_in[5];
    const float* split_b = (const float*)d_in[6];
    const float* pw0 = (const float*)d_in[7];
    const float* pb0 = (const float*)d_in[8];
    const float* pw1 = (const float*)d_in[9];
    const float* pb1 = (const float*)d_in[10];
    const float* pw2 = (const float*)d_in[11];
    const float* pb2 = (const float*)d_in[12];
    const float* sw0 = (const float*)d_in[13];
    const float* sb0 = (const float*)d_in[14];
    const float* sw1 = (const float*)d_in[15];
    const float* sb1 = (const float*)d_in[16];
    const float* sw2 = (const float*)d_in[17];
    const float* sb2 = (const float*)d_in[18];
    float* out = (float*)d_out;

    float *qkv, *feats, *p0f, *p1f, *s0, *s1;
    __nv_bfloat16 *xah, *xal, *aah, *aal, *fth, *ftl, *b0h, *b0l;
    __nv_bfloat16 *qwh, *qwl, *pwh, *pwl, *swh, *swl;
    __nv_bfloat16 *w0h, *w0l, *w1h, *w1l, *u0h, *u0l, *u1h, *u1l, *u2h, *u2l;
    cudaGetSymbolAddress((void**)&qkv,   g_qkv);
    cudaGetSymbolAddress((void**)&feats, g_feats);
    cudaGetSymbolAddress((void**)&p0f,   g_p0f);
    cudaGetSymbolAddress((void**)&p1f,   g_p1f);
    cudaGetSymbolAddress((void**)&s0,    g_s0);
    cudaGetSymbolAddress((void**)&s1,    g_s1);
    cudaGetSymbolAddress((void**)&xah,   g_xah);
    cudaGetSymbolAddress((void**)&xal,   g_xal);
    cudaGetSymbolAddress((void**)&aah,   g_aah);
    cudaGetSymbolAddress((void**)&aal,   g_aal);
    cudaGetSymbolAddress((void**)&fth,   g_fth);
    cudaGetSymbolAddress((void**)&ftl,   g_ftl);
    cudaGetSymbolAddress((void**)&b0h,   g_b0h);
    cudaGetSymbolAddress((void**)&b0l,   g_b0l);
    cudaGetSymbolAddress((void**)&qwh,   g_qwh);
    cudaGetSymbolAddress((void**)&qwl,   g_qwl);
    cudaGetSymbolAddress((void**)&pwh,   g_pwh);
    cudaGetSymbolAddress((void**)&pwl,   g_pwl);
    cudaGetSymbolAddress((void**)&swh,   g_swh);
    cudaGetSymbolAddress((void**)&swl,   g_swl);
    cudaGetSymbolAddress((void**)&w0h,   g_w0h);
    cudaGetSymbolAddress((void**)&w0l,   g_w0l);
    cudaGetSymbolAddress((void**)&w1h,   g_w1h);
    cudaGetSymbolAddress((void**)&w1l,   g_w1l);
    cudaGetSymbolAddress((void**)&u0h,   g_u0h);
    cudaGetSymbolAddress((void**)&u0l,   g_u0l);
    cudaGetSymbolAddress((void**)&u1h,   g_u1h);
    cudaGetSymbolAddress((void**)&u1l,   g_u1l);
    cudaGetSymbolAddress((void**)&u2h,   g_u2h);
    cudaGetSymbolAddress((void**)&u2l,   g_u2l);

    cudaFuncSetAttribute(gemm_mma<0, false>,
                         cudaFuncAttributeMaxDynamicSharedMemorySize, GEMM_MMA_SMEM);
    cudaFuncSetAttribute(gemm_mma<1, false>,
                         cudaFuncAttributeMaxDynamicSharedMemorySize, GEMM_MMA_SMEM);
    cudaFuncSetAttribute(gemm_mma<2, true>,
                         cudaFuncAttributeMaxDynamicSharedMemorySize, GEMM_MMA_SMEM);
    cudaFuncSetAttribute(gemm_mma<3, true>,
                         cudaFuncAttributeMaxDynamicSharedMemorySize, GEMM_MMA_SMEM);
    cudaFuncSetAttribute(gemm_mma<3, false>,
                         cudaFuncAttributeMaxDynamicSharedMemorySize, GEMM_MMA_SMEM);
    cudaFuncSetAttribute(gemm_mma<4, false>,
                         cudaFuncAttributeMaxDynamicSharedMemorySize, GEMM_MMA_SMEM);

    const dim3 tb(32, 8);

    // -------- weight / input prep (all independent, hoisted upfront) --------
    split_rows<<<(TOK * 256 + 255) / 256, 256>>>(latent, xah, xal, TOK * 256);
    for (int l = 0; l < 3; l++) {
        transpose_split<<<dim3(768 / 32, 256 / 32), tb>>>(
            qkv_w + l * 256 * 768, qwh + l * 768 * 256, qwl + l * 768 * 256,
            256, 768, 768);
        transpose_split<<<dim3(256 / 32, 256 / 32), tb>>>(
            proj_w + l * 256 * 256, pwh + l * 256 * 256, pwl + l * 256 * 256,
            256, 256, 256);
    }
    split_rows<<<(512 * 256 + 255) / 256, 256>>>(split_w, swh, swl, 512 * 256);
    transpose_split<<<dim3(2048 / 32, 512 / 32), tb>>>(pw0, w0h, w0l, 512, 2048, 2048);
    transpose_split<<<dim3(1024 / 32, 256 / 32), tb>>>(pw1, w1h, w1l, 256, 1024, 1024);
    transpose_split<<<dim3(1024 / 32, 512 / 32), tb>>>(sw0, u0h, u0l, 512, 1024, 1024);
    transpose_split<<<dim3(512 / 32, 256 / 32), tb>>>(sw1, u1h, u1l, 256, 512, 512);
    pad_split<<<64, 256>>>(sw2, u2h, u2l, 32, 128);

    // -------- transformer layers --------
    for (int l = 0; l < 3; l++) {
        gemm_mma<0, false><<<dim3(768 / 128, TOK / 128), 256, GEMM_MMA_SMEM>>>(
            xah, xal, qwh + l * 768 * 256, qwl + l * 768 * 256,
            qkv_b + l * 768, qkv, nullptr, nullptr,
            TOK, 768, 256, 768, 0, 0, 0);

        na3d_attn_v5<<<TOK / 4, 256>>>(qkv, aah, aal);

        gemm_mma<4, false><<<dim3(256 / 128, TOK / 128), 256, GEMM_MMA_SMEM>>>(
            aah, aal, pwh + l * 256 * 256, pwl + l * 256 * 256,
            proj_b + l * 256, nullptr, xah, xal,
            TOK, 256, 256, 256, 0, 0, 0);
    }

    // split (MODE 1): feats [512][5760] channel-first
    gemm_mma<1, false><<<dim3(TOK / 128, 512 / 128), 256, GEMM_MMA_SMEM>>>(
        swh, swl, xah, xal, split_b, feats, nullptr, nullptr,
        512, TOK, 256, TOK, 0, 0, 0);

    // featsT (all 5760 tokens: press uses rows [0,4608), surf rows [4608,5760))
    transpose_split<<<dim3(5760 / 32, 512 / 32), tb>>>(feats, fth, ftl, 512, 5760, TOK);

    // press0 (MODE 2): -> fp32 p0 (256, 8, 48, 96)
    gemm_mma<2, true><<<dim3(4608 / 128, 2048 / 128), 256, GEMM_MMA_SMEM>>>(
        w0h, w0l, fth, ftl, pb0, p0f, nullptr, nullptr,
        2048, 4608, 512, 0, 4, 24, 48);

    // press1 (MODE 2): B = p0T
    transpose_split<<<dim3(36864 / 32, 256 / 32), tb>>>(p0f, b0h, b0l, 256, 36864, 36864);
    gemm_mma<2, true><<<dim3(36864 / 128, 1024 / 128), 256, GEMM_MMA_SMEM>>>(
        w1h, w1l, b0h, b0l, pb1, p1f, nullptr, nullptr,
        1024, 36864, 256, 0, 8, 48, 96);

    // press2 (fp32, M=40 -> BM=64; B already [K][N])
    gemm_db<64, true, false, 2, false><<<dim3(294912 / 128, 1), 128>>>(
        pw2, p1f, pb2, out + 8 * 192 * 384,
        40, 294912, 128, 40, 294912, 0, 16, 96, 192);

    // surf0 (MODE 3): A = sw0T, B = featsT rows 4608.., -> fp32 s0 (256,48,96)
    gemm_mma<3, true><<<dim3(1152 / 128, 1024 / 128), 256, GEMM_MMA_SMEM>>>(
        u0h, u0l, fth + (size_t)4608 * 512, ftl + (size_t)4608 * 512,
        sb0, s0, nullptr, nullptr,
        1024, 1152, 512, 0, 0, 24, 48);

    // surf1 (MODE 3): B = s0T (reuse b0 buffer; p0T consumed by press1 already)
    transpose_split<<<dim3(4608 / 32, 256 / 32), tb>>>(s0, b0h, b0l, 256, 4608, 4608);
    gemm_mma<3, true><<<dim3(4608 / 128, 512 / 128), 256, GEMM_MMA_SMEM>>>(
        u1h, u1l, b0h, b0l, sb1, s1, nullptr, nullptr,
        512, 4608, 256, 0, 0, 48, 96);

    // surf2 (MODE 3, M=32 guarded): B = s1T (offset region of b0 buffer)
    __nv_bfloat16* s1th = b0h + (size_t)4608 * 256;
    __nv_bfloat16* s1tl = b0l + (size_t)4608 * 256;
    transpose_split<<<dim3(18432 / 32, 128 / 32), tb>>>(s1, s1th, s1tl, 128, 18432, 18432);
    gemm_mma<3, false><<<dim3(18432 / 128, 1), 256, GEMM_MMA_SMEM>>>(
        u2h, u2l, s1th, s1tl, sb2, out, nullptr, nullptr,
        32, 18432, 128, 0, 0, 96, 192);
}

// round 16
// speedup vs baseline: 2.1481x; 1.0174x over previous
#include <cuda_runtime.h>
#include <cuda_bf16.h>
#include <math.h>
#include <stdint.h>

// ---------------------------------------------------------------------------
// Problem constants
// ---------------------------------------------------------------------------
#define TOK   5760          // 5*24*48
#define CH    256
#define DD    5
#define HH    24
#define WW    48
#define NHEAD 8
#define HDIM  32

// fp32 scratch
__device__ float g_qkv [TOK * 768];
__device__ float g_feats[512 * TOK];                 // channel-first (512, 5, 24, 48)
__device__ float g_p0f [256 * 36864];                // press0 out (256, 8, 48, 96)
__device__ float g_p1f [128 * 294912];               // press1 out (128, 16, 96, 192)
__device__ float g_s0  [256 * 48 * 96];
__device__ float g_s1  [128 * 96 * 192];

// bf16 hi/lo scratch
__device__ __align__(16) __nv_bfloat16 g_xah[TOK * 256],   g_xal[TOK * 256];   // x (layer act)
__device__ __align__(16) __nv_bfloat16 g_aah[TOK * 256],   g_aal[TOK * 256];   // attn out
__device__ __align__(16) __nv_bfloat16 g_qwh[3 * 768 * 256], g_qwl[3 * 768 * 256]; // qkv_w^T
__device__ __align__(16) __nv_bfloat16 g_pwh[3 * 256 * 256], g_pwl[3 * 256 * 256]; // proj_w^T
__device__ __align__(16) __nv_bfloat16 g_swh[512 * 256],   g_swl[512 * 256];   // split_w
__device__ __align__(16) __nv_bfloat16 g_w0h[2048 * 512],  g_w0l[2048 * 512];  // pw0^T
__device__ __align__(16) __nv_bfloat16 g_w1h[1024 * 256],  g_w1l[1024 * 256];  // pw1^T
__device__ __align__(16) __nv_bfloat16 g_u0h[1024 * 512],  g_u0l[1024 * 512];  // sw0^T
__device__ __align__(16) __nv_bfloat16 g_u1h[512 * 256],   g_u1l[512 * 256];   // sw1^T
__device__ __align__(16) __nv_bfloat16 g_u2h[128 * 128],   g_u2l[128 * 128];   // sw2 padded
__device__ __align__(16) __nv_bfloat16 g_fth[5760 * 512],  g_ftl[5760 * 512];  // featsT (all d)
__device__ __align__(16) __nv_bfloat16 g_b0h[36864 * 256], g_b0l[36864 * 256]; // p0T; later s0T/s1T

// ---------------------------------------------------------------------------
// fp32 -> bf16 hi/lo split, contiguous
// ---------------------------------------------------------------------------
__global__ void split_rows(const float* __restrict__ in,
                           __nv_bfloat16* __restrict__ oh,
                           __nv_bfloat16* __restrict__ ol, int n)
{
    int i = blockIdx.x * blockDim.x + threadIdx.x;
    if (i < n) {
        float v = in[i];
        __nv_bfloat16 h = __float2bfloat16(v);
        oh[i] = h;
        ol[i] = __float2bfloat16(v - __bfloat162float(h));
    }
}

// fp32 [R][C] (row stride ld) -> bf16 hi/lo [C][R]   (R, C multiples of 32)
__global__ void transpose_split(const float* __restrict__ in,
                                __nv_bfloat16* __restrict__ oh,
                                __nv_bfloat16* __restrict__ ol,
                                int R, int C, int ld)
{
    __shared__ float t[32][33];
    const int r0 = blockIdx.y * 32, c0 = blockIdx.x * 32;
    const int tx = threadIdx.x, ty = threadIdx.y;
    #pragma unroll
    for (int i = ty; i < 32; i += 8)
        t[i][tx] = in[(size_t)(r0 + i) * ld + c0 + tx];
    __syncthreads();
    #pragma unroll
    for (int i = ty; i < 32; i += 8) {
        float v = t[tx][i];
        __nv_bfloat16 h = __float2bfloat16(v);
        oh[(size_t)(c0 + i) * R + r0 + tx] = h;
        ol[(size_t)(c0 + i) * R + r0 + tx] = __float2bfloat16(v - __bfloat162float(h));
    }
}

// src fp32 [K][Mreal] -> padded A hi/lo [128][K], rows >= Mreal zero. K*128 elems.
__global__ void pad_split(const float* __restrict__ src,
                          __nv_bfloat16* __restrict__ oh,
                          __nv_bfloat16* __restrict__ ol, int Mreal, int K)
{
    const int idx = blockIdx.x * 256 + threadIdx.x;
    if (idx < 128 * K) {
        const int m = idx / K, k = idx % K;
        float v = (m < Mreal) ? src[k * Mreal + m] : 0.f;
        __nv_bfloat16 h = __float2bfloat16(v);
        oh[idx] = h;
        ol[idx] = __float2bfloat16(v - __bfloat162float(h));
    }
}

// ---------------------------------------------------------------------------
// Tensor-core GEMM, bf16x3 split (hi*hi + hi*lo + lo*hi), fp32 accum.
// cp.async double-buffered; ldmatrix.x4 fragment loads.
//   C[m][n] = epilogue( sum_k A[m][k]*B[k][n] + bias )
// Tile 128x128x32, 256 threads = 8 warps (2 m x 4 n), warp tile 64x32,
// mma.sync.m16n8k16. N multiple of 128; K multiple of 32.
// MODE 0: fp32 C row-major [M][ldc], bias[n]
// MODE 1: fp32 C row-major [M][ldc], bias[m]
// MODE 2: up3d scatter to fp32 C, bias[m>>3], optional SiLU, m<M guarded
// MODE 3: up2d scatter to fp32 C, bias[m>>2], optional SiLU, m<M guarded
// MODE 4: bf16 hi/lo Oh/Ol row-major [M][ldc], bias[n]
// ---------------------------------------------------------------------------
#define MMA_BF16(c, a0, a1, a2, a3, b0, b1)                                   \
    asm volatile("mma.sync.aligned.m16n8k16.row.col.f32.bf16.bf16.f32 "       \
                 "{%0,%1,%2,%3}, {%4,%5,%6,%7}, {%8,%9}, {%0,%1,%2,%3};"      \
                 : "+f"(c[0]), "+f"(c[1]), "+f"(c[2]), "+f"(c[3])             \
                 : "r"(a0), "r"(a1), "r"(a2), "r"(a3), "r"(b0), "r"(b1))

__device__ __forceinline__ void cp16(uint32_t dst, const void* src) {
    asm volatile("cp.async.ca.shared.global [%0], [%1], 16;" :: "r"(dst), "l"(src));
}

__device__ __forceinline__ void ldsm4(uint32_t& r0, uint32_t& r1,
                                      uint32_t& r2, uint32_t& r3, uint32_t addr) {
    asm volatile("ldmatrix.sync.aligned.m8n8.x4.shared.b16 {%0,%1,%2,%3}, [%4];"
                 : "=r"(r0), "=r"(r1), "=r"(r2), "=r"(r3) : "r"(addr));
}

#define GEMM_MMA_SMEM 81920

template<int MODE, bool SILU>
__global__ __launch_bounds__(256)
void gemm_mma(const __nv_bfloat16* __restrict__ Ah, const __nv_bfloat16* __restrict__ Al,
              const __nv_bfloat16* __restrict__ Bh, const __nv_bfloat16* __restrict__ Bl,
              const float* __restrict__ bias, float* __restrict__ C,
              __nv_bfloat16* __restrict__ Oh, __nv_bfloat16* __restrict__ Ol,
              int M, int N, int K, int ldc, int Din, int Hin, int Win)
{
    constexpr int RS = 20;                  // smem words per row (16 data + 4 pad)
    constexpr int BUFW = 128 * RS;          // words per array
    extern __shared__ __align__(16) float smem_dyn[];
    const uint32_t sbase = (uint32_t)__cvta_generic_to_shared(smem_dyn);

    const int tid  = threadIdx.x;
    const int warp = tid >> 5, lane = tid & 31;
    const int g = lane >> 2, t = lane & 3;
    const int wm = warp & 1, wn = warp >> 1;       // warp tile origin (wm*64, wn*32)
    const int m0 = blockIdx.y * 128, n0 = blockIdx.x * 128;

    const int lrow = tid >> 1, lseg = tid & 1;     // loader: 2 threads/row, 16 bf16 each

    // ldmatrix per-lane row/chunk decomposition
    const int rA = (lane & 7) + ((lane >> 3) & 1) * 8;
    const int cA = (lane >> 4) & 1;
    const int rB = (lane & 7) + ((lane >> 4) & 1) * 8;
    const int cB = (lane >> 3) & 1;

    float acc[4][4][4];
    #pragma unroll
    for (int a = 0; a < 4; a++)
        #pragma unroll
        for (int b = 0; b < 4; b++)
            #pragma unroll
            for (int c = 0; c < 4; c++) acc[a][b][c] = 0.f;

    auto issue = [&](int k0, int buf) {
        const size_t ga = (size_t)(m0 + lrow) * K + k0 + lseg * 16;
        const size_t gb = (size_t)(n0 + lrow) * K + k0 + lseg * 16;
        const uint32_t doff = (uint32_t)(lrow * RS + lseg * 8) * 4;
        const uint32_t p0 = sbase + (uint32_t)(buf * 4 + 0) * BUFW * 4 + doff;
        const uint32_t p1 = sbase + (uint32_t)(buf * 4 + 1) * BUFW * 4 + doff;
        const uint32_t p2 = sbase + (uint32_t)(buf * 4 + 2) * BUFW * 4 + doff;
        const uint32_t p3 = sbase + (uint32_t)(buf * 4 + 3) * BUFW * 4 + doff;
        cp16(p0, Ah + ga); cp16(p0 + 16, Ah + ga + 8);
        cp16(p1, Al + ga); cp16(p1 + 16, Al + ga + 8);
        cp16(p2, Bh + gb); cp16(p2 + 16, Bh + gb + 8);
        cp16(p3, Bl + gb); cp16(p3 + 16, Bl + gb + 8);
    };

    issue(0, 0);
    asm volatile("cp.async.commit_group;" ::: "memory");

    const int nslab = K >> 5;
    int buf = 0;
    for (int s = 0; s < nslab; s++) {
        asm volatile("cp.async.wait_group 0;" ::: "memory");
        __syncthreads();
        if (s + 1 < nslab) {
            issue((s + 1) << 5, buf ^ 1);
            asm volatile("cp.async.commit_group;" ::: "memory");
        }

        const uint32_t bAh = sbase + (uint32_t)(buf * 4 + 0) * BUFW * 4;
        const uint32_t bAl = sbase + (uint32_t)(buf * 4 + 1) * BUFW * 4;
        const uint32_t bBh = sbase + (uint32_t)(buf * 4 + 2) * BUFW * 4;
        const uint32_t bBl = sbase + (uint32_t)(buf * 4 + 3) * BUFW * 4;

        #pragma unroll
        for (int ks = 0; ks < 2; ks++) {
            uint32_t bh[4][2], bl[4][2];
            #pragma unroll
            for (int p = 0; p < 2; p++) {
                const uint32_t boff =
                    (uint32_t)((wn * 32 + p * 16 + rB) * RS + ks * 8 + cB * 4) * 4;
                ldsm4(bh[2 * p][0], bh[2 * p][1], bh[2 * p + 1][0], bh[2 * p + 1][1],
                      bBh + boff);
                ldsm4(bl[2 * p][0], bl[2 * p][1], bl[2 * p + 1][0], bl[2 * p + 1][1],
                      bBl + boff);
            }
            #pragma unroll
            for (int mt = 0; mt < 4; mt++) {
                const uint32_t aoff =
                    (uint32_t)((wm * 64 + mt * 16 + rA) * RS + ks * 8 + cA * 4) * 4;
                uint32_t ah0, ah1, ah2, ah3, al0, al1, al2, al3;
                ldsm4(ah0, ah1, ah2, ah3, bAh + aoff);
                ldsm4(al0, al1, al2, al3, bAl + aoff);
                #pragma unroll
                for (int nt = 0; nt < 4; nt++) {
                    MMA_BF16(acc[mt][nt], ah0, ah1, ah2, ah3, bh[nt][0], bh[nt][1]);
                    MMA_BF16(acc[mt][nt], ah0, ah1, ah2, ah3, bl[nt][0], bl[nt][1]);
                    MMA_BF16(acc[mt][nt], al0, al1, al2, al3, bh[nt][0], bh[nt][1]);
                }
            }
        }
        buf ^= 1;
    }

    // element (mt, nt, reg): m = m0+wm*64+mt*16+g+(reg>=2)*8,
    //                        n = n0+wn*32+nt*8+t*2+(reg&1)
    if (MODE == 0 || MODE == 1) {
        #pragma unroll
        for (int mt = 0; mt < 4; mt++) {
            const int mb = m0 + wm * 64 + mt * 16 + g;
            const float bmA = (MODE == 1) ? bias[mb]     : 0.f;
            const float bmB = (MODE == 1) ? bias[mb + 8] : 0.f;
            #pragma unroll
            for (int nt = 0; nt < 4; nt++) {
                const int nb = n0 + wn * 32 + nt * 8 + t * 2;
                float b0 = bmA, b1 = bmA, b2 = bmB, b3 = bmB;
                if (MODE == 0) { b0 = b2 = bias[nb]; b1 = b3 = bias[nb + 1]; }
                float2 v0 = make_float2(acc[mt][nt][0] + b0, acc[mt][nt][1] + b1);
                float2 v1 = make_float2(acc[mt][nt][2] + b2, acc[mt][nt][3] + b3);
                *(float2*)&C[(size_t)mb * ldc + nb]       = v0;
                *(float2*)&C[(size_t)(mb + 8) * ldc + nb] = v1;
            }
        }
    } else if (MODE == 4) {
        #pragma unroll
        for (int mt = 0; mt < 4; mt++) {
            const int mb = m0 + wm * 64 + mt * 16 + g;
            #pragma unroll
            for (int nt = 0; nt < 4; nt++) {
                const int nb = n0 + wn * 32 + nt * 8 + t * 2;
                const float b0 = bias[nb], b1 = bias[nb + 1];
                #pragma unroll
                for (int half = 0; half < 2; half++) {
                    const int m = mb + half * 8;
                    const float va = acc[mt][nt][half * 2 + 0] + b0;
                    const float vb = acc[mt][nt][half * 2 + 1] + b1;
                    const __nv_bfloat16 ha = __float2bfloat16(va);
                    const __nv_bfloat16 hb = __float2bfloat16(vb);
                    __nv_bfloat162 hp, lp;
                    hp.x = ha; hp.y = hb;
                    lp.x = __float2bfloat16(va - __bfloat162float(ha));
                    lp.y = __float2bfloat16(vb - __bfloat162float(hb));
                    *(__nv_bfloat162*)&Oh[(size_t)m * ldc + nb] = hp;
                    *(__nv_bfloat162*)&Ol[(size_t)m * ldc + nb] = lp;
                }
            }
        }
    } else if (MODE == 2) { // up3d scatter to fp32 (o-major)
        int nw[4][2], nh[4][2], nd[4][2];
        #pragma unroll
        for (int nt = 0; nt < 4; nt++)
            #pragma unroll
            for (int e = 0; e < 2; e++) {
                const int n = n0 + wn * 32 + nt * 8 + t * 2 + e;
                nw[nt][e] = n % Win;
                const int tt = n / Win;
                nh[nt][e] = tt % Hin;
                nd[nt][e] = tt / Hin;
            }
        const int OD = 2 * Din, OH = 2 * Hin, OW = 2 * Win;
        #pragma unroll
        for (int mt = 0; mt < 4; mt++) {
            #pragma unroll
            for (int half = 0; half < 2; half++) {
                const int m = m0 + wm * 64 + mt * 16 + g + half * 8;
                if (m < M) {
                    const int o = m >> 3, r = m & 7;
                    const int ri = (r >> 2) & 1, rj = (r >> 1) & 1, rk = r & 1;
                    const float bv = bias[o];
                    #pragma unroll
                    for (int nt = 0; nt < 4; nt++) {
                        #pragma unroll
                        for (int e = 0; e < 2; e++) {
                            float v = acc[mt][nt][half * 2 + e] + bv;
                            if (SILU) v = v / (1.f + __expf(-v));
                            const size_t idx =
                                ((size_t)(o * OD + 2 * nd[nt][e] + ri) * OH
                                 + 2 * nh[nt][e] + rj) * OW + 2 * nw[nt][e] + rk;
                            C[idx] = v;
                        }
                    }
                }
            }
        }
    } else { // MODE 3 : up2d scatter to fp32 (o-major)
        int nw[4][2], nh[4][2];
        #pragma unroll
        for (int nt = 0; nt < 4; nt++)
            #pragma unroll
            for (int e = 0; e < 2; e++) {
                const int n = n0 + wn * 32 + nt * 8 + t * 2 + e;
                nw[nt][e] = n % Win;
                nh[nt][e] = n / Win;
            }
        const int OH = 2 * Hin, OW = 2 * Win;
        #pragma unroll
        for (int mt = 0; mt < 4; mt++) {
            #pragma unroll
            for (int half = 0; half < 2; half++) {
                const int m = m0 + wm * 64 + mt * 16 + g + half * 8;
                if (m < M) {
                    const int o = m >> 2, r = m & 3;
                    const int ri = (r >> 1) & 1, rj = r & 1;
                    const float bv = bias[o];
                    #pragma unroll
                    for (int nt = 0; nt < 4; nt++) {
                        #pragma unroll
                        for (int e = 0; e < 2; e++) {
                            float v = acc[mt][nt][half * 2 + e] + bv;
                            if (SILU) v = v / (1.f + __expf(-v));
                            const size_t idx =
                                (size_t)(o * OH + 2 * nh[nt][e] + ri) * OW
                                + 2 * nw[nt][e] + rj;
                            C[idx] = v;
                        }
                    }
                }
            }
        }
    }
}

// ---------------------------------------------------------------------------
// Double-buffered fp32 SGEMM (press2 only; B layout [K][N] is ideal here)
// ---------------------------------------------------------------------------
template<int BM, bool TA, bool TB, int MODE, bool SILU>
__global__ __launch_bounds__(BM * 2)
void gemm_db(const float* __restrict__ A, const float* __restrict__ B,
             const float* __restrict__ bias, float* __restrict__ C,
             int M, int N, int K, int lda, int ldb, int ldc,
             int Din, int Hin, int Win)
{
    constexpr int THREADS = BM * 2;
    __shared__ float As[2][8][BM];
    __shared__ float Bs[2][8][128];
    const int tid = threadIdx.x;
    const int m0 = blockIdx.y * BM;
    const int n0 = blockIdx.x * 128;
    const int tx = tid & 15, ty = tid >> 4;

    int a_k, a_m;
    if (TA) { a_k = tid / (BM / 4); a_m = (tid % (BM / 4)) * 4; }
    else    { a_m = tid >> 1;       a_k = (tid & 1) << 2; }
    const int bn_k = TB ? ((tid & 1) << 2) : (tid >> 5);
    const int bn_n = TB ? (tid >> 1)       : ((tid & 31) << 2);

    float4 ra, rb0, rb1;

    auto ldA = [&](int k0) {
        if (TA) {
            const float* p = A + (size_t)(k0 + a_k) * lda + m0 + a_m;
            float4 v;
            if (m0 + a_m + 3 < M) v = *(const float4*)p;
            else {
                v.x = (m0 + a_m     < M) ? p[0] : 0.f;
                v.y = (m0 + a_m + 1 < M) ? p[1] : 0.f;
                v.z = (m0 + a_m + 2 < M) ? p[2] : 0.f;
                v.w = (m0 + a_m + 3 < M) ? p[3] : 0.f;
            }
            ra = v;
        } else {
            float4 v = make_float4(0.f, 0.f, 0.f, 0.f);
            if (m0 + a_m < M) v = *(const float4*)(A + (size_t)(m0 + a_m) * lda + k0 + a_k);
            ra = v;
        }
    };
    auto ldB = [&](int k0) {
        if (TB) {
            rb0 = *(const float4*)(B + (size_t)(n0 + bn_n) * ldb + k0 + bn_k);
        } else {
            rb0 = *(const float4*)(B + (size_t)(k0 + bn_k) * ldb + n0 + bn_n);
            if (THREADS == 128)
                rb1 = *(const float4*)(B + (size_t)(k0 + bn_k + 4) * ldb + n0 + bn_n);
        }
    };
    auto stA = [&](int buf) {
        if (TA) {
            *(float4*)&As[buf][a_k][a_m] = ra;
        } else {
            As[buf][a_k + 0][a_m] = ra.x; As[buf][a_k + 1][a_m] = ra.y;
            As[buf][a_k + 2][a_m] = ra.z; As[buf][a_k + 3][a_m] = ra.w;
        }
    };
    auto stB = [&](int buf) {
        if (TB) {
            Bs[buf][bn_k + 0][bn_n] = rb0.x; Bs[buf][bn_k + 1][bn_n] = rb0.y;
            Bs[buf][bn_k + 2][bn_n] = rb0.z; Bs[buf][bn_k + 3][bn_n] = rb0.w;
        } else {
            *(float4*)&Bs[buf][bn_k][bn_n] = rb0;
            if (THREADS == 128) *(float4*)&Bs[buf][bn_k + 4][bn_n] = rb1;
        }
    };

    float acc[8][8] = {};

    ldA(0); ldB(0);
    stA(0); stB(0);
    __syncthreads();

    const int nslab = K >> 3;
    int buf = 0;
    for (int s = 0; s < nslab; s++) {
        if (s + 1 < nslab) { ldA((s + 1) << 3); ldB((s + 1) << 3); }
        #pragma unroll
        for (int kk = 0; kk < 8; kk++) {
            float a[8], b[8];
            *(float4*)&a[0] = *(float4*)&As[buf][kk][ty * 4];
            *(float4*)&a[4] = *(float4*)&As[buf][kk][ty * 4 + BM / 2];
            *(float4*)&b[0] = *(float4*)&Bs[buf][kk][tx * 4];
            *(float4*)&b[4] = *(float4*)&Bs[buf][kk][tx * 4 + 64];
            #pragma unroll
            for (int i = 0; i < 8; i++)
                #pragma unroll
                for (int j = 0; j < 8; j++)
                    acc[i][j] += a[i] * b[j];
        }
        if (s + 1 < nslab) {
            stA(buf ^ 1); stB(buf ^ 1);
            __syncthreads();
            buf ^= 1;
        }
    }

    if (MODE == 2) {
        int dj[8], hj[8], wj[8];
        #pragma unroll
        for (int j = 0; j < 8; j++) {
            const int n = n0 + tx * 4 + (j & 3) + ((j >> 2) * 64);
            wj[j] = n % Win;
            const int t = n / Win;
            hj[j] = t % Hin;
            dj[j] = t / Hin;
        }
        const int OD = 2 * Din, OH = 2 * Hin, OW = 2 * Win;
        #pragma unroll
        for (int i = 0; i < 8; i++) {
            const int m = m0 + ty * 4 + (i & 3) + ((i >> 2) * (BM / 2));
            if (m < M) {
                const int o = m >> 3, r = m & 7;
                const int ri = (r >> 2) & 1, rj = (r >> 1) & 1, rk = r & 1;
                const float bv = bias[o];
                #pragma unroll
                for (int j = 0; j < 8; j++) {
                    float v = acc[i][j] + bv;
                    if (SILU) v = v / (1.f + __expf(-v));
                    const size_t idx =
                        ((size_t)(o * OD + 2 * dj[j] + ri) * OH + 2 * hj[j] + rj) * OW
                        + 2 * wj[j] + rk;
                    C[idx] = v;
                }
            }
        }
    }
}

// ---------------------------------------------------------------------------
// 3D neighborhood attention v5: 4 tokens per block share a window union.
// __launch_bounds__(256, 4): cap regs at 64 -> 4 blocks/SM (was 70 regs / 3).
// ---------------------------------------------------------------------------
__global__ __launch_bounds__(256, 4)
void na3d_attn_v5(const float* __restrict__ qkv,
                  __nv_bfloat16* __restrict__ oh,
                  __nv_bfloat16* __restrict__ ol)
{
    __shared__ __align__(16) float sp[NHEAD][120][4];

    const int t4 = blockIdx.x * 4;
    const int d = t4 / (HH * WW);
    const int rem = t4 % (HH * WW);
    const int h = rem / WW;
    const int w0 = rem % WW;
    const int head = threadIdx.x >> 5;
    const int lane = threadIdx.x & 31;
    const int qd  = lane >> 2;
    const int sub = lane & 3;

    const int sd = min(max(d - 1, 0), DD - 3);
    const int sh = min(max(h - 2, 0), HH - 5);
    const int swu = min(max(w0 - 2, 0), WW - 8);
    int off[4];
    #pragma unroll
    for (int t = 0; t < 4; t++)
        off[t] = min(max(w0 + t - 2, 0), WW - 5) - swu;

    const float sc0 = 0.17677669529663687f;
    float4 q0[4], q1[4];
    #pragma unroll
    for (int t = 0; t < 4; t++) {
        const float* qp = qkv + (size_t)(t4 + t) * 768 + head * HDIM + sub * 8;
        q0[t] = *(const float4*)qp;
        q1[t] = *(const float4*)(qp + 4);
        q0[t].x *= sc0; q0[t].y *= sc0; q0[t].z *= sc0; q0[t].w *= sc0;
        q1[t].x *= sc0; q1[t].y *= sc0; q1[t].z *= sc0; q1[t].w *= sc0;
    }

    for (int r = 0; r < 15; r++) {
        const int dd = r / 5, hh2 = r % 5;
        const int nb = ((sd + dd) * HH + (sh + hh2)) * WW + swu + qd;
        const float* kp = qkv + (size_t)nb * 768 + 256 + head * HDIM + sub * 8;
        const float4 k0 = *(const float4*)kp;
        const float4 k1 = *(const float4*)(kp + 4);
        float4 sv;
        float sr[4];
        #pragma unroll
        for (int t = 0; t < 4; t++) {
            float s = q0[t].x * k0.x + q0[t].y * k0.y + q0[t].z * k0.z + q0[t].w * k0.w
                    + q1[t].x * k1.x + q1[t].y * k1.y + q1[t].z * k1.z + q1[t].w * k1.w;
            s += __shfl_xor_sync(0xffffffffu, s, 1);
            s += __shfl_xor_sync(0xffffffffu, s, 2);
            const bool valid = (qd >= off[t]) && (qd < off[t] + 5);
            sr[t] = valid ? s : -1e30f;
        }
        sv.x = sr[0]; sv.y = sr[1]; sv.z = sr[2]; sv.w = sr[3];
        if (sub == 0) *(float4*)&sp[head][r * 8 + qd][0] = sv;
    }
    __syncwarp();

    #pragma unroll
    for (int t = 0; t < 4; t++) {
        const float v0 = sp[head][lane][t];
        const float v1 = sp[head][lane + 32][t];
        const float v2 = sp[head][lane + 64][t];
        const float v3 = (lane < 24) ? sp[head][lane + 96][t] : -1e30f;
        float m = fmaxf(fmaxf(v0, v1), fmaxf(v2, v3));
        #pragma unroll
        for (int o = 16; o; o >>= 1) m = fmaxf(m, __shfl_xor_sync(0xffffffffu, m, o));
        const float e0 = __expf(v0 - m);
        const float e1 = __expf(v1 - m);
        const float e2 = __expf(v2 - m);
        const float e3 = (lane < 24) ? __expf(v3 - m) : 0.f;
        float ssum = e0 + e1 + e2 + e3;
        #pragma unroll
        for (int o = 16; o; o >>= 1) ssum += __shfl_xor_sync(0xffffffffu, ssum, o);
        const float inv = 1.f / ssum;
        sp[head][lane][t]      = e0 * inv;
        sp[head][lane + 32][t] = e1 * inv;
        sp[head][lane + 64][t] = e2 * inv;
        if (lane < 24) sp[head][lane + 96][t] = e3 * inv;
    }
    __syncwarp();

    float acc[4] = {0.f, 0.f, 0.f, 0.f};
    const float* vbase = qkv + 512 + head * HDIM + lane;
    int p = 0;
    #pragma unroll
    for (int dd = 0; dd < 3; dd++) {
        #pragma unroll
        for (int hh2 = 0; hh2 < 5; hh2++) {
            const int rowb = ((sd + dd) * HH + (sh + hh2)) * WW + swu;
            #pragma unroll
            for (int wwu = 0; wwu < 8; wwu++) {
                const float v = vbase[(size_t)(rowb + wwu) * 768];
                const float4 pr = *(const float4*)&sp[head][p][0];
                acc[0] += pr.x * v;
                acc[1] += pr.y * v;
                acc[2] += pr.z * v;
                acc[3] += pr.w * v;
                p++;
            }
        }
    }
    #pragma unroll
    for (int t = 0; t < 4; t++) {
        const size_t oidx = (size_t)(t4 + t) * CH + head * HDIM + lane;
        const __nv_bfloat16 hv = __float2bfloat16(acc[t]);
        oh[oidx] = hv;
        ol[oidx] = __float2bfloat16(acc[t] - __bfloat162float(hv));
    }
}

// ---------------------------------------------------------------------------
// Launcher
// ---------------------------------------------------------------------------
extern "C" void kernel_launch(void* const* d_in, const int* in_sizes, int n_in,
                              void* d_out, int out_size)
{
    const float* latent  = (const float*)d_in[0];
    const float* qkv_w   = (const float*)d_in[1];
    const float* qkv_b   = (const float*)d_in[2];
    const float* proj_w  = (const float*)d_in[3];
    const float* proj_b  = (const float*)d_in[4];
    const float* split_w = (const float*)d_in[5];
    const float* split_b = (const float*)d_in[6];
    const float* pw0 = (const float*)d_in[7];
    const float* pb0 = (const float*)d_in[8];
    const float* pw1 = (const float*)d_in[9];
    const float* pb1 = (const float*)d_in[10];
    const float* pw2 = (const float*)d_in[11];
    const float* pb2 = (const float*)d_in[12];
    const float* sw0 = (const float*)d_in[13];
    const float* sb0 = (const float*)d_in[14];
    const float* sw1 = (const float*)d_in[15];
    const float* sb1 = (const float*)d_in[16];
    const float* sw2 = (const float*)d_in[17];
    const float* sb2 = (const float*)d_in[18];
    float* out = (float*)d_out;

    float *qkv, *feats, *p0f, *p1f, *s0, *s1;
    __nv_bfloat16 *xah, *xal, *aah, *aal, *fth, *ftl, *b0h, *b0l;
    __nv_bfloat16 *qwh, *qwl, *pwh, *pwl, *swh, *swl;
    __nv_bfloat16 *w0h, *w0l, *w1h, *w1l, *u0h, *u0l, *u1h, *u1l, *u2h, *u2l;
    cudaGetSymbolAddress((void**)&qkv,   g_qkv);
    cudaGetSymbolAddress((void**)&feats, g_feats);
    cudaGetSymbolAddress((void**)&p0f,   g_p0f);
    cudaGetSymbolAddress((void**)&p1f,   g_p1f);
    cudaGetSymbolAddress((void**)&s0,    g_s0);
    cudaGetSymbolAddress((void**)&s1,    g_s1);
    cudaGetSymbolAddress((void**)&xah,   g_xah);
    cudaGetSymbolAddress((void**)&xal,   g_xal);
    cudaGetSymbolAddress((void**)&aah,   g_aah);
    cudaGetSymbolAddress((void**)&aal,   g_aal);
    cudaGetSymbolAddress((void**)&fth,   g_fth);
    cudaGetSymbolAddress((void**)&ftl,   g_ftl);
    cudaGetSymbolAddress((void**)&b0h,   g_b0h);
    cudaGetSymbolAddress((void**)&b0l,   g_b0l);
    cudaGetSymbolAddress((void**)&qwh,   g_qwh);
    cudaGetSymbolAddress((void**)&qwl,   g_qwl);
    cudaGetSymbolAddress((void**)&pwh,   g_pwh);
    cudaGetSymbolAddress((void**)&pwl,   g_pwl);
    cudaGetSymbolAddress((void**)&swh,   g_swh);
    cudaGetSymbolAddress((void**)&swl,   g_swl);
    cudaGetSymbolAddress((void**)&w0h,   g_w0h);
    cudaGetSymbolAddress((void**)&w0l,   g_w0l);
    cudaGetSymbolAddress((void**)&w1h,   g_w1h);
    cudaGetSymbolAddress((void**)&w1l,   g_w1l);
    cudaGetSymbolAddress((void**)&u0h,   g_u0h);
    cudaGetSymbolAddress((void**)&u0l,   g_u0l);
    cudaGetSymbolAddress((void**)&u1h,   g_u1h);
    cudaGetSymbolAddress((void**)&u1l,   g_u1l);
    cudaGetSymbolAddress((void**)&u2h,   g_u2h);
    cudaGetSymbolAddress((void**)&u2l,   g_u2l);

    cudaFuncSetAttribute(gemm_mma<0, false>,
                         cudaFuncAttributeMaxDynamicSharedMemorySize, GEMM_MMA_SMEM);
    cudaFuncSetAttribute(gemm_mma<1, false>,
                         cudaFuncAttributeMaxDynamicSharedMemorySize, GEMM_MMA_SMEM);
    cudaFuncSetAttribute(gemm_mma<2, true>,
                         cudaFuncAttributeMaxDynamicSharedMemorySize, GEMM_MMA_SMEM);
    cudaFuncSetAttribute(gemm_mma<3, true>,
                         cudaFuncAttributeMaxDynamicSharedMemorySize, GEMM_MMA_SMEM);
    cudaFuncSetAttribute(gemm_mma<3, false>,
                         cudaFuncAttributeMaxDynamicSharedMemorySize, GEMM_MMA_SMEM);
    cudaFuncSetAttribute(gemm_mma<4, false>,
                         cudaFuncAttributeMaxDynamicSharedMemorySize, GEMM_MMA_SMEM);

    const dim3 tb(32, 8);

    // -------- weight / input prep (all independent, hoisted upfront) --------
    split_rows<<<(TOK * 256 + 255) / 256, 256>>>(latent, xah, xal, TOK * 256);
    for (int l = 0; l < 3; l++) {
        transpose_split<<<dim3(768 / 32, 256 / 32), tb>>>(
            qkv_w + l * 256 * 768, qwh + l * 768 * 256, qwl + l * 768 * 256,
            256, 768, 768);
        transpose_split<<<dim3(256 / 32, 256 / 32), tb>>>(
            proj_w + l * 256 * 256, pwh + l * 256 * 256, pwl + l * 256 * 256,
            256, 256, 256);
    }
    split_rows<<<(512 * 256 + 255) / 256, 256>>>(split_w, swh, swl, 512 * 256);
    transpose_split<<<dim3(2048 / 32, 512 / 32), tb>>>(pw0, w0h, w0l, 512, 2048, 2048);
    transpose_split<<<dim3(1024 / 32, 256 / 32), tb>>>(pw1, w1h, w1l, 256, 1024, 1024);
    transpose_split<<<dim3(1024 / 32, 512 / 32), tb>>>(sw0, u0h, u0l, 512, 1024, 1024);
    transpose_split<<<dim3(512 / 32, 256 / 32), tb>>>(sw1, u1h, u1l, 256, 512, 512);
    pad_split<<<64, 256>>>(sw2, u2h, u2l, 32, 128);

    // -------- transformer layers --------
    for (int l = 0; l < 3; l++) {
        gemm_mma<0, false><<<dim3(768 / 128, TOK / 128), 256, GEMM_MMA_SMEM>>>(
            xah, xal, qwh + l * 768 * 256, qwl + l * 768 * 256,
            qkv_b + l * 768, qkv, nullptr, nullptr,
            TOK, 768, 256, 768, 0, 0, 0);

        na3d_attn_v5<<<TOK / 4, 256>>>(qkv, aah, aal);

        gemm_mma<4, false><<<dim3(256 / 128, TOK / 128), 256, GEMM_MMA_SMEM>>>(
            aah, aal, pwh + l * 256 * 256, pwl + l * 256 * 256,
            proj_b + l * 256, nullptr, xah, xal,
            TOK, 256, 256, 256, 0, 0, 0);
    }

    // split (MODE 1): feats [512][5760] channel-first
    gemm_mma<1, false><<<dim3(TOK / 128, 512 / 128), 256, GEMM_MMA_SMEM>>>(
        swh, swl, xah, xal, split_b, feats, nullptr, nullptr,
        512, TOK, 256, TOK, 0, 0, 0);

    // featsT (all 5760 tokens: press uses rows [0,4608), surf rows [4608,5760))
    transpose_split<<<dim3(5760 / 32, 512 / 32), tb>>>(feats, fth, ftl, 512, 5760, TOK);

    // press0 (MODE 2): -> fp32 p0 (256, 8, 48, 96)
    gemm_mma<2, true><<<dim3(4608 / 128, 2048 / 128), 256, GEMM_MMA_SMEM>>>(
        w0h, w0l, fth, ftl, pb0, p0f, nullptr, nullptr,
        2048, 4608, 512, 0, 4, 24, 48);

    // press1 (MODE 2): B = p0T
    transpose_split<<<dim3(36864 / 32, 256 / 32), tb>>>(p0f, b0h, b0l, 256, 36864, 36864);
    gemm_mma<2, true><<<dim3(36864 / 128, 1024 / 128), 256, GEMM_MMA_SMEM>>>(
        w1h, w1l, b0h, b0l, pb1, p1f, nullptr, nullptr,
        1024, 36864, 256, 0, 8, 48, 96);

    // press2 (fp32, M=40 -> BM=64; B already [K][N])
    gemm_db<64, true, false, 2, false><<<dim3(294912 / 128, 1), 128>>>(
        pw2, p1f, pb2, out + 8 * 192 * 384,
        40, 294912, 128, 40, 294912, 0, 16, 96, 192);

    // surf0 (MODE 3): A = sw0T, B = featsT rows 4608.., -> fp32 s0 (256,48,96)
    gemm_mma<3, true><<<dim3(1152 / 128, 1024 / 128), 256, GEMM_MMA_SMEM>>>(
        u0h, u0l, fth + (size_t)4608 * 512, ftl + (size_t)4608 * 512,
        sb0, s0, nullptr, nullptr,
        1024, 1152, 512, 0, 0, 24, 48);

    // surf1 (MODE 3): B = s0T (reuse b0 buffer)
    transpose_split<<<dim3(4608 / 32, 256 / 32), tb>>>(s0, b0h, b0l, 256, 4608, 4608);
    gemm_mma<3, true><<<dim3(4608 / 128, 512 / 128), 256, GEMM_MMA_SMEM>>>(
        u1h, u1l, b0h, b0l, sb1, s1, nullptr, nullptr,
        512, 4608, 256, 0, 0, 48, 96);

    // surf2 (MODE 3, M=32 guarded): B = s1T (offset region of b0 buffer)
    __nv_bfloat16* s1th = b0h + (size_t)4608 * 256;
    __nv_bfloat16* s1tl = b0l + (size_t)4608 * 256;
    transpose_split<<<dim3(18432 / 32, 128 / 32), tb>>>(s1, s1th, s1tl, 128, 18432, 18432);
    gemm_mma<3, false><<<dim3(18432 / 128, 1), 256, GEMM_MMA_SMEM>>>(
        u2h, u2l, s1th, s1tl, sb2, out, nullptr, nullptr,
        32, 18432, 128, 0, 0, 96, 192);
}

// round 17
// speedup vs baseline: 2.1853x; 1.0173x over previous
#include <cuda_runtime.h>
#include <cuda_bf16.h>
#include <math.h>
#include <stdint.h>

// ---------------------------------------------------------------------------
// Problem constants
// ---------------------------------------------------------------------------
#define TOK   5760          // 5*24*48
#define CH    256
#define DD    5
#define HH    24
#define WW    48
#define NHEAD 8
#define HDIM  32

// fp32 scratch
__device__ float g_qkv [TOK * 768];
__device__ float g_p0f [256 * 36864];                // press0 out (256, 8, 48, 96)
__device__ float g_p1f [128 * 294912];               // press1 out (128, 16, 96, 192)
__device__ float g_s0  [256 * 48 * 96];
__device__ float g_s1  [128 * 96 * 192];

// bf16 hi/lo scratch
__device__ __align__(16) __nv_bfloat16 g_xah[TOK * 256],   g_xal[TOK * 256];   // x (layer act)
__device__ __align__(16) __nv_bfloat16 g_aah[TOK * 256],   g_aal[TOK * 256];   // attn out
__device__ __align__(16) __nv_bfloat16 g_qwh[3 * 768 * 256], g_qwl[3 * 768 * 256]; // qkv_w^T
__device__ __align__(16) __nv_bfloat16 g_pwh[3 * 256 * 256], g_pwl[3 * 256 * 256]; // proj_w^T
__device__ __align__(16) __nv_bfloat16 g_swh[512 * 256],   g_swl[512 * 256];   // split_w
__device__ __align__(16) __nv_bfloat16 g_w0h[2048 * 512],  g_w0l[2048 * 512];  // pw0^T
__device__ __align__(16) __nv_bfloat16 g_w1h[1024 * 256],  g_w1l[1024 * 256];  // pw1^T
__device__ __align__(16) __nv_bfloat16 g_u0h[1024 * 512],  g_u0l[1024 * 512];  // sw0^T
__device__ __align__(16) __nv_bfloat16 g_u1h[512 * 256],   g_u1l[512 * 256];   // sw1^T
__device__ __align__(16) __nv_bfloat16 g_u2h[128 * 128],   g_u2l[128 * 128];   // sw2 padded
__device__ __align__(16) __nv_bfloat16 g_fth[5760 * 512],  g_ftl[5760 * 512];  // featsT (token-major)
__device__ __align__(16) __nv_bfloat16 g_b0h[36864 * 256], g_b0l[36864 * 256]; // p0T; later s0T/s1T

// ---------------------------------------------------------------------------
// fp32 -> bf16 hi/lo split, contiguous
// ---------------------------------------------------------------------------
__global__ void split_rows(const float* __restrict__ in,
                           __nv_bfloat16* __restrict__ oh,
                           __nv_bfloat16* __restrict__ ol, int n)
{
    int i = blockIdx.x * blockDim.x + threadIdx.x;
    if (i < n) {
        float v = in[i];
        __nv_bfloat16 h = __float2bfloat16(v);
        oh[i] = h;
        ol[i] = __float2bfloat16(v - __bfloat162float(h));
    }
}

// fp32 [R][C] (row stride ld) -> bf16 hi/lo [C][R]   (R, C multiples of 32)
__global__ void transpose_split(const float* __restrict__ in,
                                __nv_bfloat16* __restrict__ oh,
                                __nv_bfloat16* __restrict__ ol,
                                int R, int C, int ld)
{
    __shared__ float t[32][33];
    const int r0 = blockIdx.y * 32, c0 = blockIdx.x * 32;
    const int tx = threadIdx.x, ty = threadIdx.y;
    #pragma unroll
    for (int i = ty; i < 32; i += 8)
        t[i][tx] = in[(size_t)(r0 + i) * ld + c0 + tx];
    __syncthreads();
    #pragma unroll
    for (int i = ty; i < 32; i += 8) {
        float v = t[tx][i];
        __nv_bfloat16 h = __float2bfloat16(v);
        oh[(size_t)(c0 + i) * R + r0 + tx] = h;
        ol[(size_t)(c0 + i) * R + r0 + tx] = __float2bfloat16(v - __bfloat162float(h));
    }
}

// src fp32 [K][Mreal] -> padded A hi/lo [128][K], rows >= Mreal zero. K*128 elems.
__global__ void pad_split(const float* __restrict__ src,
                          __nv_bfloat16* __restrict__ oh,
                          __nv_bfloat16* __restrict__ ol, int Mreal, int K)
{
    const int idx = blockIdx.x * 256 + threadIdx.x;
    if (idx < 128 * K) {
        const int m = idx / K, k = idx % K;
        float v = (m < Mreal) ? src[k * Mreal + m] : 0.f;
        __nv_bfloat16 h = __float2bfloat16(v);
        oh[idx] = h;
        ol[idx] = __float2bfloat16(v - __bfloat162float(h));
    }
}

// ---------------------------------------------------------------------------
// press2: out[m-scatter] = sum_k pw2[k][m] * p1[k][n] + pb2[m>>3]
// pw2 staged in smem as float4 (40 floats/row = 10 float4).
// One thread per spatial column n (fully coalesced p1 loads).
// p1 is [128][294912]; out scatter: Din=16,Hin=96,Win=192 -> (32,192,384).
// ---------------------------------------------------------------------------
__global__ __launch_bounds__(256)
void press2_kernel(const float* __restrict__ p1, const float* __restrict__ pw2,
                   const float* __restrict__ bias, float* __restrict__ outp)
{
    __shared__ float4 sA[128 * 10];
    const int tid = threadIdx.x;
    #pragma unroll
    for (int idx = tid; idx < 1280; idx += 256)
        sA[idx] = ((const float4*)pw2)[idx];
    __syncthreads();

    const int n = blockIdx.x * 256 + tid;
    float4 acc[10];
    #pragma unroll
    for (int c = 0; c < 10; c++) acc[c] = make_float4(0.f, 0.f, 0.f, 0.f);

    const float* pn = p1 + n;
    #pragma unroll 4
    for (int k = 0; k < 128; k++) {
        const float v = pn[(size_t)k * 294912];
        const float4* a = &sA[k * 10];
        #pragma unroll
        for (int c = 0; c < 10; c++) {
            acc[c].x += a[c].x * v;
            acc[c].y += a[c].y * v;
            acc[c].z += a[c].z * v;
            acc[c].w += a[c].w * v;
        }
    }

    const int w = n % 192;
    const int t = n / 192;
    const int h = t % 96;
    const int d = t / 96;
    const float* accf = (const float*)acc;
    #pragma unroll
    for (int m = 0; m < 40; m++) {
        const int o = m >> 3, r = m & 7;
        const int ri = (r >> 2) & 1, rj = (r >> 1) & 1, rk = r & 1;
        outp[((size_t)(o * 32 + 2 * d + ri) * 192 + 2 * h + rj) * 384 + 2 * w + rk]
            = accf[m] + bias[o];
    }
}

// ---------------------------------------------------------------------------
// Tensor-core GEMM, bf16x3 split (hi*hi + hi*lo + lo*hi), fp32 accum.
// cp.async double-buffered; ldmatrix.x4 fragment loads.
//   C[m][n] = epilogue( sum_k A[m][k]*B[k][n] + bias )
// Tile 128x128x32, 256 threads = 8 warps (2 m x 4 n), warp tile 64x32,
// mma.sync.m16n8k16. N multiple of 128; K multiple of 32.
// MODE 0: fp32 C row-major [M][ldc], bias[n]
// MODE 2: up3d scatter to fp32 C, bias[m>>3], optional SiLU, m<M guarded
// MODE 3: up2d scatter to fp32 C, bias[m>>2], optional SiLU, m<M guarded
// MODE 4: bf16 hi/lo Oh/Ol row-major [M][ldc], bias[n]
// ---------------------------------------------------------------------------
#define MMA_BF16(c, a0, a1, a2, a3, b0, b1)                                   \
    asm volatile("mma.sync.aligned.m16n8k16.row.col.f32.bf16.bf16.f32 "       \
                 "{%0,%1,%2,%3}, {%4,%5,%6,%7}, {%8,%9}, {%0,%1,%2,%3};"      \
                 : "+f"(c[0]), "+f"(c[1]), "+f"(c[2]), "+f"(c[3])             \
                 : "r"(a0), "r"(a1), "r"(a2), "r"(a3), "r"(b0), "r"(b1))

__device__ __forceinline__ void cp16(uint32_t dst, const void* src) {
    asm volatile("cp.async.ca.shared.global [%0], [%1], 16;" :: "r"(dst), "l"(src));
}

__device__ __forceinline__ void ldsm4(uint32_t& r0, uint32_t& r1,
                                      uint32_t& r2, uint32_t& r3, uint32_t addr) {
    asm volatile("ldmatrix.sync.aligned.m8n8.x4.shared.b16 {%0,%1,%2,%3}, [%4];"
                 : "=r"(r0), "=r"(r1), "=r"(r2), "=r"(r3) : "r"(addr));
}

#define GEMM_MMA_SMEM 81920

template<int MODE, bool SILU>
__global__ __launch_bounds__(256)
void gemm_mma(const __nv_bfloat16* __restrict__ Ah, const __nv_bfloat16* __restrict__ Al,
              const __nv_bfloat16* __restrict__ Bh, const __nv_bfloat16* __restrict__ Bl,
              const float* __restrict__ bias, float* __restrict__ C,
              __nv_bfloat16* __restrict__ Oh, __nv_bfloat16* __restrict__ Ol,
              int M, int N, int K, int ldc, int Din, int Hin, int Win)
{
    constexpr int RS = 20;                  // smem words per row (16 data + 4 pad)
    constexpr int BUFW = 128 * RS;          // words per array
    extern __shared__ __align__(16) float smem_dyn[];
    const uint32_t sbase = (uint32_t)__cvta_generic_to_shared(smem_dyn);

    const int tid  = threadIdx.x;
    const int warp = tid >> 5, lane = tid & 31;
    const int g = lane >> 2, t = lane & 3;
    const int wm = warp & 1, wn = warp >> 1;       // warp tile origin (wm*64, wn*32)
    const int m0 = blockIdx.y * 128, n0 = blockIdx.x * 128;

    const int lrow = tid >> 1, lseg = tid & 1;     // loader: 2 threads/row, 16 bf16 each

    // ldmatrix per-lane row/chunk decomposition
    const int rA = (lane & 7) + ((lane >> 3) & 1) * 8;
    const int cA = (lane >> 4) & 1;
    const int rB = (lane & 7) + ((lane >> 4) & 1) * 8;
    const int cB = (lane >> 3) & 1;

    float acc[4][4][4];
    #pragma unroll
    for (int a = 0; a < 4; a++)
        #pragma unroll
        for (int b = 0; b < 4; b++)
            #pragma unroll
            for (int c = 0; c < 4; c++) acc[a][b][c] = 0.f;

    auto issue = [&](int k0, int buf) {
        const size_t ga = (size_t)(m0 + lrow) * K + k0 + lseg * 16;
        const size_t gb = (size_t)(n0 + lrow) * K + k0 + lseg * 16;
        const uint32_t doff = (uint32_t)(lrow * RS + lseg * 8) * 4;
        const uint32_t p0 = sbase + (uint32_t)(buf * 4 + 0) * BUFW * 4 + doff;
        const uint32_t p1 = sbase + (uint32_t)(buf * 4 + 1) * BUFW * 4 + doff;
        const uint32_t p2 = sbase + (uint32_t)(buf * 4 + 2) * BUFW * 4 + doff;
        const uint32_t p3 = sbase + (uint32_t)(buf * 4 + 3) * BUFW * 4 + doff;
        cp16(p0, Ah + ga); cp16(p0 + 16, Ah + ga + 8);
        cp16(p1, Al + ga); cp16(p1 + 16, Al + ga + 8);
        cp16(p2, Bh + gb); cp16(p2 + 16, Bh + gb + 8);
        cp16(p3, Bl + gb); cp16(p3 + 16, Bl + gb + 8);
    };

    issue(0, 0);
    asm volatile("cp.async.commit_group;" ::: "memory");

    const int nslab = K >> 5;
    int buf = 0;
    for (int s = 0; s < nslab; s++) {
        asm volatile("cp.async.wait_group 0;" ::: "memory");
        __syncthreads();
        if (s + 1 < nslab) {
            issue((s + 1) << 5, buf ^ 1);
            asm volatile("cp.async.commit_group;" ::: "memory");
        }

        const uint32_t bAh = sbase + (uint32_t)(buf * 4 + 0) * BUFW * 4;
        const uint32_t bAl = sbase + (uint32_t)(buf * 4 + 1) * BUFW * 4;
        const uint32_t bBh = sbase + (uint32_t)(buf * 4 + 2) * BUFW * 4;
        const uint32_t bBl = sbase + (uint32_t)(buf * 4 + 3) * BUFW * 4;

        #pragma unroll
        for (int ks = 0; ks < 2; ks++) {
            uint32_t bh[4][2], bl[4][2];
            #pragma unroll
            for (int p = 0; p < 2; p++) {
                const uint32_t boff =
                    (uint32_t)((wn * 32 + p * 16 + rB) * RS + ks * 8 + cB * 4) * 4;
                ldsm4(bh[2 * p][0], bh[2 * p][1], bh[2 * p + 1][0], bh[2 * p + 1][1],
                      bBh + boff);
                ldsm4(bl[2 * p][0], bl[2 * p][1], bl[2 * p + 1][0], bl[2 * p + 1][1],
                      bBl + boff);
            }
            #pragma unroll
            for (int mt = 0; mt < 4; mt++) {
                const uint32_t aoff =
                    (uint32_t)((wm * 64 + mt * 16 + rA) * RS + ks * 8 + cA * 4) * 4;
                uint32_t ah0, ah1, ah2, ah3, al0, al1, al2, al3;
                ldsm4(ah0, ah1, ah2, ah3, bAh + aoff);
                ldsm4(al0, al1, al2, al3, bAl + aoff);
                #pragma unroll
                for (int nt = 0; nt < 4; nt++) {
                    MMA_BF16(acc[mt][nt], ah0, ah1, ah2, ah3, bh[nt][0], bh[nt][1]);
                    MMA_BF16(acc[mt][nt], ah0, ah1, ah2, ah3, bl[nt][0], bl[nt][1]);
                    MMA_BF16(acc[mt][nt], al0, al1, al2, al3, bh[nt][0], bh[nt][1]);
                }
            }
        }
        buf ^= 1;
    }

    // element (mt, nt, reg): m = m0+wm*64+mt*16+g+(reg>=2)*8,
    //                        n = n0+wn*32+nt*8+t*2+(reg&1)
    if (MODE == 0) {
        #pragma unroll
        for (int mt = 0; mt < 4; mt++) {
            const int mb = m0 + wm * 64 + mt * 16 + g;
            #pragma unroll
            for (int nt = 0; nt < 4; nt++) {
                const int nb = n0 + wn * 32 + nt * 8 + t * 2;
                const float b0 = bias[nb], b1 = bias[nb + 1];
                float2 v0 = make_float2(acc[mt][nt][0] + b0, acc[mt][nt][1] + b1);
                float2 v1 = make_float2(acc[mt][nt][2] + b0, acc[mt][nt][3] + b1);
                *(float2*)&C[(size_t)mb * ldc + nb]       = v0;
                *(float2*)&C[(size_t)(mb + 8) * ldc + nb] = v1;
            }
        }
    } else if (MODE == 4) {
        #pragma unroll
        for (int mt = 0; mt < 4; mt++) {
            const int mb = m0 + wm * 64 + mt * 16 + g;
            #pragma unroll
            for (int nt = 0; nt < 4; nt++) {
                const int nb = n0 + wn * 32 + nt * 8 + t * 2;
                const float b0 = bias[nb], b1 = bias[nb + 1];
                #pragma unroll
                for (int half = 0; half < 2; half++) {
                    const int m = mb + half * 8;
                    const float va = acc[mt][nt][half * 2 + 0] + b0;
                    const float vb = acc[mt][nt][half * 2 + 1] + b1;
                    const __nv_bfloat16 ha = __float2bfloat16(va);
                    const __nv_bfloat16 hb = __float2bfloat16(vb);
                    __nv_bfloat162 hp, lp;
                    hp.x = ha; hp.y = hb;
                    lp.x = __float2bfloat16(va - __bfloat162float(ha));
                    lp.y = __float2bfloat16(vb - __bfloat162float(hb));
                    *(__nv_bfloat162*)&Oh[(size_t)m * ldc + nb] = hp;
                    *(__nv_bfloat162*)&Ol[(size_t)m * ldc + nb] = lp;
                }
            }
        }
    } else if (MODE == 2) { // up3d scatter to fp32 (o-major)
        int nw[4][2], nh[4][2], nd[4][2];
        #pragma unroll
        for (int nt = 0; nt < 4; nt++)
            #pragma unroll
            for (int e = 0; e < 2; e++) {
                const int n = n0 + wn * 32 + nt * 8 + t * 2 + e;
                nw[nt][e] = n % Win;
                const int tt = n / Win;
                nh[nt][e] = tt % Hin;
                nd[nt][e] = tt / Hin;
            }
        const int OD = 2 * Din, OH = 2 * Hin, OW = 2 * Win;
        #pragma unroll
        for (int mt = 0; mt < 4; mt++) {
            #pragma unroll
            for (int half = 0; half < 2; half++) {
                const int m = m0 + wm * 64 + mt * 16 + g + half * 8;
                if (m < M) {
                    const int o = m >> 3, r = m & 7;
                    const int ri = (r >> 2) & 1, rj = (r >> 1) & 1, rk = r & 1;
                    const float bv = bias[o];
                    #pragma unroll
                    for (int nt = 0; nt < 4; nt++) {
                        #pragma unroll
                        for (int e = 0; e < 2; e++) {
                            float v = acc[mt][nt][half * 2 + e] + bv;
                            if (SILU) v = v / (1.f + __expf(-v));
                            const size_t idx =
                                ((size_t)(o * OD + 2 * nd[nt][e] + ri) * OH
                                 + 2 * nh[nt][e] + rj) * OW + 2 * nw[nt][e] + rk;
                            C[idx] = v;
                        }
                    }
                }
            }
        }
    } else { // MODE 3 : up2d scatter to fp32 (o-major)
        int nw[4][2], nh[4][2];
        #pragma unroll
        for (int nt = 0; nt < 4; nt++)
            #pragma unroll
            for (int e = 0; e < 2; e++) {
                const int n = n0 + wn * 32 + nt * 8 + t * 2 + e;
                nw[nt][e] = n % Win;
                nh[nt][e] = n / Win;
            }
        const int OH = 2 * Hin, OW = 2 * Win;
        #pragma unroll
        for (int mt = 0; mt < 4; mt++) {
            #pragma unroll
            for (int half = 0; half < 2; half++) {
                const int m = m0 + wm * 64 + mt * 16 + g + half * 8;
                if (m < M) {
                    const int o = m >> 2, r = m & 3;
                    const int ri = (r >> 1) & 1, rj = r & 1;
                    const float bv = bias[o];
                    #pragma unroll
                    for (int nt = 0; nt < 4; nt++) {
                        #pragma unroll
                        for (int e = 0; e < 2; e++) {
                            float v = acc[mt][nt][half * 2 + e] + bv;
                            if (SILU) v = v / (1.f + __expf(-v));
                            const size_t idx =
                                (size_t)(o * OH + 2 * nh[nt][e] + ri) * OW
                                + 2 * nw[nt][e] + rj;
                            C[idx] = v;
                        }
                    }
                }
            }
        }
    }
}

// ---------------------------------------------------------------------------
// 3D neighborhood attention v5: 4 tokens per block share a window union.
// ---------------------------------------------------------------------------
__global__ __launch_bounds__(256, 4)
void na3d_attn_v5(const float* __restrict__ qkv,
                  __nv_bfloat16* __restrict__ oh,
                  __nv_bfloat16* __restrict__ ol)
{
    __shared__ __align__(16) float sp[NHEAD][120][4];

    const int t4 = blockIdx.x * 4;
    const int d = t4 / (HH * WW);
    const int rem = t4 % (HH * WW);
    const int h = rem / WW;
    const int w0 = rem % WW;
    const int head = threadIdx.x >> 5;
    const int lane = threadIdx.x & 31;
    const int qd  = lane >> 2;
    const int sub = lane & 3;

    const int sd = min(max(d - 1, 0), DD - 3);
    const int sh = min(max(h - 2, 0), HH - 5);
    const int swu = min(max(w0 - 2, 0), WW - 8);
    int off[4];
    #pragma unroll
    for (int t = 0; t < 4; t++)
        off[t] = min(max(w0 + t - 2, 0), WW - 5) - swu;

    const float sc0 = 0.17677669529663687f;
    float4 q0[4], q1[4];
    #pragma unroll
    for (int t = 0; t < 4; t++) {
        const float* qp = qkv + (size_t)(t4 + t) * 768 + head * HDIM + sub * 8;
        q0[t] = *(const float4*)qp;
        q1[t] = *(const float4*)(qp + 4);
        q0[t].x *= sc0; q0[t].y *= sc0; q0[t].z *= sc0; q0[t].w *= sc0;
        q1[t].x *= sc0; q1[t].y *= sc0; q1[t].z *= sc0; q1[t].w *= sc0;
    }

    for (int r = 0; r < 15; r++) {
        const int dd = r / 5, hh2 = r % 5;
        const int nb = ((sd + dd) * HH + (sh + hh2)) * WW + swu + qd;
        const float* kp = qkv + (size_t)nb * 768 + 256 + head * HDIM + sub * 8;
        const float4 k0 = *(const float4*)kp;
        const float4 k1 = *(const float4*)(kp + 4);
        float4 sv;
        float sr[4];
        #pragma unroll
        for (int t = 0; t < 4; t++) {
            float s = q0[t].x * k0.x + q0[t].y * k0.y + q0[t].z * k0.z + q0[t].w * k0.w
                    + q1[t].x * k1.x + q1[t].y * k1.y + q1[t].z * k1.z + q1[t].w * k1.w;
            s += __shfl_xor_sync(0xffffffffu, s, 1);
            s += __shfl_xor_sync(0xffffffffu, s, 2);
            const bool valid = (qd >= off[t]) && (qd < off[t] + 5);
            sr[t] = valid ? s : -1e30f;
        }
        sv.x = sr[0]; sv.y = sr[1]; sv.z = sr[2]; sv.w = sr[3];
        if (sub == 0) *(float4*)&sp[head][r * 8 + qd][0] = sv;
    }
    __syncwarp();

    #pragma unroll
    for (int t = 0; t < 4; t++) {
        const float v0 = sp[head][lane][t];
        const float v1 = sp[head][lane + 32][t];
        const float v2 = sp[head][lane + 64][t];
        const float v3 = (lane < 24) ? sp[head][lane + 96][t] : -1e30f;
        float m = fmaxf(fmaxf(v0, v1), fmaxf(v2, v3));
        #pragma unroll
        for (int o = 16; o; o >>= 1) m = fmaxf(m, __shfl_xor_sync(0xffffffffu, m, o));
        const float e0 = __expf(v0 - m);
        const float e1 = __expf(v1 - m);
        const float e2 = __expf(v2 - m);
        const float e3 = (lane < 24) ? __expf(v3 - m) : 0.f;
        float ssum = e0 + e1 + e2 + e3;
        #pragma unroll
        for (int o = 16; o; o >>= 1) ssum += __shfl_xor_sync(0xffffffffu, ssum, o);
        const float inv = 1.f / ssum;
        sp[head][lane][t]      = e0 * inv;
        sp[head][lane + 32][t] = e1 * inv;
        sp[head][lane + 64][t] = e2 * inv;
        if (lane < 24) sp[head][lane + 96][t] = e3 * inv;
    }
    __syncwarp();

    float acc[4] = {0.f, 0.f, 0.f, 0.f};
    const float* vbase = qkv + 512 + head * HDIM + lane;
    int p = 0;
    #pragma unroll
    for (int dd = 0; dd < 3; dd++) {
        #pragma unroll
        for (int hh2 = 0; hh2 < 5; hh2++) {
            const int rowb = ((sd + dd) * HH + (sh + hh2)) * WW + swu;
            #pragma unroll
            for (int wwu = 0; wwu < 8; wwu++) {
                const float v = vbase[(size_t)(rowb + wwu) * 768];
                const float4 pr = *(const float4*)&sp[head][p][0];
                acc[0] += pr.x * v;
                acc[1] += pr.y * v;
                acc[2] += pr.z * v;
                acc[3] += pr.w * v;
                p++;
            }
        }
    }
    #pragma unroll
    for (int t = 0; t < 4; t++) {
        const size_t oidx = (size_t)(t4 + t) * CH + head * HDIM + lane;
        const __nv_bfloat16 hv = __float2bfloat16(acc[t]);
        oh[oidx] = hv;
        ol[oidx] = __float2bfloat16(acc[t] - __bfloat162float(hv));
    }
}

// ---------------------------------------------------------------------------
// Launcher
// ---------------------------------------------------------------------------
extern "C" void kernel_launch(void* const* d_in, const int* in_sizes, int n_in,
                              void* d_out, int out_size)
{
    const float* latent  = (const float*)d_in[0];
    const float* qkv_w   = (const float*)d_in[1];
    const float* qkv_b   = (const float*)d_in[2];
    const float* proj_w  = (const float*)d_in[3];
    const float* proj_b  = (const float*)d_in[4];
    const float* split_w = (const float*)d_in[5];
    const float* split_b = (const float*)d_in[6];
    const float* pw0 = (const float*)d_in[7];
    const float* pb0 = (const float*)d_in[8];
    const float* pw1 = (const float*)d_in[9];
    const float* pb1 = (const float*)d_in[10];
    const float* pw2 = (const float*)d_in[11];
    const float* pb2 = (const float*)d_in[12];
    const float* sw0 = (const float*)d_in[13];
    const float* sb0 = (const float*)d_in[14];
    const float* sw1 = (const float*)d_in[15];
    const float* sb1 = (const float*)d_in[16];
    const float* sw2 = (const float*)d_in[17];
    const float* sb2 = (const float*)d_in[18];
    float* out = (float*)d_out;

    float *qkv, *p0f, *p1f, *s0, *s1;
    __nv_bfloat16 *xah, *xal, *aah, *aal, *fth, *ftl, *b0h, *b0l;
    __nv_bfloat16 *qwh, *qwl, *pwh, *pwl, *swh, *swl;
    __nv_bfloat16 *w0h, *w0l, *w1h, *w1l, *u0h, *u0l, *u1h, *u1l, *u2h, *u2l;
    cudaGetSymbolAddress((void**)&qkv,   g_qkv);
    cudaGetSymbolAddress((void**)&p0f,   g_p0f);
    cudaGetSymbolAddress((void**)&p1f,   g_p1f);
    cudaGetSymbolAddress((void**)&s0,    g_s0);
    cudaGetSymbolAddress((void**)&s1,    g_s1);
    cudaGetSymbolAddress((void**)&xah,   g_xah);
    cudaGetSymbolAddress((void**)&xal,   g_xal);
    cudaGetSymbolAddress((void**)&aah,   g_aah);
    cudaGetSymbolAddress((void**)&aal,   g_aal);
    cudaGetSymbolAddress((void**)&fth,   g_fth);
    cudaGetSymbolAddress((void**)&ftl,   g_ftl);
    cudaGetSymbolAddress((void**)&b0h,   g_b0h);
    cudaGetSymbolAddress((void**)&b0l,   g_b0l);
    cudaGetSymbolAddress((void**)&qwh,   g_qwh);
    cudaGetSymbolAddress((void**)&qwl,   g_qwl);
    cudaGetSymbolAddress((void**)&pwh,   g_pwh);
    cudaGetSymbolAddress((void**)&pwl,   g_pwl);
    cudaGetSymbolAddress((void**)&swh,   g_swh);
    cudaGetSymbolAddress((void**)&swl,   g_swl);
    cudaGetSymbolAddress((void**)&w0h,   g_w0h);
    cudaGetSymbolAddress((void**)&w0l,   g_w0l);
    cudaGetSymbolAddress((void**)&w1h,   g_w1h);
    cudaGetSymbolAddress((void**)&w1l,   g_w1l);
    cudaGetSymbolAddress((void**)&u0h,   g_u0h);
    cudaGetSymbolAddress((void**)&u0l,   g_u0l);
    cudaGetSymbolAddress((void**)&u1h,   g_u1h);
    cudaGetSymbolAddress((void**)&u1l,   g_u1l);
    cudaGetSymbolAddress((void**)&u2h,   g_u2h);
    cudaGetSymbolAddress((void**)&u2l,   g_u2l);

    cudaFuncSetAttribute(gemm_mma<0, false>,
                         cudaFuncAttributeMaxDynamicSharedMemorySize, GEMM_MMA_SMEM);
    cudaFuncSetAttribute(gemm_mma<2, true>,
                         cudaFuncAttributeMaxDynamicSharedMemorySize, GEMM_MMA_SMEM);
    cudaFuncSetAttribute(gemm_mma<3, true>,
                         cudaFuncAttributeMaxDynamicSharedMemorySize, GEMM_MMA_SMEM);
    cudaFuncSetAttribute(gemm_mma<3, false>,
                         cudaFuncAttributeMaxDynamicSharedMemorySize, GEMM_MMA_SMEM);
    cudaFuncSetAttribute(gemm_mma<4, false>,
                         cudaFuncAttributeMaxDynamicSharedMemorySize, GEMM_MMA_SMEM);

    const dim3 tb(32, 8);

    // -------- weight / input prep (all independent, hoisted upfront) --------
    split_rows<<<(TOK * 256 + 255) / 256, 256>>>(latent, xah, xal, TOK * 256);
    for (int l = 0; l < 3; l++) {
        transpose_split<<<dim3(768 / 32, 256 / 32), tb>>>(
            qkv_w + l * 256 * 768, qwh + l * 768 * 256, qwl + l * 768 * 256,
            256, 768, 768);
        transpose_split<<<dim3(256 / 32, 256 / 32), tb>>>(
            proj_w + l * 256 * 256, pwh + l * 256 * 256, pwl + l * 256 * 256,
            256, 256, 256);
    }
    split_rows<<<(512 * 256 + 255) / 256, 256>>>(split_w, swh, swl, 512 * 256);
    transpose_split<<<dim3(2048 / 32, 512 / 32), tb>>>(pw0, w0h, w0l, 512, 2048, 2048);
    transpose_split<<<dim3(1024 / 32, 256 / 32), tb>>>(pw1, w1h, w1l, 256, 1024, 1024);
    transpose_split<<<dim3(1024 / 32, 512 / 32), tb>>>(sw0, u0h, u0l, 512, 1024, 1024);
    transpose_split<<<dim3(512 / 32, 256 / 32), tb>>>(sw1, u1h, u1l, 256, 512, 512);
    pad_split<<<64, 256>>>(sw2, u2h, u2l, 32, 128);

    // -------- transformer layers --------
    for (int l = 0; l < 3; l++) {
        gemm_mma<0, false><<<dim3(768 / 128, TOK / 128), 256, GEMM_MMA_SMEM>>>(
            xah, xal, qwh + l * 768 * 256, qwl + l * 768 * 256,
            qkv_b + l * 768, qkv, nullptr, nullptr,
            TOK, 768, 256, 768, 0, 0, 0);

        na3d_attn_v5<<<TOK / 4, 256>>>(qkv, aah, aal);

        gemm_mma<4, false><<<dim3(256 / 128, TOK / 128), 256, GEMM_MMA_SMEM>>>(
            aah, aal, pwh + l * 256 * 256, pwl + l * 256 * 256,
            proj_b + l * 256, nullptr, xah, xal,
            TOK, 256, 256, 256, 0, 0, 0);
    }

    // split (MODE 4): A = x [5760][256], B = split_w [512][256] ->
    // featsT token-major bf16 hi/lo [5760][512] directly (no fp32 roundtrip)
    gemm_mma<4, false><<<dim3(512 / 128, TOK / 128), 256, GEMM_MMA_SMEM>>>(
        xah, xal, swh, swl, split_b, nullptr, fth, ftl,
        TOK, 512, 256, 512, 0, 0, 0);

    // press0 (MODE 2): B = featsT rows [0,4608) -> fp32 p0 (256, 8, 48, 96)
    gemm_mma<2, true><<<dim3(4608 / 128, 2048 / 128), 256, GEMM_MMA_SMEM>>>(
        w0h, w0l, fth, ftl, pb0, p0f, nullptr, nullptr,
        2048, 4608, 512, 0, 4, 24, 48);

    // press1 (MODE 2): B = p0T
    transpose_split<<<dim3(36864 / 32, 256 / 32), tb>>>(p0f, b0h, b0l, 256, 36864, 36864);
    gemm_mma<2, true><<<dim3(36864 / 128, 1024 / 128), 256, GEMM_MMA_SMEM>>>(
        w1h, w1l, b0h, b0l, pb1, p1f, nullptr, nullptr,
        1024, 36864, 256, 0, 8, 48, 96);

    // press2: dedicated broadcast kernel (pw2 smem, coalesced p1 columns)
    press2_kernel<<<294912 / 256, 256>>>(p1f, pw2, pb2, out + 8 * 192 * 384);

    // surf0 (MODE 3): A = sw0T, B = featsT rows 4608.., -> fp32 s0 (256,48,96)
    gemm_mma<3, true><<<dim3(1152 / 128, 1024 / 128), 256, GEMM_MMA_SMEM>>>(
        u0h, u0l, fth + (size_t)4608 * 512, ftl + (size_t)4608 * 512,
        sb0, s0, nullptr, nullptr,
        1024, 1152, 512, 0, 0, 24, 48);

    // surf1 (MODE 3): B = s0T (reuse b0 buffer)
    transpose_split<<<dim3(4608 / 32, 256 / 32), tb>>>(s0, b0h, b0l, 256, 4608, 4608);
    gemm_mma<3, true><<<dim3(4608 / 128, 512 / 128), 256, GEMM_MMA_SMEM>>>(
        u1h, u1l, b0h, b0l, sb1, s1, nullptr, nullptr,
        512, 4608, 256, 0, 0, 48, 96);

    // surf2 (MODE 3, M=32 guarded): B = s1T (offset region of b0 buffer)
    __nv_bfloat16* s1th = b0h + (size_t)4608 * 256;
    __nv_bfloat16* s1tl = b0l + (size_t)4608 * 256;
    transpose_split<<<dim3(18432 / 32, 128 / 32), tb>>>(s1, s1th, s1tl, 128, 18432, 18432);
    gemm_mma<3, false><<<dim3(18432 / 128, 1), 256, GEMM_MMA_SMEM>>>(
        u2h, u2l, s1th, s1tl, sb2, out, nullptr, nullptr,
        32, 18432, 128, 0, 0, 96, 192);
}